// round 1
// baseline (speedup 1.0000x reference)
#include <cuda_runtime.h>
#include <math.h>

#define BB 4
#define TT 2048
#define DD 1024
#define HH 16
#define HDIM 64
#define MROWS (BB*TT)   // 8192

// Scratch (device globals — no allocation allowed)
__device__ float g_q[MROWS * DD];
__device__ float g_k[MROWS * DD];
__device__ float g_v[MROWS * DD];
__device__ float g_y[MROWS * DD];

// ---------------------------------------------------------------------------
// SGEMM (NT): C[m,n] = sum_k A[m,k] * W[n,k] + bias[n]
// A: [M,K] row-major, W: [N,K] row-major. BM=BN=128, BK=8, 256 thr, 8x8/thr.
// M=8192, N=1024, K=1024 (all multiples of tile dims; no bounds checks).
// ---------------------------------------------------------------------------
__global__ void __launch_bounds__(256, 2) sgemm_nt_bias(
    const float* __restrict__ A, const float* __restrict__ W,
    const float* __restrict__ bias, float* __restrict__ C,
    int M, int N, int K)
{
    __shared__ float As[8][132];
    __shared__ float Bs[8][132];

    const int tid = threadIdx.x;
    const int ty = tid >> 4;        // 0..15
    const int tx = tid & 15;        // 0..15
    const int rowBase = blockIdx.y * 128;
    const int colBase = blockIdx.x * 128;

    const int lm = tid >> 1;        // 0..127
    const int lk = (tid & 1) << 2;  // 0 or 4

    const float* Ap = A + (size_t)(rowBase + lm) * K + lk;
    const float* Wp = W + (size_t)(colBase + lm) * K + lk;

    float acc[8][8];
#pragma unroll
    for (int i = 0; i < 8; i++)
#pragma unroll
        for (int j = 0; j < 8; j++) acc[i][j] = 0.f;

    for (int k0 = 0; k0 < K; k0 += 8) {
        float4 av = *(const float4*)(Ap + k0);
        float4 wv = *(const float4*)(Wp + k0);
        As[lk + 0][lm] = av.x; As[lk + 1][lm] = av.y;
        As[lk + 2][lm] = av.z; As[lk + 3][lm] = av.w;
        Bs[lk + 0][lm] = wv.x; Bs[lk + 1][lm] = wv.y;
        Bs[lk + 2][lm] = wv.z; Bs[lk + 3][lm] = wv.w;
        __syncthreads();

#pragma unroll
        for (int kk = 0; kk < 8; kk++) {
            float a[8], b[8];
            *(float4*)&a[0] = *(const float4*)&As[kk][ty * 8];
            *(float4*)&a[4] = *(const float4*)&As[kk][ty * 8 + 4];
            *(float4*)&b[0] = *(const float4*)&Bs[kk][tx * 8];
            *(float4*)&b[4] = *(const float4*)&Bs[kk][tx * 8 + 4];
#pragma unroll
            for (int i = 0; i < 8; i++)
#pragma unroll
                for (int j = 0; j < 8; j++)
                    acc[i][j] += a[i] * b[j];
        }
        __syncthreads();
    }

    float bb[8];
    *(float4*)&bb[0] = *(const float4*)&bias[colBase + tx * 8];
    *(float4*)&bb[4] = *(const float4*)&bias[colBase + tx * 8 + 4];

#pragma unroll
    for (int i = 0; i < 8; i++) {
        int m = rowBase + ty * 8 + i;
        float4 o0 = make_float4(acc[i][0] + bb[0], acc[i][1] + bb[1],
                                acc[i][2] + bb[2], acc[i][3] + bb[3]);
        float4 o1 = make_float4(acc[i][4] + bb[4], acc[i][5] + bb[5],
                                acc[i][6] + bb[6], acc[i][7] + bb[7]);
        *(float4*)&C[(size_t)m * N + colBase + tx * 8]     = o0;
        *(float4*)&C[(size_t)m * N + colBase + tx * 8 + 4] = o1;
    }
}

// ---------------------------------------------------------------------------
// RoPE (in-place on Q and K, layout [B*T, D] with head-major cols h*64+d).
// pos = t+1, theta_i = 10000^(-2i/64), rotate-half convention.
// idx bits: i[0:5) h[5:9) t[9:20) b[20:22)
// ---------------------------------------------------------------------------
__global__ void rope_kernel(float* __restrict__ Q, float* __restrict__ K)
{
    int idx = blockIdx.x * blockDim.x + threadIdx.x;
    int i = idx & 31;
    int h = (idx >> 5) & (HH - 1);
    int t = (idx >> 9) & (TT - 1);
    int b = idx >> 20;

    size_t base = ((size_t)(b * TT + t)) * DD + h * HDIM;

    float theta = expf(-(float)i * (logf(10000.f) / 32.f));
    float ang = (float)(t + 1) * theta;
    float s, c;
    sincosf(ang, &s, &c);

    float q1 = Q[base + i], q2 = Q[base + i + 32];
    Q[base + i]      = q1 * c - q2 * s;
    Q[base + i + 32] = q2 * c + q1 * s;

    float k1 = K[base + i], k2 = K[base + i + 32];
    K[base + i]      = k1 * c - k2 * s;
    K[base + i + 32] = k2 * c + k1 * s;
}

// ---------------------------------------------------------------------------
// Flash attention (fp32, causal). 64x64 Q tile per block, 256 threads,
// each thread a 4x4 micro-tile. Online softmax with 16-lane shfl reductions.
// Q,K,V,Y layout: [B*T, D] row-major, head cols h*64+d.
// Dynamic shared: Qs,Ks,Vs,Ps each [64][68] floats = 69632 B.
// ---------------------------------------------------------------------------
__global__ void __launch_bounds__(256) attn_kernel(
    const float* __restrict__ Q, const float* __restrict__ K,
    const float* __restrict__ V, float* __restrict__ Y)
{
    extern __shared__ float sm[];
    float (*Qs)[68] = (float(*)[68])(sm);              // Qs[d][i]
    float (*Ks)[68] = (float(*)[68])(sm + 64 * 68);    // Ks[d][j]
    float (*Vs)[68] = (float(*)[68])(sm + 2 * 64 * 68);// Vs[j][d]
    float (*Ps)[68] = (float(*)[68])(sm + 3 * 64 * 68);// Ps[i][j]

    const int tid = threadIdx.x;
    const int ty = tid >> 4;   // 0..15
    const int tx = tid & 15;   // 0..15
    const int i0 = ty * 4;
    const int j0 = tx * 4;

    const int qb = blockIdx.x;           // 0..31
    const int bh = blockIdx.y;           // 0..63
    const int b = bh >> 4;
    const int h = bh & 15;

    const size_t headBase = ((size_t)b * TT) * DD + h * HDIM;

    // Load Q tile (scaled by 1/sqrt(64))
    for (int idx = tid; idx < 64 * 64; idx += 256) {
        int i = idx >> 6, d = idx & 63;
        Qs[d][i] = Q[headBase + (size_t)(qb * 64 + i) * DD + d] * 0.125f;
    }

    float o[4][4];
    float m[4], l[4];
#pragma unroll
    for (int ii = 0; ii < 4; ii++) {
        m[ii] = -3.0e38f; l[ii] = 0.f;
#pragma unroll
        for (int dd = 0; dd < 4; dd++) o[ii][dd] = 0.f;
    }

    for (int jb = 0; jb <= qb; jb++) {
        __syncthreads();  // prior iteration's Ks/Vs/Ps reads complete
        for (int idx = tid; idx < 64 * 64; idx += 256) {
            int j = idx >> 6, d = idx & 63;
            size_t g = headBase + (size_t)(jb * 64 + j) * DD + d;
            Ks[d][j] = K[g];
            Vs[j][d] = V[g];
        }
        __syncthreads();

        // S = Q K^T (64x64), thread tile 4x4
        float s[4][4];
#pragma unroll
        for (int ii = 0; ii < 4; ii++)
#pragma unroll
            for (int jj = 0; jj < 4; jj++) s[ii][jj] = 0.f;

#pragma unroll 8
        for (int d = 0; d < 64; d++) {
            float4 qv = *(const float4*)&Qs[d][i0];
            float4 kv = *(const float4*)&Ks[d][j0];
            float qa[4] = {qv.x, qv.y, qv.z, qv.w};
            float ka[4] = {kv.x, kv.y, kv.z, kv.w};
#pragma unroll
            for (int ii = 0; ii < 4; ii++)
#pragma unroll
                for (int jj = 0; jj < 4; jj++)
                    s[ii][jj] += qa[ii] * ka[jj];
        }

        // Causal mask on the diagonal block
        if (jb == qb) {
#pragma unroll
            for (int ii = 0; ii < 4; ii++)
#pragma unroll
                for (int jj = 0; jj < 4; jj++)
                    if (j0 + jj > i0 + ii) s[ii][jj] = -3.0e38f;
        }

        // Online softmax (rows owned by the 16 lanes sharing ty)
#pragma unroll
        for (int ii = 0; ii < 4; ii++) {
            float mr = fmaxf(fmaxf(s[ii][0], s[ii][1]), fmaxf(s[ii][2], s[ii][3]));
            mr = fmaxf(mr, __shfl_xor_sync(0xffffffffu, mr, 1));
            mr = fmaxf(mr, __shfl_xor_sync(0xffffffffu, mr, 2));
            mr = fmaxf(mr, __shfl_xor_sync(0xffffffffu, mr, 4));
            mr = fmaxf(mr, __shfl_xor_sync(0xffffffffu, mr, 8));
            float mn = fmaxf(m[ii], mr);
            float alpha = __expf(m[ii] - mn);
            float rs = 0.f;
#pragma unroll
            for (int jj = 0; jj < 4; jj++) {
                float p = __expf(s[ii][jj] - mn);
                s[ii][jj] = p;
                rs += p;
            }
            rs += __shfl_xor_sync(0xffffffffu, rs, 1);
            rs += __shfl_xor_sync(0xffffffffu, rs, 2);
            rs += __shfl_xor_sync(0xffffffffu, rs, 4);
            rs += __shfl_xor_sync(0xffffffffu, rs, 8);
            l[ii] = l[ii] * alpha + rs;
            m[ii] = mn;
#pragma unroll
            for (int dd = 0; dd < 4; dd++) o[ii][dd] *= alpha;
#pragma unroll
            for (int jj = 0; jj < 4; jj++)
                Ps[i0 + ii][j0 + jj] = s[ii][jj];
        }
        __syncthreads();

        // O += P V (thread owns rows i0..i0+3, cols tx*4..tx*4+3)
#pragma unroll 8
        for (int j = 0; j < 64; j++) {
            float4 vv = *(const float4*)&Vs[j][tx * 4];
            float va[4] = {vv.x, vv.y, vv.z, vv.w};
            float p0 = Ps[i0 + 0][j];
            float p1 = Ps[i0 + 1][j];
            float p2 = Ps[i0 + 2][j];
            float p3 = Ps[i0 + 3][j];
#pragma unroll
            for (int dd = 0; dd < 4; dd++) {
                o[0][dd] += p0 * va[dd];
                o[1][dd] += p1 * va[dd];
                o[2][dd] += p2 * va[dd];
                o[3][dd] += p3 * va[dd];
            }
        }
    }

    // Epilogue: normalize and store (row-major [B*T, D])
#pragma unroll
    for (int ii = 0; ii < 4; ii++) {
        float inv = 1.0f / l[ii];
        float4 ov = make_float4(o[ii][0] * inv, o[ii][1] * inv,
                                o[ii][2] * inv, o[ii][3] * inv);
        size_t yoff = ((size_t)(b * TT + qb * 64 + i0 + ii)) * DD + h * HDIM + tx * 4;
        *(float4*)&Y[yoff] = ov;
    }
}

// ---------------------------------------------------------------------------
// Launch
// inputs: x, Wq, bq, Wk, bk, Wv, bv, Wo, bo  (all fp32)
// ---------------------------------------------------------------------------
extern "C" void kernel_launch(void* const* d_in, const int* in_sizes, int n_in,
                              void* d_out, int out_size)
{
    const float* x  = (const float*)d_in[0];
    const float* Wq = (const float*)d_in[1];
    const float* bq = (const float*)d_in[2];
    const float* Wk = (const float*)d_in[3];
    const float* bk = (const float*)d_in[4];
    const float* Wv = (const float*)d_in[5];
    const float* bv = (const float*)d_in[6];
    const float* Wo = (const float*)d_in[7];
    const float* bo = (const float*)d_in[8];
    float* out = (float*)d_out;

    float *q, *k, *v, *y;
    cudaGetSymbolAddress((void**)&q, g_q);
    cudaGetSymbolAddress((void**)&k, g_k);
    cudaGetSymbolAddress((void**)&v, g_v);
    cudaGetSymbolAddress((void**)&y, g_y);

    dim3 gproj(DD / 128, MROWS / 128);   // (8, 64)

    sgemm_nt_bias<<<gproj, 256>>>(x, Wq, bq, q, MROWS, DD, DD);
    sgemm_nt_bias<<<gproj, 256>>>(x, Wk, bk, k, MROWS, DD, DD);
    sgemm_nt_bias<<<gproj, 256>>>(x, Wv, bv, v, MROWS, DD, DD);

    rope_kernel<<<(BB * TT * HH * 32) / 256, 256>>>(q, k);

    const int attn_smem = 4 * 64 * 68 * 4;  // 69632 B
    cudaFuncSetAttribute(attn_kernel, cudaFuncAttributeMaxDynamicSharedMemorySize, attn_smem);
    attn_kernel<<<dim3(TT / 64, BB * HH), 256, attn_smem>>>(q, k, v, y);

    sgemm_nt_bias<<<gproj, 256>>>(y, Wo, bo, out, MROWS, DD, DD);
}

// round 3
// speedup vs baseline: 1.4491x; 1.4491x over previous
#include <cuda_runtime.h>
#include <cuda_bf16.h>
#include <math.h>
#include <cstdint>

#define BB 4
#define TT 2048
#define DD 1024
#define HH 16
#define HDIM 64
#define MROWS (BB*TT)   // 8192

typedef __nv_bfloat16 bf16;

// ---------------------------------------------------------------------------
// Scratch (device globals — no allocation allowed)
// ---------------------------------------------------------------------------
__device__ float g_q[MROWS * DD];
__device__ float g_k[MROWS * DD];
__device__ float g_v[MROWS * DD];
__device__ float g_y[MROWS * DD];
__device__ bf16  g_xh[MROWS * DD];
__device__ bf16  g_xl[MROWS * DD];
__device__ bf16  g_yh[MROWS * DD];
__device__ bf16  g_yl[MROWS * DD];
__device__ bf16  g_wh[4 * DD * DD];   // Wq,Wk,Wv,Wo hi parts
__device__ bf16  g_wl[4 * DD * DD];   // lo parts

// ---------------------------------------------------------------------------
// Split fp32 -> bf16 hi + bf16 lo
// ---------------------------------------------------------------------------
__global__ void split_kernel(const float* __restrict__ src,
                             bf16* __restrict__ hi, bf16* __restrict__ lo, int n)
{
    int i = blockIdx.x * blockDim.x + threadIdx.x;
    if (i < n) {
        float v = src[i];
        bf16 h = __float2bfloat16_rn(v);
        hi[i] = h;
        lo[i] = __float2bfloat16_rn(v - __bfloat162float(h));
    }
}

// ---------------------------------------------------------------------------
// Split-bf16 GEMM on tensor cores (mma.sync.m16n8k16.row.col.f32.bf16.bf16.f32)
// C[m,n] = sum_k A[m,k]*W[n,k] + bias[n], computed as Ah*Wh + Ah*Wl + Al*Wh.
// A: [M,1024] row-major (hi/lo), W: [N,1024] row-major (hi/lo).
// Block 128x128, BK=32, 256 threads = 8 warps (2 x 4), warp tile 64x32.
// ---------------------------------------------------------------------------
#define GK 1024
#define BK 32
#define SSTR 40   // padded smem stride (halves): banks 20*i mod 32 distinct

__device__ __forceinline__ uint32_t smem_u32(const void* p) {
    return (uint32_t)__cvta_generic_to_shared(p);
}

__global__ void __launch_bounds__(256, 2) gemm_bf16x3(
    const bf16* __restrict__ Ah, const bf16* __restrict__ Al,
    const bf16* __restrict__ Wh, const bf16* __restrict__ Wl,
    const float* __restrict__ bias, float* __restrict__ C, int N)
{
    __shared__ bf16 As[2][128][SSTR];
    __shared__ bf16 Bs[2][128][SSTR];

    const int tid  = threadIdx.x;
    const int lane = tid & 31;
    const int wid  = tid >> 5;
    const int warpM = wid >> 2;   // 0..1
    const int warpN = wid & 3;    // 0..3

    const int rowBase = blockIdx.y * 128;
    const int colBase = blockIdx.x * 128;

    // loader: each thread loads 2x 16B from A and 2x 16B from W per stage
    const int lr = tid >> 2;          // 0..63
    const int lc = (tid & 3) * 8;     // 0,8,16,24 (halves)

    float acc[4][4][4];
#pragma unroll
    for (int mf = 0; mf < 4; mf++)
#pragma unroll
        for (int nf = 0; nf < 4; nf++)
#pragma unroll
            for (int r = 0; r < 4; r++) acc[mf][nf][r] = 0.f;

    const int nIter = 3 * (GK / BK);  // 96

    uint4 ra0, ra1, rb0, rb1;

    // ldmatrix source offsets (same formula for A and B tiles)
    const int lm_row = (lane & 15);
    const int lm_col = ((lane >> 4) << 3);

    // ---- prologue: load iter 0 ----
    {
        const bf16* Ab = Ah;
        const bf16* Wb = Wh;
        ra0 = *(const uint4*)(Ab + (size_t)(rowBase + lr) * GK + lc);
        ra1 = *(const uint4*)(Ab + (size_t)(rowBase + lr + 64) * GK + lc);
        rb0 = *(const uint4*)(Wb + (size_t)(colBase + lr) * GK + lc);
        rb1 = *(const uint4*)(Wb + (size_t)(colBase + lr + 64) * GK + lc);
        *(uint4*)&As[0][lr][lc]      = ra0;
        *(uint4*)&As[0][lr + 64][lc] = ra1;
        *(uint4*)&Bs[0][lr][lc]      = rb0;
        *(uint4*)&Bs[0][lr + 64][lc] = rb1;
    }
    __syncthreads();

    for (int iter = 0; iter < nIter; iter++) {
        const int buf = iter & 1;

        // prefetch next stage into registers
        if (iter + 1 < nIter) {
            int kk  = (iter + 1) * BK;
            int seg = kk >> 10;           // GK = 1024
            int kloc = kk & (GK - 1);
            const bf16* Ab = (seg < 2) ? Ah : Al;
            const bf16* Wb = (seg == 1) ? Wl : Wh;
            ra0 = *(const uint4*)(Ab + (size_t)(rowBase + lr) * GK + kloc + lc);
            ra1 = *(const uint4*)(Ab + (size_t)(rowBase + lr + 64) * GK + kloc + lc);
            rb0 = *(const uint4*)(Wb + (size_t)(colBase + lr) * GK + kloc + lc);
            rb1 = *(const uint4*)(Wb + (size_t)(colBase + lr + 64) * GK + kloc + lc);
        }

        // compute 2 k-steps of 16 from smem[buf]
#pragma unroll
        for (int ks = 0; ks < BK; ks += 16) {
            uint32_t a[4][4];
#pragma unroll
            for (int mf = 0; mf < 4; mf++) {
                uint32_t addr = smem_u32(&As[buf][warpM * 64 + mf * 16 + lm_row][ks + lm_col]);
                asm volatile("ldmatrix.sync.aligned.m8n8.x4.shared.b16 {%0,%1,%2,%3}, [%4];\n"
                             : "=r"(a[mf][0]), "=r"(a[mf][1]), "=r"(a[mf][2]), "=r"(a[mf][3])
                             : "r"(addr));
            }
            uint32_t b[4][2];
#pragma unroll
            for (int p = 0; p < 2; p++) {
                uint32_t addr = smem_u32(&Bs[buf][warpN * 32 + p * 16 + lm_row][ks + lm_col]);
                uint32_t r0, r1, r2, r3;
                asm volatile("ldmatrix.sync.aligned.m8n8.x4.shared.b16 {%0,%1,%2,%3}, [%4];\n"
                             : "=r"(r0), "=r"(r1), "=r"(r2), "=r"(r3)
                             : "r"(addr));
                b[2 * p][0] = r0; b[2 * p + 1][0] = r1;
                b[2 * p][1] = r2; b[2 * p + 1][1] = r3;
            }
#pragma unroll
            for (int mf = 0; mf < 4; mf++)
#pragma unroll
                for (int nf = 0; nf < 4; nf++) {
                    asm volatile(
                        "mma.sync.aligned.m16n8k16.row.col.f32.bf16.bf16.f32 "
                        "{%0,%1,%2,%3}, {%4,%5,%6,%7}, {%8,%9}, {%0,%1,%2,%3};\n"
                        : "+f"(acc[mf][nf][0]), "+f"(acc[mf][nf][1]),
                          "+f"(acc[mf][nf][2]), "+f"(acc[mf][nf][3])
                        : "r"(a[mf][0]), "r"(a[mf][1]), "r"(a[mf][2]), "r"(a[mf][3]),
                          "r"(b[nf][0]), "r"(b[nf][1]));
                }
        }

        // stage next buffer
        if (iter + 1 < nIter) {
            const int nb = (iter + 1) & 1;
            *(uint4*)&As[nb][lr][lc]      = ra0;
            *(uint4*)&As[nb][lr + 64][lc] = ra1;
            *(uint4*)&Bs[nb][lr][lc]      = rb0;
            *(uint4*)&Bs[nb][lr + 64][lc] = rb1;
        }
        __syncthreads();
    }

    // epilogue: C = acc + bias
#pragma unroll
    for (int mf = 0; mf < 4; mf++)
#pragma unroll
        for (int nf = 0; nf < 4; nf++) {
            int m0 = rowBase + warpM * 64 + mf * 16 + (lane >> 2);
            int n0 = colBase + warpN * 32 + nf * 8 + (lane & 3) * 2;
            float b0 = bias[n0], b1 = bias[n0 + 1];
            float2 o0 = make_float2(acc[mf][nf][0] + b0, acc[mf][nf][1] + b1);
            float2 o1 = make_float2(acc[mf][nf][2] + b0, acc[mf][nf][3] + b1);
            *(float2*)&C[(size_t)m0 * N + n0]       = o0;
            *(float2*)&C[(size_t)(m0 + 8) * N + n0] = o1;
        }
}

// ---------------------------------------------------------------------------
// RoPE (in-place on Q and K, layout [B*T, D] with head-major cols h*64+d).
// ---------------------------------------------------------------------------
__global__ void rope_kernel(float* __restrict__ Q, float* __restrict__ K)
{
    int idx = blockIdx.x * blockDim.x + threadIdx.x;
    int i = idx & 31;
    int h = (idx >> 5) & (HH - 1);
    int t = (idx >> 9) & (TT - 1);
    int b = idx >> 20;

    size_t base = ((size_t)(b * TT + t)) * DD + h * HDIM;

    float theta = expf(-(float)i * (logf(10000.f) / 32.f));
    float ang = (float)(t + 1) * theta;
    float s, c;
    sincosf(ang, &s, &c);

    float q1 = Q[base + i], q2 = Q[base + i + 32];
    Q[base + i]      = q1 * c - q2 * s;
    Q[base + i + 32] = q2 * c + q1 * s;

    float k1 = K[base + i], k2 = K[base + i + 32];
    K[base + i]      = k1 * c - k2 * s;
    K[base + i + 32] = k2 * c + k1 * s;
}

// ---------------------------------------------------------------------------
// Flash attention (fp32, causal). 64x64 Q tile per block, 256 threads.
// ---------------------------------------------------------------------------
__global__ void __launch_bounds__(256) attn_kernel(
    const float* __restrict__ Q, const float* __restrict__ K,
    const float* __restrict__ V, float* __restrict__ Y)
{
    extern __shared__ float sm[];
    float (*Qs)[68] = (float(*)[68])(sm);
    float (*Ks)[68] = (float(*)[68])(sm + 64 * 68);
    float (*Vs)[68] = (float(*)[68])(sm + 2 * 64 * 68);
    float (*Ps)[68] = (float(*)[68])(sm + 3 * 64 * 68);

    const int tid = threadIdx.x;
    const int ty = tid >> 4;
    const int tx = tid & 15;
    const int i0 = ty * 4;
    const int j0 = tx * 4;

    const int qb = blockIdx.x;
    const int bh = blockIdx.y;
    const int b = bh >> 4;
    const int h = bh & 15;

    const size_t headBase = ((size_t)b * TT) * DD + h * HDIM;

    for (int idx = tid; idx < 64 * 64; idx += 256) {
        int i = idx >> 6, d = idx & 63;
        Qs[d][i] = Q[headBase + (size_t)(qb * 64 + i) * DD + d] * 0.125f;
    }

    float o[4][4];
    float m[4], l[4];
#pragma unroll
    for (int ii = 0; ii < 4; ii++) {
        m[ii] = -3.0e38f; l[ii] = 0.f;
#pragma unroll
        for (int dd = 0; dd < 4; dd++) o[ii][dd] = 0.f;
    }

    for (int jb = 0; jb <= qb; jb++) {
        __syncthreads();
        for (int idx = tid; idx < 64 * 64; idx += 256) {
            int j = idx >> 6, d = idx & 63;
            size_t g = headBase + (size_t)(jb * 64 + j) * DD + d;
            Ks[d][j] = K[g];
            Vs[j][d] = V[g];
        }
        __syncthreads();

        float s[4][4];
#pragma unroll
        for (int ii = 0; ii < 4; ii++)
#pragma unroll
            for (int jj = 0; jj < 4; jj++) s[ii][jj] = 0.f;

#pragma unroll 8
        for (int d = 0; d < 64; d++) {
            float4 qv = *(const float4*)&Qs[d][i0];
            float4 kv = *(const float4*)&Ks[d][j0];
            float qa[4] = {qv.x, qv.y, qv.z, qv.w};
            float ka[4] = {kv.x, kv.y, kv.z, kv.w};
#pragma unroll
            for (int ii = 0; ii < 4; ii++)
#pragma unroll
                for (int jj = 0; jj < 4; jj++)
                    s[ii][jj] += qa[ii] * ka[jj];
        }

        if (jb == qb) {
#pragma unroll
            for (int ii = 0; ii < 4; ii++)
#pragma unroll
                for (int jj = 0; jj < 4; jj++)
                    if (j0 + jj > i0 + ii) s[ii][jj] = -3.0e38f;
        }

#pragma unroll
        for (int ii = 0; ii < 4; ii++) {
            float mr = fmaxf(fmaxf(s[ii][0], s[ii][1]), fmaxf(s[ii][2], s[ii][3]));
            mr = fmaxf(mr, __shfl_xor_sync(0xffffffffu, mr, 1));
            mr = fmaxf(mr, __shfl_xor_sync(0xffffffffu, mr, 2));
            mr = fmaxf(mr, __shfl_xor_sync(0xffffffffu, mr, 4));
            mr = fmaxf(mr, __shfl_xor_sync(0xffffffffu, mr, 8));
            float mn = fmaxf(m[ii], mr);
            float alpha = __expf(m[ii] - mn);
            float rs = 0.f;
#pragma unroll
            for (int jj = 0; jj < 4; jj++) {
                float p = __expf(s[ii][jj] - mn);
                s[ii][jj] = p;
                rs += p;
            }
            rs += __shfl_xor_sync(0xffffffffu, rs, 1);
            rs += __shfl_xor_sync(0xffffffffu, rs, 2);
            rs += __shfl_xor_sync(0xffffffffu, rs, 4);
            rs += __shfl_xor_sync(0xffffffffu, rs, 8);
            l[ii] = l[ii] * alpha + rs;
            m[ii] = mn;
#pragma unroll
            for (int dd = 0; dd < 4; dd++) o[ii][dd] *= alpha;
#pragma unroll
            for (int jj = 0; jj < 4; jj++)
                Ps[i0 + ii][j0 + jj] = s[ii][jj];
        }
        __syncthreads();

#pragma unroll 8
        for (int j = 0; j < 64; j++) {
            float4 vv = *(const float4*)&Vs[j][tx * 4];
            float va[4] = {vv.x, vv.y, vv.z, vv.w};
            float p0 = Ps[i0 + 0][j];
            float p1 = Ps[i0 + 1][j];
            float p2 = Ps[i0 + 2][j];
            float p3 = Ps[i0 + 3][j];
#pragma unroll
            for (int dd = 0; dd < 4; dd++) {
                o[0][dd] += p0 * va[dd];
                o[1][dd] += p1 * va[dd];
                o[2][dd] += p2 * va[dd];
                o[3][dd] += p3 * va[dd];
            }
        }
    }

#pragma unroll
    for (int ii = 0; ii < 4; ii++) {
        float inv = 1.0f / l[ii];
        float4 ov = make_float4(o[ii][0] * inv, o[ii][1] * inv,
                                o[ii][2] * inv, o[ii][3] * inv);
        size_t yoff = ((size_t)(b * TT + qb * 64 + i0 + ii)) * DD + h * HDIM + tx * 4;
        *(float4*)&Y[yoff] = ov;
    }
}

// ---------------------------------------------------------------------------
// Launch: x, Wq, bq, Wk, bk, Wv, bv, Wo, bo (all fp32)
// ---------------------------------------------------------------------------
extern "C" void kernel_launch(void* const* d_in, const int* in_sizes, int n_in,
                              void* d_out, int out_size)
{
    const float* x  = (const float*)d_in[0];
    const float* Wq = (const float*)d_in[1];
    const float* bq = (const float*)d_in[2];
    const float* Wk = (const float*)d_in[3];
    const float* bk = (const float*)d_in[4];
    const float* Wv = (const float*)d_in[5];
    const float* bv = (const float*)d_in[6];
    const float* Wo = (const float*)d_in[7];
    const float* bo = (const float*)d_in[8];
    float* out = (float*)d_out;

    float *q, *k, *v, *y;
    bf16 *xh, *xl, *yh, *yl, *wh, *wl;
    cudaGetSymbolAddress((void**)&q,  g_q);
    cudaGetSymbolAddress((void**)&k,  g_k);
    cudaGetSymbolAddress((void**)&v,  g_v);
    cudaGetSymbolAddress((void**)&y,  g_y);
    cudaGetSymbolAddress((void**)&xh, g_xh);
    cudaGetSymbolAddress((void**)&xl, g_xl);
    cudaGetSymbolAddress((void**)&yh, g_yh);
    cudaGetSymbolAddress((void**)&yl, g_yl);
    cudaGetSymbolAddress((void**)&wh, g_wh);
    cudaGetSymbolAddress((void**)&wl, g_wl);

    const int nX = MROWS * DD;       // 8M
    const int nW = DD * DD;          // 1M

    // splits
    split_kernel<<<(nX + 255) / 256, 256>>>(x, xh, xl, nX);
    split_kernel<<<(nW + 255) / 256, 256>>>(Wq, wh + 0 * nW, wl + 0 * nW, nW);
    split_kernel<<<(nW + 255) / 256, 256>>>(Wk, wh + 1 * nW, wl + 1 * nW, nW);
    split_kernel<<<(nW + 255) / 256, 256>>>(Wv, wh + 2 * nW, wl + 2 * nW, nW);
    split_kernel<<<(nW + 255) / 256, 256>>>(Wo, wh + 3 * nW, wl + 3 * nW, nW);

    dim3 gproj(DD / 128, MROWS / 128);   // (8, 64)

    gemm_bf16x3<<<gproj, 256>>>(xh, xl, wh + 0 * nW, wl + 0 * nW, bq, q, DD);
    gemm_bf16x3<<<gproj, 256>>>(xh, xl, wh + 1 * nW, wl + 1 * nW, bk, k, DD);
    gemm_bf16x3<<<gproj, 256>>>(xh, xl, wh + 2 * nW, wl + 2 * nW, bv, v, DD);

    rope_kernel<<<(BB * TT * HH * 32) / 256, 256>>>(q, k);

    const int attn_smem = 4 * 64 * 68 * 4;  // 69632 B
    cudaFuncSetAttribute(attn_kernel, cudaFuncAttributeMaxDynamicSharedMemorySize, attn_smem);
    attn_kernel<<<dim3(TT / 64, BB * HH), 256, attn_smem>>>(q, k, v, y);

    split_kernel<<<(nX + 255) / 256, 256>>>(y, yh, yl, nX);
    gemm_bf16x3<<<gproj, 256>>>(yh, yl, wh + 3 * nW, wl + 3 * nW, bo, out, DD);
}

// round 4
// speedup vs baseline: 1.9435x; 1.3412x over previous
#include <cuda_runtime.h>
#include <cuda_bf16.h>
#include <math.h>
#include <cstdint>

#define BB 4
#define TT 2048
#define DD 1024
#define HH 16
#define HDIM 64
#define MROWS (BB*TT)   // 8192

typedef __nv_bfloat16 bf16;

// ---------------------------------------------------------------------------
// Scratch (device globals — no allocation allowed)
// ---------------------------------------------------------------------------
__device__ float g_q[MROWS * DD];
__device__ float g_k[MROWS * DD];
__device__ float g_v[MROWS * DD];
__device__ float g_y[MROWS * DD];
__device__ bf16  g_xh[MROWS * DD];
__device__ bf16  g_xl[MROWS * DD];
__device__ bf16  g_yh[MROWS * DD];
__device__ bf16  g_yl[MROWS * DD];
__device__ bf16  g_wh[4 * DD * DD];   // Wq,Wk,Wv,Wo hi parts
__device__ bf16  g_wl[4 * DD * DD];   // lo parts

__device__ __forceinline__ uint32_t smem_u32(const void* p) {
    return (uint32_t)__cvta_generic_to_shared(p);
}

__device__ __forceinline__ void split1(float v, bf16& h, bf16& l) {
    h = __float2bfloat16_rn(v);
    l = __float2bfloat16_rn(v - __bfloat162float(h));
}

__device__ __forceinline__ void split2(float x, float y, uint32_t& hi, uint32_t& lo) {
    bf16 hx, lx, hy, ly;
    split1(x, hx, lx);
    split1(y, hy, ly);
    __nv_bfloat162 H = __halves2bfloat162(hx, hy);
    __nv_bfloat162 L = __halves2bfloat162(lx, ly);
    hi = *reinterpret_cast<uint32_t*>(&H);
    lo = *reinterpret_cast<uint32_t*>(&L);
}

__device__ __forceinline__ void mma16816(float* c, const uint32_t* a, const uint32_t* b) {
    asm volatile(
        "mma.sync.aligned.m16n8k16.row.col.f32.bf16.bf16.f32 "
        "{%0,%1,%2,%3}, {%4,%5,%6,%7}, {%8,%9}, {%0,%1,%2,%3};\n"
        : "+f"(c[0]), "+f"(c[1]), "+f"(c[2]), "+f"(c[3])
        : "r"(a[0]), "r"(a[1]), "r"(a[2]), "r"(a[3]), "r"(b[0]), "r"(b[1]));
}

__device__ __forceinline__ void ldsm4(uint32_t& r0, uint32_t& r1, uint32_t& r2, uint32_t& r3,
                                      uint32_t addr) {
    asm volatile("ldmatrix.sync.aligned.m8n8.x4.shared.b16 {%0,%1,%2,%3}, [%4];\n"
                 : "=r"(r0), "=r"(r1), "=r"(r2), "=r"(r3) : "r"(addr));
}

// ---------------------------------------------------------------------------
// Split fp32 -> bf16 hi + bf16 lo
// ---------------------------------------------------------------------------
__global__ void split_kernel(const float* __restrict__ src,
                             bf16* __restrict__ hi, bf16* __restrict__ lo, int n)
{
    int i = blockIdx.x * blockDim.x + threadIdx.x;
    if (i < n) {
        float v = src[i];
        bf16 h = __float2bfloat16_rn(v);
        hi[i] = h;
        lo[i] = __float2bfloat16_rn(v - __bfloat162float(h));
    }
}

// ---------------------------------------------------------------------------
// Split-bf16 GEMM on tensor cores (validated round 3)
// ---------------------------------------------------------------------------
#define GK 1024
#define BK 32
#define SSTR 40

__global__ void __launch_bounds__(256, 2) gemm_bf16x3(
    const bf16* __restrict__ Ah, const bf16* __restrict__ Al,
    const bf16* __restrict__ Wh, const bf16* __restrict__ Wl,
    const float* __restrict__ bias, float* __restrict__ C, int N)
{
    __shared__ bf16 As[2][128][SSTR];
    __shared__ bf16 Bs[2][128][SSTR];

    const int tid  = threadIdx.x;
    const int lane = tid & 31;
    const int wid  = tid >> 5;
    const int warpM = wid >> 2;
    const int warpN = wid & 3;

    const int rowBase = blockIdx.y * 128;
    const int colBase = blockIdx.x * 128;

    const int lr = tid >> 2;
    const int lc = (tid & 3) * 8;

    float acc[4][4][4];
#pragma unroll
    for (int mf = 0; mf < 4; mf++)
#pragma unroll
        for (int nf = 0; nf < 4; nf++)
#pragma unroll
            for (int r = 0; r < 4; r++) acc[mf][nf][r] = 0.f;

    const int nIter = 3 * (GK / BK);

    uint4 ra0, ra1, rb0, rb1;

    const int lm_row = (lane & 15);
    const int lm_col = ((lane >> 4) << 3);

    {
        ra0 = *(const uint4*)(Ah + (size_t)(rowBase + lr) * GK + lc);
        ra1 = *(const uint4*)(Ah + (size_t)(rowBase + lr + 64) * GK + lc);
        rb0 = *(const uint4*)(Wh + (size_t)(colBase + lr) * GK + lc);
        rb1 = *(const uint4*)(Wh + (size_t)(colBase + lr + 64) * GK + lc);
        *(uint4*)&As[0][lr][lc]      = ra0;
        *(uint4*)&As[0][lr + 64][lc] = ra1;
        *(uint4*)&Bs[0][lr][lc]      = rb0;
        *(uint4*)&Bs[0][lr + 64][lc] = rb1;
    }
    __syncthreads();

    for (int iter = 0; iter < nIter; iter++) {
        const int buf = iter & 1;

        if (iter + 1 < nIter) {
            int kk  = (iter + 1) * BK;
            int seg = kk >> 10;
            int kloc = kk & (GK - 1);
            const bf16* Ab = (seg < 2) ? Ah : Al;
            const bf16* Wb = (seg == 1) ? Wl : Wh;
            ra0 = *(const uint4*)(Ab + (size_t)(rowBase + lr) * GK + kloc + lc);
            ra1 = *(const uint4*)(Ab + (size_t)(rowBase + lr + 64) * GK + kloc + lc);
            rb0 = *(const uint4*)(Wb + (size_t)(colBase + lr) * GK + kloc + lc);
            rb1 = *(const uint4*)(Wb + (size_t)(colBase + lr + 64) * GK + kloc + lc);
        }

#pragma unroll
        for (int ks = 0; ks < BK; ks += 16) {
            uint32_t a[4][4];
#pragma unroll
            for (int mf = 0; mf < 4; mf++) {
                uint32_t addr = smem_u32(&As[buf][warpM * 64 + mf * 16 + lm_row][ks + lm_col]);
                ldsm4(a[mf][0], a[mf][1], a[mf][2], a[mf][3], addr);
            }
            uint32_t b[4][2];
#pragma unroll
            for (int p = 0; p < 2; p++) {
                uint32_t addr = smem_u32(&Bs[buf][warpN * 32 + p * 16 + lm_row][ks + lm_col]);
                uint32_t r0, r1, r2, r3;
                ldsm4(r0, r1, r2, r3, addr);
                b[2 * p][0] = r0; b[2 * p + 1][0] = r1;
                b[2 * p][1] = r2; b[2 * p + 1][1] = r3;
            }
#pragma unroll
            for (int mf = 0; mf < 4; mf++)
#pragma unroll
                for (int nf = 0; nf < 4; nf++)
                    mma16816(acc[mf][nf], a[mf], b[nf]);
        }

        if (iter + 1 < nIter) {
            const int nb = (iter + 1) & 1;
            *(uint4*)&As[nb][lr][lc]      = ra0;
            *(uint4*)&As[nb][lr + 64][lc] = ra1;
            *(uint4*)&Bs[nb][lr][lc]      = rb0;
            *(uint4*)&Bs[nb][lr + 64][lc] = rb1;
        }
        __syncthreads();
    }

#pragma unroll
    for (int mf = 0; mf < 4; mf++)
#pragma unroll
        for (int nf = 0; nf < 4; nf++) {
            int m0 = rowBase + warpM * 64 + mf * 16 + (lane >> 2);
            int n0 = colBase + warpN * 32 + nf * 8 + (lane & 3) * 2;
            float b0 = bias[n0], b1 = bias[n0 + 1];
            float2 o0 = make_float2(acc[mf][nf][0] + b0, acc[mf][nf][1] + b1);
            float2 o1 = make_float2(acc[mf][nf][2] + b0, acc[mf][nf][3] + b1);
            *(float2*)&C[(size_t)m0 * N + n0]       = o0;
            *(float2*)&C[(size_t)(m0 + 8) * N + n0] = o1;
        }
}

// ---------------------------------------------------------------------------
// RoPE (in-place on Q and K)
// ---------------------------------------------------------------------------
__global__ void rope_kernel(float* __restrict__ Q, float* __restrict__ K)
{
    int idx = blockIdx.x * blockDim.x + threadIdx.x;
    int i = idx & 31;
    int h = (idx >> 5) & (HH - 1);
    int t = (idx >> 9) & (TT - 1);
    int b = idx >> 20;

    size_t base = ((size_t)(b * TT + t)) * DD + h * HDIM;

    float theta = expf(-(float)i * (logf(10000.f) / 32.f));
    float ang = (float)(t + 1) * theta;
    float s, c;
    sincosf(ang, &s, &c);

    float q1 = Q[base + i], q2 = Q[base + i + 32];
    Q[base + i]      = q1 * c - q2 * s;
    Q[base + i + 32] = q2 * c + q1 * s;

    float k1 = K[base + i], k2 = K[base + i + 32];
    K[base + i]      = k1 * c - k2 * s;
    K[base + i + 32] = k2 * c + k1 * s;
}

// ---------------------------------------------------------------------------
// Flash attention with split-bf16 tensor-core mma.
// Block: 128 q-rows of one (b,h). 8 warps, warp m-tile 16 rows.
// j-tiles of 64 keys. S = QhKh+QhKl+QlKh; O += PhVh+PhVl+PlVh.
// Smem: Kh/Kl [j][d] 64x72, Vh/Vl transposed [d][j] 64x72 (bf16).
// ---------------------------------------------------------------------------
#define VSTR 72

__global__ void __launch_bounds__(256) attn_mma(
    const float* __restrict__ Q, const float* __restrict__ K,
    const float* __restrict__ V, float* __restrict__ Y)
{
    __shared__ bf16 Ksh[64][VSTR];
    __shared__ bf16 Ksl[64][VSTR];
    __shared__ bf16 Vsh[64][VSTR];   // transposed: [d][j]
    __shared__ bf16 Vsl[64][VSTR];

    const int tid  = threadIdx.x;
    const int lane = tid & 31;
    const int wid  = tid >> 5;           // 0..7
    const int g    = lane >> 2;          // 0..7
    const int t    = lane & 3;           // 0..3
    const int lm_row = lane & 15;
    const int lm_col = (lane >> 4) << 3;

    const int qb = (gridDim.x - 1) - blockIdx.x;   // heavy blocks first
    const int bh = blockIdx.y;
    const int b  = bh >> 4;
    const int h  = bh & 15;

    const size_t headBase = (size_t)b * TT * DD + h * HDIM;
    const int rowA = qb * 128 + wid * 16 + g;      // thread's first q-row (local t index)

    // ---- load Q fragments (scaled, split) ----
    uint32_t qh[4][4], ql[4][4];
#pragma unroll
    for (int kf = 0; kf < 4; kf++) {
        int c0 = kf * 16 + 2 * t;
        float2 v00 = *(const float2*)&Q[headBase + (size_t)rowA * DD + c0];
        float2 v10 = *(const float2*)&Q[headBase + (size_t)(rowA + 8) * DD + c0];
        float2 v01 = *(const float2*)&Q[headBase + (size_t)rowA * DD + c0 + 8];
        float2 v11 = *(const float2*)&Q[headBase + (size_t)(rowA + 8) * DD + c0 + 8];
        split2(v00.x * 0.125f, v00.y * 0.125f, qh[kf][0], ql[kf][0]);
        split2(v10.x * 0.125f, v10.y * 0.125f, qh[kf][1], ql[kf][1]);
        split2(v01.x * 0.125f, v01.y * 0.125f, qh[kf][2], ql[kf][2]);
        split2(v11.x * 0.125f, v11.y * 0.125f, qh[kf][3], ql[kf][3]);
    }

    float oa[8][4];
#pragma unroll
    for (int df = 0; df < 8; df++)
#pragma unroll
        for (int r = 0; r < 4; r++) oa[df][r] = 0.f;
    float m0 = -1e30f, m1 = -1e30f, l0 = 0.f, l1 = 0.f;

    const int vd = tid & 63;       // d for V transpose load
    const int vj = (tid >> 6) * 16;

    const int nTiles = 2 * qb + 2;
    for (int jt = 0; jt < nTiles; jt++) {
        // ---- fill K (row) and V (transposed) tiles, split to bf16 ----
#pragma unroll
        for (int e = tid; e < 1024; e += 256) {
            int j = e >> 4, d4 = (e & 15) * 4;
            float4 kv = *(const float4*)&K[headBase + (size_t)(jt * 64 + j) * DD + d4];
            bf16 hh, ll;
            split1(kv.x, hh, ll); Ksh[j][d4 + 0] = hh; Ksl[j][d4 + 0] = ll;
            split1(kv.y, hh, ll); Ksh[j][d4 + 1] = hh; Ksl[j][d4 + 1] = ll;
            split1(kv.z, hh, ll); Ksh[j][d4 + 2] = hh; Ksl[j][d4 + 2] = ll;
            split1(kv.w, hh, ll); Ksh[j][d4 + 3] = hh; Ksl[j][d4 + 3] = ll;
        }
#pragma unroll
        for (int jj = 0; jj < 16; jj++) {
            int j = vj + jj;
            float v = V[headBase + (size_t)(jt * 64 + j) * DD + vd];
            bf16 hh, ll;
            split1(v, hh, ll);
            Vsh[vd][j] = hh; Vsl[vd][j] = ll;
        }
        __syncthreads();

        // ---- S = Q K^T (split x3) ----
        float sa[8][4];
#pragma unroll
        for (int nf = 0; nf < 8; nf++)
#pragma unroll
            for (int r = 0; r < 4; r++) sa[nf][r] = 0.f;

#pragma unroll
        for (int kf = 0; kf < 4; kf++) {
            uint32_t kbh[8][2], kbl[8][2];
#pragma unroll
            for (int p = 0; p < 4; p++) {
                uint32_t r0, r1, r2, r3;
                uint32_t addr = smem_u32(&Ksh[p * 16 + lm_row][kf * 16 + lm_col]);
                ldsm4(r0, r1, r2, r3, addr);
                kbh[2 * p][0] = r0; kbh[2 * p + 1][0] = r1;
                kbh[2 * p][1] = r2; kbh[2 * p + 1][1] = r3;
                addr = smem_u32(&Ksl[p * 16 + lm_row][kf * 16 + lm_col]);
                ldsm4(r0, r1, r2, r3, addr);
                kbl[2 * p][0] = r0; kbl[2 * p + 1][0] = r1;
                kbl[2 * p][1] = r2; kbl[2 * p + 1][1] = r3;
            }
#pragma unroll
            for (int nf = 0; nf < 8; nf++) {
                mma16816(sa[nf], qh[kf], kbh[nf]);
                mma16816(sa[nf], qh[kf], kbl[nf]);
                mma16816(sa[nf], ql[kf], kbh[nf]);
            }
        }

        // ---- causal mask (only near diagonal) ----
        if (jt >= 2 * qb) {
#pragma unroll
            for (int nf = 0; nf < 8; nf++) {
                int col = jt * 64 + nf * 8 + 2 * t;
                if (col > rowA)         sa[nf][0] = -1e30f;
                if (col + 1 > rowA)     sa[nf][1] = -1e30f;
                if (col > rowA + 8)     sa[nf][2] = -1e30f;
                if (col + 1 > rowA + 8) sa[nf][3] = -1e30f;
            }
        }

        // ---- online softmax ----
        float mx0 = -1e30f, mx1 = -1e30f;
#pragma unroll
        for (int nf = 0; nf < 8; nf++) {
            mx0 = fmaxf(mx0, fmaxf(sa[nf][0], sa[nf][1]));
            mx1 = fmaxf(mx1, fmaxf(sa[nf][2], sa[nf][3]));
        }
        mx0 = fmaxf(mx0, __shfl_xor_sync(0xffffffffu, mx0, 1));
        mx0 = fmaxf(mx0, __shfl_xor_sync(0xffffffffu, mx0, 2));
        mx1 = fmaxf(mx1, __shfl_xor_sync(0xffffffffu, mx1, 1));
        mx1 = fmaxf(mx1, __shfl_xor_sync(0xffffffffu, mx1, 2));
        float mn0 = fmaxf(m0, mx0);
        float mn1 = fmaxf(m1, mx1);
        float al0 = __expf(m0 - mn0);
        float al1 = __expf(m1 - mn1);

        float sum0 = 0.f, sum1 = 0.f;
#pragma unroll
        for (int nf = 0; nf < 8; nf++) {
            sa[nf][0] = __expf(sa[nf][0] - mn0);
            sa[nf][1] = __expf(sa[nf][1] - mn0);
            sa[nf][2] = __expf(sa[nf][2] - mn1);
            sa[nf][3] = __expf(sa[nf][3] - mn1);
            sum0 += sa[nf][0] + sa[nf][1];
            sum1 += sa[nf][2] + sa[nf][3];
        }
        sum0 += __shfl_xor_sync(0xffffffffu, sum0, 1);
        sum0 += __shfl_xor_sync(0xffffffffu, sum0, 2);
        sum1 += __shfl_xor_sync(0xffffffffu, sum1, 1);
        sum1 += __shfl_xor_sync(0xffffffffu, sum1, 2);
        l0 = l0 * al0 + sum0;
        l1 = l1 * al1 + sum1;
        m0 = mn0; m1 = mn1;
#pragma unroll
        for (int df = 0; df < 8; df++) {
            oa[df][0] *= al0; oa[df][1] *= al0;
            oa[df][2] *= al1; oa[df][3] *= al1;
        }

        // ---- O += P V (split x3) ----
#pragma unroll
        for (int kk = 0; kk < 4; kk++) {
            uint32_t pha[4], pla[4];
            split2(sa[2 * kk][0],     sa[2 * kk][1],     pha[0], pla[0]);
            split2(sa[2 * kk][2],     sa[2 * kk][3],     pha[1], pla[1]);
            split2(sa[2 * kk + 1][0], sa[2 * kk + 1][1], pha[2], pla[2]);
            split2(sa[2 * kk + 1][2], sa[2 * kk + 1][3], pha[3], pla[3]);

            uint32_t vbh[8][2], vbl[8][2];
#pragma unroll
            for (int p = 0; p < 4; p++) {
                uint32_t r0, r1, r2, r3;
                uint32_t addr = smem_u32(&Vsh[p * 16 + lm_row][kk * 16 + lm_col]);
                ldsm4(r0, r1, r2, r3, addr);
                vbh[2 * p][0] = r0; vbh[2 * p + 1][0] = r1;
                vbh[2 * p][1] = r2; vbh[2 * p + 1][1] = r3;
                addr = smem_u32(&Vsl[p * 16 + lm_row][kk * 16 + lm_col]);
                ldsm4(r0, r1, r2, r3, addr);
                vbl[2 * p][0] = r0; vbl[2 * p + 1][0] = r1;
                vbl[2 * p][1] = r2; vbl[2 * p + 1][1] = r3;
            }
#pragma unroll
            for (int df = 0; df < 8; df++) {
                mma16816(oa[df], pha, vbh[df]);
                mma16816(oa[df], pha, vbl[df]);
                mma16816(oa[df], pla, vbh[df]);
            }
        }
        __syncthreads();
    }

    // ---- epilogue ----
    float inv0 = 1.0f / l0;
    float inv1 = 1.0f / l1;
#pragma unroll
    for (int df = 0; df < 8; df++) {
        int dcol = df * 8 + 2 * t;
        size_t off0 = headBase + (size_t)rowA * DD + dcol;
        size_t off1 = headBase + (size_t)(rowA + 8) * DD + dcol;
        *(float2*)&Y[off0] = make_float2(oa[df][0] * inv0, oa[df][1] * inv0);
        *(float2*)&Y[off1] = make_float2(oa[df][2] * inv1, oa[df][3] * inv1);
    }
}

// ---------------------------------------------------------------------------
// Launch: x, Wq, bq, Wk, bk, Wv, bv, Wo, bo (all fp32)
// ---------------------------------------------------------------------------
extern "C" void kernel_launch(void* const* d_in, const int* in_sizes, int n_in,
                              void* d_out, int out_size)
{
    const float* x  = (const float*)d_in[0];
    const float* Wq = (const float*)d_in[1];
    const float* bq = (const float*)d_in[2];
    const float* Wk = (const float*)d_in[3];
    const float* bk = (const float*)d_in[4];
    const float* Wv = (const float*)d_in[5];
    const float* bv = (const float*)d_in[6];
    const float* Wo = (const float*)d_in[7];
    const float* bo = (const float*)d_in[8];
    float* out = (float*)d_out;

    float *q, *k, *v, *y;
    bf16 *xh, *xl, *yh, *yl, *wh, *wl;
    cudaGetSymbolAddress((void**)&q,  g_q);
    cudaGetSymbolAddress((void**)&k,  g_k);
    cudaGetSymbolAddress((void**)&v,  g_v);
    cudaGetSymbolAddress((void**)&y,  g_y);
    cudaGetSymbolAddress((void**)&xh, g_xh);
    cudaGetSymbolAddress((void**)&xl, g_xl);
    cudaGetSymbolAddress((void**)&yh, g_yh);
    cudaGetSymbolAddress((void**)&yl, g_yl);
    cudaGetSymbolAddress((void**)&wh, g_wh);
    cudaGetSymbolAddress((void**)&wl, g_wl);

    const int nX = MROWS * DD;
    const int nW = DD * DD;

    split_kernel<<<(nX + 255) / 256, 256>>>(x, xh, xl, nX);
    split_kernel<<<(nW + 255) / 256, 256>>>(Wq, wh + 0 * nW, wl + 0 * nW, nW);
    split_kernel<<<(nW + 255) / 256, 256>>>(Wk, wh + 1 * nW, wl + 1 * nW, nW);
    split_kernel<<<(nW + 255) / 256, 256>>>(Wv, wh + 2 * nW, wl + 2 * nW, nW);
    split_kernel<<<(nW + 255) / 256, 256>>>(Wo, wh + 3 * nW, wl + 3 * nW, nW);

    dim3 gproj(DD / 128, MROWS / 128);

    gemm_bf16x3<<<gproj, 256>>>(xh, xl, wh + 0 * nW, wl + 0 * nW, bq, q, DD);
    gemm_bf16x3<<<gproj, 256>>>(xh, xl, wh + 1 * nW, wl + 1 * nW, bk, k, DD);
    gemm_bf16x3<<<gproj, 256>>>(xh, xl, wh + 2 * nW, wl + 2 * nW, bv, v, DD);

    rope_kernel<<<(BB * TT * HH * 32) / 256, 256>>>(q, k);

    attn_mma<<<dim3(TT / 128, BB * HH), 256>>>(q, k, v, y);

    split_kernel<<<(nX + 255) / 256, 256>>>(y, yh, yl, nX);
    gemm_bf16x3<<<gproj, 256>>>(yh, yl, wh + 3 * nW, wl + 3 * nW, bo, out, DD);
}

// round 5
// speedup vs baseline: 2.0794x; 1.0699x over previous
#include <cuda_runtime.h>
#include <cuda_bf16.h>
#include <math.h>
#include <cstdint>

#define BB 4
#define TT 2048
#define DD 1024
#define HH 16
#define HDIM 64
#define MROWS (BB*TT)   // 8192

typedef __nv_bfloat16 bf16;

// ---------------------------------------------------------------------------
// Scratch (device globals — no allocation allowed)
// ---------------------------------------------------------------------------
__device__ float g_q[MROWS * DD];
__device__ float g_k[MROWS * DD];
__device__ float g_v[MROWS * DD];
__device__ bf16  g_xh[MROWS * DD];
__device__ bf16  g_xl[MROWS * DD];
__device__ bf16  g_yh[MROWS * DD];
__device__ bf16  g_yl[MROWS * DD];
__device__ bf16  g_wh[4 * DD * DD];   // Wq,Wk,Wv,Wo hi parts
__device__ bf16  g_wl[4 * DD * DD];   // lo parts

__device__ __forceinline__ uint32_t smem_u32(const void* p) {
    return (uint32_t)__cvta_generic_to_shared(p);
}

__device__ __forceinline__ void split1(float v, bf16& h, bf16& l) {
    h = __float2bfloat16_rn(v);
    l = __float2bfloat16_rn(v - __bfloat162float(h));
}

__device__ __forceinline__ void split2(float x, float y, uint32_t& hi, uint32_t& lo) {
    bf16 hx, lx, hy, ly;
    split1(x, hx, lx);
    split1(y, hy, ly);
    __nv_bfloat162 H = __halves2bfloat162(hx, hy);
    __nv_bfloat162 L = __halves2bfloat162(lx, ly);
    hi = *reinterpret_cast<uint32_t*>(&H);
    lo = *reinterpret_cast<uint32_t*>(&L);
}

__device__ __forceinline__ void mma16816(float* c, const uint32_t* a, const uint32_t* b) {
    asm volatile(
        "mma.sync.aligned.m16n8k16.row.col.f32.bf16.bf16.f32 "
        "{%0,%1,%2,%3}, {%4,%5,%6,%7}, {%8,%9}, {%0,%1,%2,%3};\n"
        : "+f"(c[0]), "+f"(c[1]), "+f"(c[2]), "+f"(c[3])
        : "r"(a[0]), "r"(a[1]), "r"(a[2]), "r"(a[3]), "r"(b[0]), "r"(b[1]));
}

__device__ __forceinline__ void ldsm4(uint32_t& r0, uint32_t& r1, uint32_t& r2, uint32_t& r3,
                                      uint32_t addr) {
    asm volatile("ldmatrix.sync.aligned.m8n8.x4.shared.b16 {%0,%1,%2,%3}, [%4];\n"
                 : "=r"(r0), "=r"(r1), "=r"(r2), "=r"(r3) : "r"(addr));
}

__device__ __forceinline__ void cpa16(uint32_t saddr, const void* g) {
    asm volatile("cp.async.ca.shared.global [%0], [%1], 16;\n" :: "r"(saddr), "l"(g));
}
__device__ __forceinline__ void cpa_commit() {
    asm volatile("cp.async.commit_group;\n");
}
template <int N>
__device__ __forceinline__ void cpa_wait() {
    asm volatile("cp.async.wait_group %0;\n" :: "n"(N));
}

// ---------------------------------------------------------------------------
// Split fp32 -> bf16 hi + bf16 lo
// ---------------------------------------------------------------------------
__global__ void split_kernel(const float* __restrict__ src,
                             bf16* __restrict__ hi, bf16* __restrict__ lo, int n)
{
    int i = blockIdx.x * blockDim.x + threadIdx.x;
    if (i < n) {
        float v = src[i];
        bf16 h = __float2bfloat16_rn(v);
        hi[i] = h;
        lo[i] = __float2bfloat16_rn(v - __bfloat162float(h));
    }
}

// ---------------------------------------------------------------------------
// Split-bf16 GEMM, single K pass: load Ah/Al/Wh/Wl tiles per k-chunk once,
// do the 3 mma combos. cp.async 2-stage pipeline, 32 iterations.
// Block 128x128, BK=32, 256 threads = 8 warps (2x4), warp tile 64x32.
// Dynamic smem: 4 arrays x 2 stages x 128 x SSTR bf16 = 81920 B.
// ---------------------------------------------------------------------------
#define GK 1024
#define BK 32
#define SSTR 40
#define TILEH (128 * SSTR)

__global__ void __launch_bounds__(256) gemm_bf16x3(
    const bf16* __restrict__ Ah, const bf16* __restrict__ Al,
    const bf16* __restrict__ Wh, const bf16* __restrict__ Wl,
    const float* __restrict__ bias, float* __restrict__ C, int N)
{
    extern __shared__ bf16 smg[];
    bf16* sAh = smg;
    bf16* sAl = smg + 2 * TILEH;
    bf16* sBh = smg + 4 * TILEH;
    bf16* sBl = smg + 6 * TILEH;

    const int tid  = threadIdx.x;
    const int lane = tid & 31;
    const int wid  = tid >> 5;
    const int warpM = wid >> 2;
    const int warpN = wid & 3;

    const int rowBase = blockIdx.y * 128;
    const int colBase = blockIdx.x * 128;

    // loader mapping: row lr = tid>>1, halves lc = (tid&1)*16 (+0 and +8)
    const int lr = tid >> 1;
    const int lc = (tid & 1) * 16;

    const bf16* gAh = Ah + (size_t)(rowBase + lr) * GK + lc;
    const bf16* gAl = Al + (size_t)(rowBase + lr) * GK + lc;
    const bf16* gWh = Wh + (size_t)(colBase + lr) * GK + lc;
    const bf16* gWl = Wl + (size_t)(colBase + lr) * GK + lc;

    const uint32_t soff = (uint32_t)((lr * SSTR + lc) * 2);
    const uint32_t sAhB = smem_u32(sAh);
    const uint32_t sAlB = smem_u32(sAl);
    const uint32_t sBhB = smem_u32(sBh);
    const uint32_t sBlB = smem_u32(sBl);

    const int lm_row = (lane & 15);
    const int lm_col = ((lane >> 4) << 3);

    float acc[4][4][4];
#pragma unroll
    for (int mf = 0; mf < 4; mf++)
#pragma unroll
        for (int nf = 0; nf < 4; nf++)
#pragma unroll
            for (int r = 0; r < 4; r++) acc[mf][nf][r] = 0.f;

    const int nIter = GK / BK;   // 32

    // prologue: stage 0
    {
        uint32_t sb = 0;
        cpa16(sAhB + sb + soff,      gAh);
        cpa16(sAhB + sb + soff + 16, gAh + 8);
        cpa16(sAlB + sb + soff,      gAl);
        cpa16(sAlB + sb + soff + 16, gAl + 8);
        cpa16(sBhB + sb + soff,      gWh);
        cpa16(sBhB + sb + soff + 16, gWh + 8);
        cpa16(sBlB + sb + soff,      gWl);
        cpa16(sBlB + sb + soff + 16, gWl + 8);
        cpa_commit();
    }

    for (int iter = 0; iter < nIter; iter++) {
        const int buf = iter & 1;

        if (iter + 1 < nIter) {
            const uint32_t sb = (uint32_t)(((iter + 1) & 1) * TILEH * 2);
            const int k0 = (iter + 1) * BK;
            cpa16(sAhB + sb + soff,      gAh + k0);
            cpa16(sAhB + sb + soff + 16, gAh + k0 + 8);
            cpa16(sAlB + sb + soff,      gAl + k0);
            cpa16(sAlB + sb + soff + 16, gAl + k0 + 8);
            cpa16(sBhB + sb + soff,      gWh + k0);
            cpa16(sBhB + sb + soff + 16, gWh + k0 + 8);
            cpa16(sBlB + sb + soff,      gWl + k0);
            cpa16(sBlB + sb + soff + 16, gWl + k0 + 8);
            cpa_commit();
            cpa_wait<1>();
        } else {
            cpa_wait<0>();
        }
        __syncthreads();

#pragma unroll
        for (int ks = 0; ks < BK; ks += 16) {
            uint32_t ah[4][4], al[4][4];
#pragma unroll
            for (int mf = 0; mf < 4; mf++) {
                int roff = (warpM * 64 + mf * 16 + lm_row) * SSTR + ks + lm_col;
                ldsm4(ah[mf][0], ah[mf][1], ah[mf][2], ah[mf][3],
                      sAhB + (uint32_t)((buf * TILEH + roff) * 2));
                ldsm4(al[mf][0], al[mf][1], al[mf][2], al[mf][3],
                      sAlB + (uint32_t)((buf * TILEH + roff) * 2));
            }
            uint32_t bh[4][2], bl[4][2];
#pragma unroll
            for (int p = 0; p < 2; p++) {
                int roff = (warpN * 32 + p * 16 + lm_row) * SSTR + ks + lm_col;
                uint32_t r0, r1, r2, r3;
                ldsm4(r0, r1, r2, r3, sBhB + (uint32_t)((buf * TILEH + roff) * 2));
                bh[2 * p][0] = r0; bh[2 * p + 1][0] = r1;
                bh[2 * p][1] = r2; bh[2 * p + 1][1] = r3;
                ldsm4(r0, r1, r2, r3, sBlB + (uint32_t)((buf * TILEH + roff) * 2));
                bl[2 * p][0] = r0; bl[2 * p + 1][0] = r1;
                bl[2 * p][1] = r2; bl[2 * p + 1][1] = r3;
            }
#pragma unroll
            for (int mf = 0; mf < 4; mf++)
#pragma unroll
                for (int nf = 0; nf < 4; nf++) {
                    mma16816(acc[mf][nf], ah[mf], bh[nf]);
                    mma16816(acc[mf][nf], ah[mf], bl[nf]);
                    mma16816(acc[mf][nf], al[mf], bh[nf]);
                }
        }
        __syncthreads();
    }

    // epilogue: C = acc + bias
#pragma unroll
    for (int mf = 0; mf < 4; mf++)
#pragma unroll
        for (int nf = 0; nf < 4; nf++) {
            int m0 = rowBase + warpM * 64 + mf * 16 + (lane >> 2);
            int n0 = colBase + warpN * 32 + nf * 8 + (lane & 3) * 2;
            float b0 = bias[n0], b1 = bias[n0 + 1];
            float2 o0 = make_float2(acc[mf][nf][0] + b0, acc[mf][nf][1] + b1);
            float2 o1 = make_float2(acc[mf][nf][2] + b0, acc[mf][nf][3] + b1);
            *(float2*)&C[(size_t)m0 * N + n0]       = o0;
            *(float2*)&C[(size_t)(m0 + 8) * N + n0] = o1;
        }
}

// ---------------------------------------------------------------------------
// RoPE (in-place on Q and K)
// ---------------------------------------------------------------------------
__global__ void rope_kernel(float* __restrict__ Q, float* __restrict__ K)
{
    int idx = blockIdx.x * blockDim.x + threadIdx.x;
    int i = idx & 31;
    int h = (idx >> 5) & (HH - 1);
    int t = (idx >> 9) & (TT - 1);
    int b = idx >> 20;

    size_t base = ((size_t)(b * TT + t)) * DD + h * HDIM;

    float theta = expf(-(float)i * (logf(10000.f) / 32.f));
    float ang = (float)(t + 1) * theta;
    float s, c;
    sincosf(ang, &s, &c);

    float q1 = Q[base + i], q2 = Q[base + i + 32];
    Q[base + i]      = q1 * c - q2 * s;
    Q[base + i + 32] = q2 * c + q1 * s;

    float k1 = K[base + i], k2 = K[base + i + 32];
    K[base + i]      = k1 * c - k2 * s;
    K[base + i + 32] = k2 * c + k1 * s;
}

// ---------------------------------------------------------------------------
// Flash attention with split-bf16 tensor-core mma (validated round 4).
// Epilogue now writes split bf16 (yh, yl) directly for the O-projection.
// ---------------------------------------------------------------------------
#define VSTR 72

__global__ void __launch_bounds__(256) attn_mma(
    const float* __restrict__ Q, const float* __restrict__ K,
    const float* __restrict__ V, bf16* __restrict__ Yh, bf16* __restrict__ Yl)
{
    __shared__ bf16 Ksh[64][VSTR];
    __shared__ bf16 Ksl[64][VSTR];
    __shared__ bf16 Vsh[64][VSTR];   // transposed: [d][j]
    __shared__ bf16 Vsl[64][VSTR];

    const int tid  = threadIdx.x;
    const int lane = tid & 31;
    const int wid  = tid >> 5;
    const int g    = lane >> 2;
    const int t    = lane & 3;
    const int lm_row = lane & 15;
    const int lm_col = (lane >> 4) << 3;

    const int qb = (gridDim.x - 1) - blockIdx.x;
    const int bh = blockIdx.y;
    const int b  = bh >> 4;
    const int h  = bh & 15;

    const size_t headBase = (size_t)b * TT * DD + h * HDIM;
    const int rowA = qb * 128 + wid * 16 + g;

    uint32_t qh[4][4], ql[4][4];
#pragma unroll
    for (int kf = 0; kf < 4; kf++) {
        int c0 = kf * 16 + 2 * t;
        float2 v00 = *(const float2*)&Q[headBase + (size_t)rowA * DD + c0];
        float2 v10 = *(const float2*)&Q[headBase + (size_t)(rowA + 8) * DD + c0];
        float2 v01 = *(const float2*)&Q[headBase + (size_t)rowA * DD + c0 + 8];
        float2 v11 = *(const float2*)&Q[headBase + (size_t)(rowA + 8) * DD + c0 + 8];
        split2(v00.x * 0.125f, v00.y * 0.125f, qh[kf][0], ql[kf][0]);
        split2(v10.x * 0.125f, v10.y * 0.125f, qh[kf][1], ql[kf][1]);
        split2(v01.x * 0.125f, v01.y * 0.125f, qh[kf][2], ql[kf][2]);
        split2(v11.x * 0.125f, v11.y * 0.125f, qh[kf][3], ql[kf][3]);
    }

    float oa[8][4];
#pragma unroll
    for (int df = 0; df < 8; df++)
#pragma unroll
        for (int r = 0; r < 4; r++) oa[df][r] = 0.f;
    float m0 = -1e30f, m1 = -1e30f, l0 = 0.f, l1 = 0.f;

    const int vd = tid & 63;
    const int vj = (tid >> 6) * 16;

    const int nTiles = 2 * qb + 2;
    for (int jt = 0; jt < nTiles; jt++) {
#pragma unroll
        for (int e = tid; e < 1024; e += 256) {
            int j = e >> 4, d4 = (e & 15) * 4;
            float4 kv = *(const float4*)&K[headBase + (size_t)(jt * 64 + j) * DD + d4];
            bf16 hh, ll;
            split1(kv.x, hh, ll); Ksh[j][d4 + 0] = hh; Ksl[j][d4 + 0] = ll;
            split1(kv.y, hh, ll); Ksh[j][d4 + 1] = hh; Ksl[j][d4 + 1] = ll;
            split1(kv.z, hh, ll); Ksh[j][d4 + 2] = hh; Ksl[j][d4 + 2] = ll;
            split1(kv.w, hh, ll); Ksh[j][d4 + 3] = hh; Ksl[j][d4 + 3] = ll;
        }
#pragma unroll
        for (int jj = 0; jj < 16; jj++) {
            int j = vj + jj;
            float v = V[headBase + (size_t)(jt * 64 + j) * DD + vd];
            bf16 hh, ll;
            split1(v, hh, ll);
            Vsh[vd][j] = hh; Vsl[vd][j] = ll;
        }
        __syncthreads();

        float sa[8][4];
#pragma unroll
        for (int nf = 0; nf < 8; nf++)
#pragma unroll
            for (int r = 0; r < 4; r++) sa[nf][r] = 0.f;

#pragma unroll
        for (int kf = 0; kf < 4; kf++) {
            uint32_t kbh[8][2], kbl[8][2];
#pragma unroll
            for (int p = 0; p < 4; p++) {
                uint32_t r0, r1, r2, r3;
                uint32_t addr = smem_u32(&Ksh[p * 16 + lm_row][kf * 16 + lm_col]);
                ldsm4(r0, r1, r2, r3, addr);
                kbh[2 * p][0] = r0; kbh[2 * p + 1][0] = r1;
                kbh[2 * p][1] = r2; kbh[2 * p + 1][1] = r3;
                addr = smem_u32(&Ksl[p * 16 + lm_row][kf * 16 + lm_col]);
                ldsm4(r0, r1, r2, r3, addr);
                kbl[2 * p][0] = r0; kbl[2 * p + 1][0] = r1;
                kbl[2 * p][1] = r2; kbl[2 * p + 1][1] = r3;
            }
#pragma unroll
            for (int nf = 0; nf < 8; nf++) {
                mma16816(sa[nf], qh[kf], kbh[nf]);
                mma16816(sa[nf], qh[kf], kbl[nf]);
                mma16816(sa[nf], ql[kf], kbh[nf]);
            }
        }

        if (jt >= 2 * qb) {
#pragma unroll
            for (int nf = 0; nf < 8; nf++) {
                int col = jt * 64 + nf * 8 + 2 * t;
                if (col > rowA)         sa[nf][0] = -1e30f;
                if (col + 1 > rowA)     sa[nf][1] = -1e30f;
                if (col > rowA + 8)     sa[nf][2] = -1e30f;
                if (col + 1 > rowA + 8) sa[nf][3] = -1e30f;
            }
        }

        float mx0 = -1e30f, mx1 = -1e30f;
#pragma unroll
        for (int nf = 0; nf < 8; nf++) {
            mx0 = fmaxf(mx0, fmaxf(sa[nf][0], sa[nf][1]));
            mx1 = fmaxf(mx1, fmaxf(sa[nf][2], sa[nf][3]));
        }
        mx0 = fmaxf(mx0, __shfl_xor_sync(0xffffffffu, mx0, 1));
        mx0 = fmaxf(mx0, __shfl_xor_sync(0xffffffffu, mx0, 2));
        mx1 = fmaxf(mx1, __shfl_xor_sync(0xffffffffu, mx1, 1));
        mx1 = fmaxf(mx1, __shfl_xor_sync(0xffffffffu, mx1, 2));
        float mn0 = fmaxf(m0, mx0);
        float mn1 = fmaxf(m1, mx1);
        float al0 = __expf(m0 - mn0);
        float al1 = __expf(m1 - mn1);

        float sum0 = 0.f, sum1 = 0.f;
#pragma unroll
        for (int nf = 0; nf < 8; nf++) {
            sa[nf][0] = __expf(sa[nf][0] - mn0);
            sa[nf][1] = __expf(sa[nf][1] - mn0);
            sa[nf][2] = __expf(sa[nf][2] - mn1);
            sa[nf][3] = __expf(sa[nf][3] - mn1);
            sum0 += sa[nf][0] + sa[nf][1];
            sum1 += sa[nf][2] + sa[nf][3];
        }
        sum0 += __shfl_xor_sync(0xffffffffu, sum0, 1);
        sum0 += __shfl_xor_sync(0xffffffffu, sum0, 2);
        sum1 += __shfl_xor_sync(0xffffffffu, sum1, 1);
        sum1 += __shfl_xor_sync(0xffffffffu, sum1, 2);
        l0 = l0 * al0 + sum0;
        l1 = l1 * al1 + sum1;
        m0 = mn0; m1 = mn1;
#pragma unroll
        for (int df = 0; df < 8; df++) {
            oa[df][0] *= al0; oa[df][1] *= al0;
            oa[df][2] *= al1; oa[df][3] *= al1;
        }

#pragma unroll
        for (int kk = 0; kk < 4; kk++) {
            uint32_t pha[4], pla[4];
            split2(sa[2 * kk][0],     sa[2 * kk][1],     pha[0], pla[0]);
            split2(sa[2 * kk][2],     sa[2 * kk][3],     pha[1], pla[1]);
            split2(sa[2 * kk + 1][0], sa[2 * kk + 1][1], pha[2], pla[2]);
            split2(sa[2 * kk + 1][2], sa[2 * kk + 1][3], pha[3], pla[3]);

            uint32_t vbh[8][2], vbl[8][2];
#pragma unroll
            for (int p = 0; p < 4; p++) {
                uint32_t r0, r1, r2, r3;
                uint32_t addr = smem_u32(&Vsh[p * 16 + lm_row][kk * 16 + lm_col]);
                ldsm4(r0, r1, r2, r3, addr);
                vbh[2 * p][0] = r0; vbh[2 * p + 1][0] = r1;
                vbh[2 * p][1] = r2; vbh[2 * p + 1][1] = r3;
                addr = smem_u32(&Vsl[p * 16 + lm_row][kk * 16 + lm_col]);
                ldsm4(r0, r1, r2, r3, addr);
                vbl[2 * p][0] = r0; vbl[2 * p + 1][0] = r1;
                vbl[2 * p][1] = r2; vbl[2 * p + 1][1] = r3;
            }
#pragma unroll
            for (int df = 0; df < 8; df++) {
                mma16816(oa[df], pha, vbh[df]);
                mma16816(oa[df], pha, vbl[df]);
                mma16816(oa[df], pla, vbh[df]);
            }
        }
        __syncthreads();
    }

    // epilogue: split y to bf16 hi/lo pairs directly
    float inv0 = 1.0f / l0;
    float inv1 = 1.0f / l1;
#pragma unroll
    for (int df = 0; df < 8; df++) {
        int dcol = df * 8 + 2 * t;
        size_t off0 = headBase + (size_t)rowA * DD + dcol;
        size_t off1 = headBase + (size_t)(rowA + 8) * DD + dcol;
        uint32_t hi, lo;
        split2(oa[df][0] * inv0, oa[df][1] * inv0, hi, lo);
        *(uint32_t*)&Yh[off0] = hi;
        *(uint32_t*)&Yl[off0] = lo;
        split2(oa[df][2] * inv1, oa[df][3] * inv1, hi, lo);
        *(uint32_t*)&Yh[off1] = hi;
        *(uint32_t*)&Yl[off1] = lo;
    }
}

// ---------------------------------------------------------------------------
// Launch: x, Wq, bq, Wk, bk, Wv, bv, Wo, bo (all fp32)
// ---------------------------------------------------------------------------
extern "C" void kernel_launch(void* const* d_in, const int* in_sizes, int n_in,
                              void* d_out, int out_size)
{
    const float* x  = (const float*)d_in[0];
    const float* Wq = (const float*)d_in[1];
    const float* bq = (const float*)d_in[2];
    const float* Wk = (const float*)d_in[3];
    const float* bk = (const float*)d_in[4];
    const float* Wv = (const float*)d_in[5];
    const float* bv = (const float*)d_in[6];
    const float* Wo = (const float*)d_in[7];
    const float* bo = (const float*)d_in[8];
    float* out = (float*)d_out;

    float *q, *k, *v;
    bf16 *xh, *xl, *yh, *yl, *wh, *wl;
    cudaGetSymbolAddress((void**)&q,  g_q);
    cudaGetSymbolAddress((void**)&k,  g_k);
    cudaGetSymbolAddress((void**)&v,  g_v);
    cudaGetSymbolAddress((void**)&xh, g_xh);
    cudaGetSymbolAddress((void**)&xl, g_xl);
    cudaGetSymbolAddress((void**)&yh, g_yh);
    cudaGetSymbolAddress((void**)&yl, g_yl);
    cudaGetSymbolAddress((void**)&wh, g_wh);
    cudaGetSymbolAddress((void**)&wl, g_wl);

    const int nX = MROWS * DD;
    const int nW = DD * DD;

    split_kernel<<<(nX + 255) / 256, 256>>>(x, xh, xl, nX);
    split_kernel<<<(nW + 255) / 256, 256>>>(Wq, wh + 0 * nW, wl + 0 * nW, nW);
    split_kernel<<<(nW + 255) / 256, 256>>>(Wk, wh + 1 * nW, wl + 1 * nW, nW);
    split_kernel<<<(nW + 255) / 256, 256>>>(Wv, wh + 2 * nW, wl + 2 * nW, nW);
    split_kernel<<<(nW + 255) / 256, 256>>>(Wo, wh + 3 * nW, wl + 3 * nW, nW);

    dim3 gproj(DD / 128, MROWS / 128);
    const int gemm_smem = 8 * TILEH * (int)sizeof(bf16);   // 81920 B
    cudaFuncSetAttribute(gemm_bf16x3, cudaFuncAttributeMaxDynamicSharedMemorySize, gemm_smem);

    gemm_bf16x3<<<gproj, 256, gemm_smem>>>(xh, xl, wh + 0 * nW, wl + 0 * nW, bq, q, DD);
    gemm_bf16x3<<<gproj, 256, gemm_smem>>>(xh, xl, wh + 1 * nW, wl + 1 * nW, bk, k, DD);
    gemm_bf16x3<<<gproj, 256, gemm_smem>>>(xh, xl, wh + 2 * nW, wl + 2 * nW, bv, v, DD);

    rope_kernel<<<(BB * TT * HH * 32) / 256, 256>>>(q, k);

    attn_mma<<<dim3(TT / 128, BB * HH), 256>>>(q, k, v, yh, yl);

    gemm_bf16x3<<<gproj, 256, gemm_smem>>>(yh, yl, wh + 3 * nW, wl + 3 * nW, bo, out, DD);
}

// round 7
// speedup vs baseline: 2.4373x; 1.1721x over previous
#include <cuda_runtime.h>
#include <cuda_bf16.h>
#include <math.h>
#include <cstdint>

#define BB 4
#define TT 2048
#define DD 1024
#define HH 16
#define HDIM 64
#define MROWS (BB*TT)   // 8192
#define GK 1024

typedef __nv_bfloat16 bf16;

// ---------------------------------------------------------------------------
// Scratch (device globals — no allocation allowed). bf16 planes alias floats.
// ---------------------------------------------------------------------------
__device__ float g_q[MROWS * DD];   // holds qh | ql (bf16 planes)
__device__ float g_k[MROWS * DD];   // holds kh | kl
__device__ float g_v[MROWS * DD];   // holds vth | vtl (transposed [b][dg][t])
__device__ bf16  g_xh[MROWS * DD];
__device__ bf16  g_xl[MROWS * DD];
__device__ bf16  g_yh[MROWS * DD];
__device__ bf16  g_yl[MROWS * DD];
__device__ bf16  g_wh[4 * DD * DD];   // Wq,Wk,Wv,Wo hi parts
__device__ bf16  g_wl[4 * DD * DD];   // lo parts

__device__ __forceinline__ uint32_t smem_u32(const void* p) {
    return (uint32_t)__cvta_generic_to_shared(p);
}

__device__ __forceinline__ void split1(float v, bf16& h, bf16& l) {
    h = __float2bfloat16_rn(v);
    l = __float2bfloat16_rn(v - __bfloat162float(h));
}

__device__ __forceinline__ void split2(float x, float y, uint32_t& hi, uint32_t& lo) {
    bf16 hx, lx, hy, ly;
    split1(x, hx, lx);
    split1(y, hy, ly);
    __nv_bfloat162 H = __halves2bfloat162(hx, hy);
    __nv_bfloat162 L = __halves2bfloat162(lx, ly);
    hi = *reinterpret_cast<uint32_t*>(&H);
    lo = *reinterpret_cast<uint32_t*>(&L);
}

__device__ __forceinline__ void mma16816(float* c, const uint32_t* a, const uint32_t* b) {
    asm volatile(
        "mma.sync.aligned.m16n8k16.row.col.f32.bf16.bf16.f32 "
        "{%0,%1,%2,%3}, {%4,%5,%6,%7}, {%8,%9}, {%0,%1,%2,%3};\n"
        : "+f"(c[0]), "+f"(c[1]), "+f"(c[2]), "+f"(c[3])
        : "r"(a[0]), "r"(a[1]), "r"(a[2]), "r"(a[3]), "r"(b[0]), "r"(b[1]));
}

__device__ __forceinline__ void ldsm4(uint32_t& r0, uint32_t& r1, uint32_t& r2, uint32_t& r3,
                                      uint32_t addr) {
    asm volatile("ldmatrix.sync.aligned.m8n8.x4.shared.b16 {%0,%1,%2,%3}, [%4];\n"
                 : "=r"(r0), "=r"(r1), "=r"(r2), "=r"(r3) : "r"(addr));
}

__device__ __forceinline__ void cpa16(uint32_t saddr, const void* g) {
    asm volatile("cp.async.ca.shared.global [%0], [%1], 16;\n" :: "r"(saddr), "l"(g));
}
__device__ __forceinline__ void cpa_commit() {
    asm volatile("cp.async.commit_group;\n");
}
template <int N>
__device__ __forceinline__ void cpa_wait() {
    asm volatile("cp.async.wait_group %0;\n" :: "n"(N));
}

// ---------------------------------------------------------------------------
// Split fp32 -> bf16 hi + bf16 lo
// ---------------------------------------------------------------------------
__global__ void split_kernel(const float* __restrict__ src,
                             bf16* __restrict__ hi, bf16* __restrict__ lo, int n)
{
    int i = blockIdx.x * blockDim.x + threadIdx.x;
    if (i < n) {
        float v = src[i];
        bf16 h = __float2bfloat16_rn(v);
        hi[i] = h;
        lo[i] = __float2bfloat16_rn(v - __bfloat162float(h));
    }
}

// ---------------------------------------------------------------------------
// Shared GEMM mainloop (round-5 validated): split-bf16 x3, BK=32, 2-stage
// cp.async pipeline. Accumulates 128x128 CTA tile in registers.
// ---------------------------------------------------------------------------
#define BK 32
#define SSTR 40
#define TILEH (128 * SSTR)

#define GEMM_MAINLOOP(AhP, AlP, WhP, WlP)                                      \
    bf16* sAh = smg;                                                           \
    bf16* sAl = smg + 2 * TILEH;                                               \
    bf16* sBh = smg + 4 * TILEH;                                               \
    bf16* sBl = smg + 6 * TILEH;                                               \
    const int lr = tid >> 1;                                                   \
    const int lc = (tid & 1) * 16;                                             \
    const bf16* gAh = (AhP) + (size_t)(rowBase + lr) * GK + lc;                \
    const bf16* gAl = (AlP) + (size_t)(rowBase + lr) * GK + lc;                \
    const bf16* gWh = (WhP) + (size_t)(colBase + lr) * GK + lc;                \
    const bf16* gWl = (WlP) + (size_t)(colBase + lr) * GK + lc;                \
    const uint32_t soff = (uint32_t)((lr * SSTR + lc) * 2);                    \
    const uint32_t sAhB = smem_u32(sAh);                                       \
    const uint32_t sAlB = smem_u32(sAl);                                       \
    const uint32_t sBhB = smem_u32(sBh);                                       \
    const uint32_t sBlB = smem_u32(sBl);                                       \
    const int lm_row = (lane & 15);                                            \
    const int lm_col = ((lane >> 4) << 3);                                     \
    float acc[4][4][4];                                                        \
    _Pragma("unroll")                                                          \
    for (int mf = 0; mf < 4; mf++)                                             \
        _Pragma("unroll")                                                      \
        for (int nf = 0; nf < 4; nf++)                                         \
            _Pragma("unroll")                                                  \
            for (int r = 0; r < 4; r++) acc[mf][nf][r] = 0.f;                  \
    const int nIter = GK / BK;                                                 \
    {                                                                          \
        cpa16(sAhB + soff,      gAh);  cpa16(sAhB + soff + 16, gAh + 8);       \
        cpa16(sAlB + soff,      gAl);  cpa16(sAlB + soff + 16, gAl + 8);       \
        cpa16(sBhB + soff,      gWh);  cpa16(sBhB + soff + 16, gWh + 8);       \
        cpa16(sBlB + soff,      gWl);  cpa16(sBlB + soff + 16, gWl + 8);       \
        cpa_commit();                                                          \
    }                                                                          \
    for (int iter = 0; iter < nIter; iter++) {                                 \
        const int buf = iter & 1;                                              \
        if (iter + 1 < nIter) {                                                \
            const uint32_t sb = (uint32_t)(((iter + 1) & 1) * TILEH * 2);      \
            const int k0 = (iter + 1) * BK;                                    \
            cpa16(sAhB + sb + soff,      gAh + k0);                            \
            cpa16(sAhB + sb + soff + 16, gAh + k0 + 8);                        \
            cpa16(sAlB + sb + soff,      gAl + k0);                            \
            cpa16(sAlB + sb + soff + 16, gAl + k0 + 8);                        \
            cpa16(sBhB + sb + soff,      gWh + k0);                            \
            cpa16(sBhB + sb + soff + 16, gWh + k0 + 8);                        \
            cpa16(sBlB + sb + soff,      gWl + k0);                            \
            cpa16(sBlB + sb + soff + 16, gWl + k0 + 8);                        \
            cpa_commit();                                                      \
            cpa_wait<1>();                                                     \
        } else {                                                               \
            cpa_wait<0>();                                                     \
        }                                                                      \
        __syncthreads();                                                       \
        _Pragma("unroll")                                                      \
        for (int ks = 0; ks < BK; ks += 16) {                                  \
            uint32_t ah[4][4], al[4][4];                                       \
            _Pragma("unroll")                                                  \
            for (int mf = 0; mf < 4; mf++) {                                   \
                int roff = (warpM * 64 + mf * 16 + lm_row) * SSTR + ks + lm_col; \
                ldsm4(ah[mf][0], ah[mf][1], ah[mf][2], ah[mf][3],              \
                      sAhB + (uint32_t)((buf * TILEH + roff) * 2));            \
                ldsm4(al[mf][0], al[mf][1], al[mf][2], al[mf][3],              \
                      sAlB + (uint32_t)((buf * TILEH + roff) * 2));            \
            }                                                                  \
            uint32_t bh[4][2], bl[4][2];                                       \
            _Pragma("unroll")                                                  \
            for (int p = 0; p < 2; p++) {                                      \
                int roff = (warpN * 32 + p * 16 + lm_row) * SSTR + ks + lm_col; \
                uint32_t r0, r1, r2, r3;                                       \
                ldsm4(r0, r1, r2, r3, sBhB + (uint32_t)((buf * TILEH + roff) * 2)); \
                bh[2 * p][0] = r0; bh[2 * p + 1][0] = r1;                      \
                bh[2 * p][1] = r2; bh[2 * p + 1][1] = r3;                      \
                ldsm4(r0, r1, r2, r3, sBlB + (uint32_t)((buf * TILEH + roff) * 2)); \
                bl[2 * p][0] = r0; bl[2 * p + 1][0] = r1;                      \
                bl[2 * p][1] = r2; bl[2 * p + 1][1] = r3;                      \
            }                                                                  \
            _Pragma("unroll")                                                  \
            for (int mf = 0; mf < 4; mf++)                                     \
                _Pragma("unroll")                                              \
                for (int nf = 0; nf < 4; nf++) {                               \
                    mma16816(acc[mf][nf], ah[mf], bh[nf]);                     \
                    mma16816(acc[mf][nf], ah[mf], bl[nf]);                     \
                    mma16816(acc[mf][nf], al[mf], bh[nf]);                     \
                }                                                              \
        }                                                                      \
        __syncthreads();                                                       \
    }

// ---------------------------------------------------------------------------
// Fused QKV GEMM + bias + RoPE + split-bf16 output (+ V transposed).
// Grid (24, 64): bx 0-7 -> q, 8-15 -> k, 16-23 -> v. 
// ---------------------------------------------------------------------------
__global__ void __launch_bounds__(256) gemm_qkv(
    const bf16* __restrict__ Ah, const bf16* __restrict__ Al,
    const bf16* __restrict__ Wh, const bf16* __restrict__ Wl,
    const float* __restrict__ bq, const float* __restrict__ bk,
    const float* __restrict__ bv,
    bf16* __restrict__ qh_, bf16* __restrict__ ql_,
    bf16* __restrict__ kh_, bf16* __restrict__ kl_,
    bf16* __restrict__ vth_, bf16* __restrict__ vtl_)
{
    extern __shared__ bf16 smg[];
    const int tid  = threadIdx.x;
    const int lane = tid & 31;
    const int wid  = tid >> 5;
    const int warpM = wid >> 2;
    const int warpN = wid & 3;
    const int bx = blockIdx.x;
    const int rowBase = blockIdx.y * 128;
    const int colBase = bx * 128;

    GEMM_MAINLOOP(Ah, Al, Wh, Wl)

    // ---- epilogue: stage to smem fp32 with bias ----
    float* Csm = (float*)smg;   // [128][132]
    const float* biasp = (bx < 8) ? (bq + bx * 128)
                       : (bx < 16) ? (bk + (bx - 8) * 128)
                                   : (bv + (bx - 16) * 128);
#pragma unroll
    for (int mf = 0; mf < 4; mf++)
#pragma unroll
        for (int nf = 0; nf < 4; nf++) {
            int r0 = warpM * 64 + mf * 16 + (lane >> 2);
            int c0 = warpN * 32 + nf * 8 + (lane & 3) * 2;
            Csm[r0 * 132 + c0]           = acc[mf][nf][0] + biasp[c0];
            Csm[r0 * 132 + c0 + 1]       = acc[mf][nf][1] + biasp[c0 + 1];
            Csm[(r0 + 8) * 132 + c0]     = acc[mf][nf][2] + biasp[c0];
            Csm[(r0 + 8) * 132 + c0 + 1] = acc[mf][nf][3] + biasp[c0 + 1];
        }
    __syncthreads();

    const int bB = rowBase >> 11;       // batch
    const int t0 = rowBase & 2047;      // time offset within batch

    if (bx < 16) {
        // q or k: RoPE + (q only) scale + split store
        bf16* Dh = (bx < 8) ? qh_ : kh_;
        bf16* Dl = (bx < 8) ? ql_ : kl_;
        const int colB = (bx & 7) * 128;
        const float scale = (bx < 8) ? 0.125f : 1.0f;
        const float lnc = logf(10000.f) / 32.f;
        for (int idx = tid; idx < 128 * 64; idx += 256) {
            int r  = idx >> 6;
            int pp = idx & 63;
            int hl = pp >> 5, dd = pp & 31;
            int c1 = hl * 64 + dd, c2 = c1 + 32;
            float x1 = Csm[r * 132 + c1];
            float x2 = Csm[r * 132 + c2];
            float theta = expf(-(float)dd * lnc);
            float ang = (float)(t0 + r + 1) * theta;
            float s, c;
            sincosf(ang, &s, &c);
            float y1 = (x1 * c - x2 * s) * scale;
            float y2 = (x2 * c + x1 * s) * scale;
            size_t gr = (size_t)(rowBase + r) * DD + colB;
            bf16 hh, ll;
            split1(y1, hh, ll); Dh[gr + c1] = hh; Dl[gr + c1] = ll;
            split1(y2, hh, ll); Dh[gr + c2] = hh; Dl[gr + c2] = ll;
        }
    } else {
        // v: split + transposed store vt[b][dg][t]
        const int cb = bx - 16;
#pragma unroll
        for (int pass = 0; pass < 4; pass++) {
            int c  = pass * 32 + (wid << 2) + (lane >> 3);
            int rb = (lane & 7) * 16;
            __align__(16) bf16 bh2[16];
            __align__(16) bf16 bl2[16];
#pragma unroll
            for (int i = 0; i < 16; i++)
                split1(Csm[(rb + i) * 132 + c], bh2[i], bl2[i]);
            size_t vb = ((size_t)bB * DD + cb * 128 + c) * TT + t0 + rb;
            *(uint4*)(vth_ + vb)     = *(uint4*)&bh2[0];
            *(uint4*)(vth_ + vb + 8) = *(uint4*)&bh2[8];
            *(uint4*)(vtl_ + vb)     = *(uint4*)&bl2[0];
            *(uint4*)(vtl_ + vb + 8) = *(uint4*)&bl2[8];
        }
    }
}

// ---------------------------------------------------------------------------
// Output-projection GEMM (round-5 validated): C = Y W^T + bias, fp32 out.
// ---------------------------------------------------------------------------
__global__ void __launch_bounds__(256) gemm_out(
    const bf16* __restrict__ Ah, const bf16* __restrict__ Al,
    const bf16* __restrict__ Wh, const bf16* __restrict__ Wl,
    const float* __restrict__ bias, float* __restrict__ C)
{
    extern __shared__ bf16 smg[];
    const int tid  = threadIdx.x;
    const int lane = tid & 31;
    const int wid  = tid >> 5;
    const int warpM = wid >> 2;
    const int warpN = wid & 3;
    const int rowBase = blockIdx.y * 128;
    const int colBase = blockIdx.x * 128;

    GEMM_MAINLOOP(Ah, Al, Wh, Wl)

#pragma unroll
    for (int mf = 0; mf < 4; mf++)
#pragma unroll
        for (int nf = 0; nf < 4; nf++) {
            int m0 = rowBase + warpM * 64 + mf * 16 + (lane >> 2);
            int n0 = colBase + warpN * 32 + nf * 8 + (lane & 3) * 2;
            float b0 = bias[n0], b1 = bias[n0 + 1];
            float2 o0 = make_float2(acc[mf][nf][0] + b0, acc[mf][nf][1] + b1);
            float2 o1 = make_float2(acc[mf][nf][2] + b0, acc[mf][nf][3] + b1);
            *(float2*)&C[(size_t)m0 * DD + n0]       = o0;
            *(float2*)&C[(size_t)(m0 + 8) * DD + n0] = o1;
        }
}

// ---------------------------------------------------------------------------
// Flash attention, split-bf16 mma, pre-split inputs (qh/ql, kh/kl, vth/vtl).
// K/V tiles loaded with coalesced cp.async; V already transposed [d][t].
// ---------------------------------------------------------------------------
#define VSTR 72

__global__ void __launch_bounds__(256) attn_mma(
    const bf16* __restrict__ Qh, const bf16* __restrict__ Ql,
    const bf16* __restrict__ Kh, const bf16* __restrict__ Kl,
    const bf16* __restrict__ Vth, const bf16* __restrict__ Vtl,
    bf16* __restrict__ Yh, bf16* __restrict__ Yl)
{
    __shared__ __align__(16) bf16 Ksh[64][VSTR];
    __shared__ __align__(16) bf16 Ksl[64][VSTR];
    __shared__ __align__(16) bf16 Vsh[64][VSTR];   // [d][j]
    __shared__ __align__(16) bf16 Vsl[64][VSTR];

    const int tid  = threadIdx.x;
    const int lane = tid & 31;
    const int wid  = tid >> 5;
    const int g    = lane >> 2;
    const int t    = lane & 3;
    const int lm_row = lane & 15;
    const int lm_col = (lane >> 4) << 3;

    const int qb = (gridDim.x - 1) - blockIdx.x;
    const int bh = blockIdx.y;
    const int b  = bh >> 4;
    const int h  = bh & 15;

    const size_t headBase = (size_t)b * TT * DD + h * HDIM;
    const size_t kRow = (size_t)b * TT;                    // K gmem row base
    const size_t vRow = (size_t)b * DD + h * HDIM;         // Vt gmem row base
    const int rowA = qb * 128 + wid * 16 + g;

    // ---- Q fragments: direct bf16-pair loads (pre-scaled, pre-roped) ----
    uint32_t qh[4][4], ql[4][4];
#pragma unroll
    for (int kf = 0; kf < 4; kf++) {
        int c0 = kf * 16 + 2 * t;
        size_t o00 = headBase + (size_t)rowA * DD + c0;
        size_t o10 = headBase + (size_t)(rowA + 8) * DD + c0;
        qh[kf][0] = *(const uint32_t*)(Qh + o00);
        qh[kf][1] = *(const uint32_t*)(Qh + o10);
        qh[kf][2] = *(const uint32_t*)(Qh + o00 + 8);
        qh[kf][3] = *(const uint32_t*)(Qh + o10 + 8);
        ql[kf][0] = *(const uint32_t*)(Ql + o00);
        ql[kf][1] = *(const uint32_t*)(Ql + o10);
        ql[kf][2] = *(const uint32_t*)(Ql + o00 + 8);
        ql[kf][3] = *(const uint32_t*)(Ql + o10 + 8);
    }

    float oa[8][4];
#pragma unroll
    for (int df = 0; df < 8; df++)
#pragma unroll
        for (int r = 0; r < 4; r++) oa[df][r] = 0.f;
    float m0 = -1e30f, m1 = -1e30f, l0 = 0.f, l1 = 0.f;

    const uint32_t kshA = smem_u32(&Ksh[0][0]);
    const uint32_t kslA = smem_u32(&Ksl[0][0]);
    const uint32_t vshA = smem_u32(&Vsh[0][0]);
    const uint32_t vslA = smem_u32(&Vsl[0][0]);

    const int nTiles = 2 * qb + 2;
    for (int jt = 0; jt < nTiles; jt++) {
        // ---- coalesced cp.async tile loads (bf16, no conversion) ----
#pragma unroll
        for (int i = 0; i < 2; i++) {
            int idx = tid + i * 256;          // 0..511
            int row = idx >> 3, ch = idx & 7;
            uint32_t sm_off = (uint32_t)(row * (VSTR * 2) + ch * 16);
            size_t gk = (kRow + jt * 64 + row) * DD + h * HDIM + ch * 8;
            cpa16(kshA + sm_off, Kh + gk);
            cpa16(kslA + sm_off, Kl + gk);
            size_t gv = (vRow + row) * TT + jt * 64 + ch * 8;
            cpa16(vshA + sm_off, Vth + gv);
            cpa16(vslA + sm_off, Vtl + gv);
        }
        cpa_commit();
        cpa_wait<0>();
        __syncthreads();

        // ---- S = Q K^T (split x3) ----
        float sa[8][4];
#pragma unroll
        for (int nf = 0; nf < 8; nf++)
#pragma unroll
            for (int r = 0; r < 4; r++) sa[nf][r] = 0.f;

#pragma unroll
        for (int kf = 0; kf < 4; kf++) {
            uint32_t kbh[8][2], kbl[8][2];
#pragma unroll
            for (int p = 0; p < 4; p++) {
                uint32_t r0, r1, r2, r3;
                uint32_t addr = smem_u32(&Ksh[p * 16 + lm_row][kf * 16 + lm_col]);
                ldsm4(r0, r1, r2, r3, addr);
                kbh[2 * p][0] = r0; kbh[2 * p + 1][0] = r1;
                kbh[2 * p][1] = r2; kbh[2 * p + 1][1] = r3;
                addr = smem_u32(&Ksl[p * 16 + lm_row][kf * 16 + lm_col]);
                ldsm4(r0, r1, r2, r3, addr);
                kbl[2 * p][0] = r0; kbl[2 * p + 1][0] = r1;
                kbl[2 * p][1] = r2; kbl[2 * p + 1][1] = r3;
            }
#pragma unroll
            for (int nf = 0; nf < 8; nf++) {
                mma16816(sa[nf], qh[kf], kbh[nf]);
                mma16816(sa[nf], qh[kf], kbl[nf]);
                mma16816(sa[nf], ql[kf], kbh[nf]);
            }
        }

        if (jt >= 2 * qb) {
#pragma unroll
            for (int nf = 0; nf < 8; nf++) {
                int col = jt * 64 + nf * 8 + 2 * t;
                if (col > rowA)         sa[nf][0] = -1e30f;
                if (col + 1 > rowA)     sa[nf][1] = -1e30f;
                if (col > rowA + 8)     sa[nf][2] = -1e30f;
                if (col + 1 > rowA + 8) sa[nf][3] = -1e30f;
            }
        }

        float mx0 = -1e30f, mx1 = -1e30f;
#pragma unroll
        for (int nf = 0; nf < 8; nf++) {
            mx0 = fmaxf(mx0, fmaxf(sa[nf][0], sa[nf][1]));
            mx1 = fmaxf(mx1, fmaxf(sa[nf][2], sa[nf][3]));
        }
        mx0 = fmaxf(mx0, __shfl_xor_sync(0xffffffffu, mx0, 1));
        mx0 = fmaxf(mx0, __shfl_xor_sync(0xffffffffu, mx0, 2));
        mx1 = fmaxf(mx1, __shfl_xor_sync(0xffffffffu, mx1, 1));
        mx1 = fmaxf(mx1, __shfl_xor_sync(0xffffffffu, mx1, 2));
        float mn0 = fmaxf(m0, mx0);
        float mn1 = fmaxf(m1, mx1);
        float al0 = __expf(m0 - mn0);
        float al1 = __expf(m1 - mn1);

        float sum0 = 0.f, sum1 = 0.f;
#pragma unroll
        for (int nf = 0; nf < 8; nf++) {
            sa[nf][0] = __expf(sa[nf][0] - mn0);
            sa[nf][1] = __expf(sa[nf][1] - mn0);
            sa[nf][2] = __expf(sa[nf][2] - mn1);
            sa[nf][3] = __expf(sa[nf][3] - mn1);
            sum0 += sa[nf][0] + sa[nf][1];
            sum1 += sa[nf][2] + sa[nf][3];
        }
        sum0 += __shfl_xor_sync(0xffffffffu, sum0, 1);
        sum0 += __shfl_xor_sync(0xffffffffu, sum0, 2);
        sum1 += __shfl_xor_sync(0xffffffffu, sum1, 1);
        sum1 += __shfl_xor_sync(0xffffffffu, sum1, 2);
        l0 = l0 * al0 + sum0;
        l1 = l1 * al1 + sum1;
        m0 = mn0; m1 = mn1;
#pragma unroll
        for (int df = 0; df < 8; df++) {
            oa[df][0] *= al0; oa[df][1] *= al0;
            oa[df][2] *= al1; oa[df][3] *= al1;
        }

        // ---- O += P V (split x3) ----
#pragma unroll
        for (int kk = 0; kk < 4; kk++) {
            uint32_t pha[4], pla[4];
            split2(sa[2 * kk][0],     sa[2 * kk][1],     pha[0], pla[0]);
            split2(sa[2 * kk][2],     sa[2 * kk][3],     pha[1], pla[1]);
            split2(sa[2 * kk + 1][0], sa[2 * kk + 1][1], pha[2], pla[2]);
            split2(sa[2 * kk + 1][2], sa[2 * kk + 1][3], pha[3], pla[3]);

            uint32_t vbh[8][2], vbl[8][2];
#pragma unroll
            for (int p = 0; p < 4; p++) {
                uint32_t r0, r1, r2, r3;
                uint32_t addr = smem_u32(&Vsh[p * 16 + lm_row][kk * 16 + lm_col]);
                ldsm4(r0, r1, r2, r3, addr);
                vbh[2 * p][0] = r0; vbh[2 * p + 1][0] = r1;
                vbh[2 * p][1] = r2; vbh[2 * p + 1][1] = r3;
                addr = smem_u32(&Vsl[p * 16 + lm_row][kk * 16 + lm_col]);
                ldsm4(r0, r1, r2, r3, addr);
                vbl[2 * p][0] = r0; vbl[2 * p + 1][0] = r1;
                vbl[2 * p][1] = r2; vbl[2 * p + 1][1] = r3;
            }
#pragma unroll
            for (int df = 0; df < 8; df++) {
                mma16816(oa[df], pha, vbh[df]);
                mma16816(oa[df], pha, vbl[df]);
                mma16816(oa[df], pla, vbh[df]);
            }
        }
        __syncthreads();
    }

    float inv0 = 1.0f / l0;
    float inv1 = 1.0f / l1;
#pragma unroll
    for (int df = 0; df < 8; df++) {
        int dcol = df * 8 + 2 * t;
        size_t off0 = headBase + (size_t)rowA * DD + dcol;
        size_t off1 = headBase + (size_t)(rowA + 8) * DD + dcol;
        uint32_t hi, lo;
        split2(oa[df][0] * inv0, oa[df][1] * inv0, hi, lo);
        *(uint32_t*)&Yh[off0] = hi;
        *(uint32_t*)&Yl[off0] = lo;
        split2(oa[df][2] * inv1, oa[df][3] * inv1, hi, lo);
        *(uint32_t*)&Yh[off1] = hi;
        *(uint32_t*)&Yl[off1] = lo;
    }
}

// ---------------------------------------------------------------------------
// Launch: x, Wq, bq, Wk, bk, Wv, bv, Wo, bo (all fp32)
// ---------------------------------------------------------------------------
extern "C" void kernel_launch(void* const* d_in, const int* in_sizes, int n_in,
                              void* d_out, int out_size)
{
    const float* x  = (const float*)d_in[0];
    const float* Wq = (const float*)d_in[1];
    const float* bq = (const float*)d_in[2];
    const float* Wk = (const float*)d_in[3];
    const float* bk = (const float*)d_in[4];
    const float* Wv = (const float*)d_in[5];
    const float* bv = (const float*)d_in[6];
    const float* Wo = (const float*)d_in[7];
    const float* bo = (const float*)d_in[8];
    float* out = (float*)d_out;

    float *qf, *kf, *vf;
    bf16 *xh, *xl, *yh, *yl, *wh, *wl;
    cudaGetSymbolAddress((void**)&qf, g_q);
    cudaGetSymbolAddress((void**)&kf, g_k);
    cudaGetSymbolAddress((void**)&vf, g_v);
    cudaGetSymbolAddress((void**)&xh, g_xh);
    cudaGetSymbolAddress((void**)&xl, g_xl);
    cudaGetSymbolAddress((void**)&yh, g_yh);
    cudaGetSymbolAddress((void**)&yl, g_yl);
    cudaGetSymbolAddress((void**)&wh, g_wh);
    cudaGetSymbolAddress((void**)&wl, g_wl);

    const int nX = MROWS * DD;
    const int nW = DD * DD;

    bf16* qh  = (bf16*)qf;  bf16* ql  = qh + nX;
    bf16* kh  = (bf16*)kf;  bf16* kl  = kh + nX;
    bf16* vth = (bf16*)vf;  bf16* vtl = vth + nX;

    split_kernel<<<(nX + 255) / 256, 256>>>(x, xh, xl, nX);
    split_kernel<<<(nW + 255) / 256, 256>>>(Wq, wh + 0 * nW, wl + 0 * nW, nW);
    split_kernel<<<(nW + 255) / 256, 256>>>(Wk, wh + 1 * nW, wl + 1 * nW, nW);
    split_kernel<<<(nW + 255) / 256, 256>>>(Wv, wh + 2 * nW, wl + 2 * nW, nW);
    split_kernel<<<(nW + 255) / 256, 256>>>(Wo, wh + 3 * nW, wl + 3 * nW, nW);

    const int gemm_smem = 8 * TILEH * (int)sizeof(bf16);   // 81920 B
    cudaFuncSetAttribute(gemm_qkv, cudaFuncAttributeMaxDynamicSharedMemorySize, gemm_smem);
    cudaFuncSetAttribute(gemm_out, cudaFuncAttributeMaxDynamicSharedMemorySize, gemm_smem);

    gemm_qkv<<<dim3(24, MROWS / 128), 256, gemm_smem>>>(
        xh, xl, wh, wl, bq, bk, bv, qh, ql, kh, kl, vth, vtl);

    attn_mma<<<dim3(TT / 128, BB * HH), 256>>>(qh, ql, kh, kl, vth, vtl, yh, yl);

    gemm_out<<<dim3(DD / 128, MROWS / 128), 256, gemm_smem>>>(
        yh, yl, wh + 3 * nW, wl + 3 * nW, bo, out);
}

// round 8
// speedup vs baseline: 2.5064x; 1.0283x over previous
#include <cuda_runtime.h>
#include <cuda_bf16.h>
#include <math.h>
#include <cstdint>

#define BB 4
#define TT 2048
#define DD 1024
#define HH 16
#define HDIM 64
#define MROWS (BB*TT)   // 8192
#define GK 1024

typedef __nv_bfloat16 bf16;

// ---------------------------------------------------------------------------
// Scratch (device globals — no allocation allowed). bf16 planes alias floats.
// ---------------------------------------------------------------------------
__device__ float g_q[MROWS * DD];   // holds qh | ql (bf16 planes)
__device__ float g_k[MROWS * DD];   // holds kh | kl
__device__ float g_v[MROWS * DD];   // holds vth | vtl (transposed [b][dg][t])
__device__ bf16  g_xh[MROWS * DD];
__device__ bf16  g_xl[MROWS * DD];
__device__ bf16  g_yh[MROWS * DD];
__device__ bf16  g_yl[MROWS * DD];
__device__ bf16  g_wh[4 * DD * DD];   // Wq,Wk,Wv,Wo hi parts
__device__ bf16  g_wl[4 * DD * DD];   // lo parts

__device__ __forceinline__ uint32_t smem_u32(const void* p) {
    return (uint32_t)__cvta_generic_to_shared(p);
}

__device__ __forceinline__ void split1(float v, bf16& h, bf16& l) {
    h = __float2bfloat16_rn(v);
    l = __float2bfloat16_rn(v - __bfloat162float(h));
}

__device__ __forceinline__ void split2(float x, float y, uint32_t& hi, uint32_t& lo) {
    bf16 hx, lx, hy, ly;
    split1(x, hx, lx);
    split1(y, hy, ly);
    __nv_bfloat162 H = __halves2bfloat162(hx, hy);
    __nv_bfloat162 L = __halves2bfloat162(lx, ly);
    hi = *reinterpret_cast<uint32_t*>(&H);
    lo = *reinterpret_cast<uint32_t*>(&L);
}

__device__ __forceinline__ void mma16816(float* c, const uint32_t* a, const uint32_t* b) {
    asm volatile(
        "mma.sync.aligned.m16n8k16.row.col.f32.bf16.bf16.f32 "
        "{%0,%1,%2,%3}, {%4,%5,%6,%7}, {%8,%9}, {%0,%1,%2,%3};\n"
        : "+f"(c[0]), "+f"(c[1]), "+f"(c[2]), "+f"(c[3])
        : "r"(a[0]), "r"(a[1]), "r"(a[2]), "r"(a[3]), "r"(b[0]), "r"(b[1]));
}

__device__ __forceinline__ void ldsm4(uint32_t& r0, uint32_t& r1, uint32_t& r2, uint32_t& r3,
                                      uint32_t addr) {
    asm volatile("ldmatrix.sync.aligned.m8n8.x4.shared.b16 {%0,%1,%2,%3}, [%4];\n"
                 : "=r"(r0), "=r"(r1), "=r"(r2), "=r"(r3) : "r"(addr));
}

__device__ __forceinline__ void cpa16(uint32_t saddr, const void* g) {
    asm volatile("cp.async.ca.shared.global [%0], [%1], 16;\n" :: "r"(saddr), "l"(g));
}
__device__ __forceinline__ void cpa_commit() {
    asm volatile("cp.async.commit_group;\n");
}
template <int N>
__device__ __forceinline__ void cpa_wait() {
    asm volatile("cp.async.wait_group %0;\n" :: "n"(N));
}

// ---------------------------------------------------------------------------
// Split fp32 -> bf16 hi + bf16 lo
// ---------------------------------------------------------------------------
__global__ void split_kernel(const float* __restrict__ src,
                             bf16* __restrict__ hi, bf16* __restrict__ lo, int n)
{
    int i = blockIdx.x * blockDim.x + threadIdx.x;
    if (i < n) {
        float v = src[i];
        bf16 h = __float2bfloat16_rn(v);
        hi[i] = h;
        lo[i] = __float2bfloat16_rn(v - __bfloat162float(h));
    }
}

// ---------------------------------------------------------------------------
// Shared GEMM mainloop (round-5 validated): split-bf16 x3, BK=32, 2-stage
// cp.async pipeline. Accumulates 128x128 CTA tile in registers.
// ---------------------------------------------------------------------------
#define BK 32
#define SSTR 40
#define TILEH (128 * SSTR)

#define GEMM_MAINLOOP(AhP, AlP, WhP, WlP)                                      \
    bf16* sAh = smg;                                                           \
    bf16* sAl = smg + 2 * TILEH;                                               \
    bf16* sBh = smg + 4 * TILEH;                                               \
    bf16* sBl = smg + 6 * TILEH;                                               \
    const int lr = tid >> 1;                                                   \
    const int lc = (tid & 1) * 16;                                             \
    const bf16* gAh = (AhP) + (size_t)(rowBase + lr) * GK + lc;                \
    const bf16* gAl = (AlP) + (size_t)(rowBase + lr) * GK + lc;                \
    const bf16* gWh = (WhP) + (size_t)(colBase + lr) * GK + lc;                \
    const bf16* gWl = (WlP) + (size_t)(colBase + lr) * GK + lc;                \
    const uint32_t soff = (uint32_t)((lr * SSTR + lc) * 2);                    \
    const uint32_t sAhB = smem_u32(sAh);                                       \
    const uint32_t sAlB = smem_u32(sAl);                                       \
    const uint32_t sBhB = smem_u32(sBh);                                       \
    const uint32_t sBlB = smem_u32(sBl);                                       \
    const int lm_row = (lane & 15);                                            \
    const int lm_col = ((lane >> 4) << 3);                                     \
    float acc[4][4][4];                                                        \
    _Pragma("unroll")                                                          \
    for (int mf = 0; mf < 4; mf++)                                             \
        _Pragma("unroll")                                                      \
        for (int nf = 0; nf < 4; nf++)                                         \
            _Pragma("unroll")                                                  \
            for (int r = 0; r < 4; r++) acc[mf][nf][r] = 0.f;                  \
    const int nIter = GK / BK;                                                 \
    {                                                                          \
        cpa16(sAhB + soff,      gAh);  cpa16(sAhB + soff + 16, gAh + 8);       \
        cpa16(sAlB + soff,      gAl);  cpa16(sAlB + soff + 16, gAl + 8);       \
        cpa16(sBhB + soff,      gWh);  cpa16(sBhB + soff + 16, gWh + 8);       \
        cpa16(sBlB + soff,      gWl);  cpa16(sBlB + soff + 16, gWl + 8);       \
        cpa_commit();                                                          \
    }                                                                          \
    for (int iter = 0; iter < nIter; iter++) {                                 \
        const int buf = iter & 1;                                              \
        if (iter + 1 < nIter) {                                                \
            const uint32_t sb = (uint32_t)(((iter + 1) & 1) * TILEH * 2);      \
            const int k0 = (iter + 1) * BK;                                    \
            cpa16(sAhB + sb + soff,      gAh + k0);                            \
            cpa16(sAhB + sb + soff + 16, gAh + k0 + 8);                        \
            cpa16(sAlB + sb + soff,      gAl + k0);                            \
            cpa16(sAlB + sb + soff + 16, gAl + k0 + 8);                        \
            cpa16(sBhB + sb + soff,      gWh + k0);                            \
            cpa16(sBhB + sb + soff + 16, gWh + k0 + 8);                        \
            cpa16(sBlB + sb + soff,      gWl + k0);                            \
            cpa16(sBlB + sb + soff + 16, gWl + k0 + 8);                        \
            cpa_commit();                                                      \
            cpa_wait<1>();                                                     \
        } else {                                                               \
            cpa_wait<0>();                                                     \
        }                                                                      \
        __syncthreads();                                                       \
        _Pragma("unroll")                                                      \
        for (int ks = 0; ks < BK; ks += 16) {                                  \
            uint32_t ah[4][4], al[4][4];                                       \
            _Pragma("unroll")                                                  \
            for (int mf = 0; mf < 4; mf++) {                                   \
                int roff = (warpM * 64 + mf * 16 + lm_row) * SSTR + ks + lm_col; \
                ldsm4(ah[mf][0], ah[mf][1], ah[mf][2], ah[mf][3],              \
                      sAhB + (uint32_t)((buf * TILEH + roff) * 2));            \
                ldsm4(al[mf][0], al[mf][1], al[mf][2], al[mf][3],              \
                      sAlB + (uint32_t)((buf * TILEH + roff) * 2));            \
            }                                                                  \
            uint32_t bh[4][2], bl[4][2];                                       \
            _Pragma("unroll")                                                  \
            for (int p = 0; p < 2; p++) {                                      \
                int roff = (warpN * 32 + p * 16 + lm_row) * SSTR + ks + lm_col; \
                uint32_t r0, r1, r2, r3;                                       \
                ldsm4(r0, r1, r2, r3, sBhB + (uint32_t)((buf * TILEH + roff) * 2)); \
                bh[2 * p][0] = r0; bh[2 * p + 1][0] = r1;                      \
                bh[2 * p][1] = r2; bh[2 * p + 1][1] = r3;                      \
                ldsm4(r0, r1, r2, r3, sBlB + (uint32_t)((buf * TILEH + roff) * 2)); \
                bl[2 * p][0] = r0; bl[2 * p + 1][0] = r1;                      \
                bl[2 * p][1] = r2; bl[2 * p + 1][1] = r3;                      \
            }                                                                  \
            _Pragma("unroll")                                                  \
            for (int mf = 0; mf < 4; mf++)                                     \
                _Pragma("unroll")                                              \
                for (int nf = 0; nf < 4; nf++) {                               \
                    mma16816(acc[mf][nf], ah[mf], bh[nf]);                     \
                    mma16816(acc[mf][nf], ah[mf], bl[nf]);                     \
                    mma16816(acc[mf][nf], al[mf], bh[nf]);                     \
                }                                                              \
        }                                                                      \
        __syncthreads();                                                       \
    }

// ---------------------------------------------------------------------------
// Fused QKV GEMM + bias + RoPE + split-bf16 output (+ V transposed).
// Grid (24, 64): bx 0-7 -> q, 8-15 -> k, 16-23 -> v.
// ---------------------------------------------------------------------------
__global__ void __launch_bounds__(256) gemm_qkv(
    const bf16* __restrict__ Ah, const bf16* __restrict__ Al,
    const bf16* __restrict__ Wh, const bf16* __restrict__ Wl,
    const float* __restrict__ bq, const float* __restrict__ bk,
    const float* __restrict__ bv,
    bf16* __restrict__ qh_, bf16* __restrict__ ql_,
    bf16* __restrict__ kh_, bf16* __restrict__ kl_,
    bf16* __restrict__ vth_, bf16* __restrict__ vtl_)
{
    extern __shared__ bf16 smg[];
    const int tid  = threadIdx.x;
    const int lane = tid & 31;
    const int wid  = tid >> 5;
    const int warpM = wid >> 2;
    const int warpN = wid & 3;
    const int bx = blockIdx.x;
    const int rowBase = blockIdx.y * 128;
    const int colBase = bx * 128;

    GEMM_MAINLOOP(Ah, Al, Wh, Wl)

    // ---- epilogue: stage to smem fp32 with bias ----
    float* Csm = (float*)smg;   // [128][132]
    const float* biasp = (bx < 8) ? (bq + bx * 128)
                       : (bx < 16) ? (bk + (bx - 8) * 128)
                                   : (bv + (bx - 16) * 128);
#pragma unroll
    for (int mf = 0; mf < 4; mf++)
#pragma unroll
        for (int nf = 0; nf < 4; nf++) {
            int r0 = warpM * 64 + mf * 16 + (lane >> 2);
            int c0 = warpN * 32 + nf * 8 + (lane & 3) * 2;
            Csm[r0 * 132 + c0]           = acc[mf][nf][0] + biasp[c0];
            Csm[r0 * 132 + c0 + 1]       = acc[mf][nf][1] + biasp[c0 + 1];
            Csm[(r0 + 8) * 132 + c0]     = acc[mf][nf][2] + biasp[c0];
            Csm[(r0 + 8) * 132 + c0 + 1] = acc[mf][nf][3] + biasp[c0 + 1];
        }
    __syncthreads();

    const int bB = rowBase >> 11;       // batch
    const int t0 = rowBase & 2047;      // time offset within batch

    if (bx < 16) {
        bf16* Dh = (bx < 8) ? qh_ : kh_;
        bf16* Dl = (bx < 8) ? ql_ : kl_;
        const int colB = (bx & 7) * 128;
        const float scale = (bx < 8) ? 0.125f : 1.0f;
        const float lnc = logf(10000.f) / 32.f;
        for (int idx = tid; idx < 128 * 64; idx += 256) {
            int r  = idx >> 6;
            int pp = idx & 63;
            int hl = pp >> 5, dd = pp & 31;
            int c1 = hl * 64 + dd, c2 = c1 + 32;
            float x1 = Csm[r * 132 + c1];
            float x2 = Csm[r * 132 + c2];
            float theta = expf(-(float)dd * lnc);
            float ang = (float)(t0 + r + 1) * theta;
            float s, c;
            sincosf(ang, &s, &c);
            float y1 = (x1 * c - x2 * s) * scale;
            float y2 = (x2 * c + x1 * s) * scale;
            size_t gr = (size_t)(rowBase + r) * DD + colB;
            bf16 hh, ll;
            split1(y1, hh, ll); Dh[gr + c1] = hh; Dl[gr + c1] = ll;
            split1(y2, hh, ll); Dh[gr + c2] = hh; Dl[gr + c2] = ll;
        }
    } else {
        const int cb = bx - 16;
#pragma unroll
        for (int pass = 0; pass < 4; pass++) {
            int c  = pass * 32 + (wid << 2) + (lane >> 3);
            int rb = (lane & 7) * 16;
            __align__(16) bf16 bh2[16];
            __align__(16) bf16 bl2[16];
#pragma unroll
            for (int i = 0; i < 16; i++)
                split1(Csm[(rb + i) * 132 + c], bh2[i], bl2[i]);
            size_t vb = ((size_t)bB * DD + cb * 128 + c) * TT + t0 + rb;
            *(uint4*)(vth_ + vb)     = *(uint4*)&bh2[0];
            *(uint4*)(vth_ + vb + 8) = *(uint4*)&bh2[8];
            *(uint4*)(vtl_ + vb)     = *(uint4*)&bl2[0];
            *(uint4*)(vtl_ + vb + 8) = *(uint4*)&bl2[8];
        }
    }
}

// ---------------------------------------------------------------------------
// Output-projection GEMM: C = Y W^T + bias, fp32 out.
// ---------------------------------------------------------------------------
__global__ void __launch_bounds__(256) gemm_out(
    const bf16* __restrict__ Ah, const bf16* __restrict__ Al,
    const bf16* __restrict__ Wh, const bf16* __restrict__ Wl,
    const float* __restrict__ bias, float* __restrict__ C)
{
    extern __shared__ bf16 smg[];
    const int tid  = threadIdx.x;
    const int lane = tid & 31;
    const int wid  = tid >> 5;
    const int warpM = wid >> 2;
    const int warpN = wid & 3;
    const int rowBase = blockIdx.y * 128;
    const int colBase = blockIdx.x * 128;

    GEMM_MAINLOOP(Ah, Al, Wh, Wl)

#pragma unroll
    for (int mf = 0; mf < 4; mf++)
#pragma unroll
        for (int nf = 0; nf < 4; nf++) {
            int m0 = rowBase + warpM * 64 + mf * 16 + (lane >> 2);
            int n0 = colBase + warpN * 32 + nf * 8 + (lane & 3) * 2;
            float b0 = bias[n0], b1 = bias[n0 + 1];
            float2 o0 = make_float2(acc[mf][nf][0] + b0, acc[mf][nf][1] + b1);
            float2 o1 = make_float2(acc[mf][nf][2] + b0, acc[mf][nf][3] + b1);
            *(float2*)&C[(size_t)m0 * DD + n0]       = o0;
            *(float2*)&C[(size_t)(m0 + 8) * DD + n0] = o1;
        }
}

// ---------------------------------------------------------------------------
// Flash attention, split-bf16 mma, pre-split inputs.
// Double-buffered K/V tiles (dynamic smem) + fully-masked-tile warp skip.
// Buffer layout (per buf, 36864 B): Ksh | Ksl | Vsh | Vsl, each 64 rows x 144 B.
// ---------------------------------------------------------------------------
#define AROW 144                      // bytes per smem row (64 bf16 + 8 pad)
#define APLANE (64 * AROW)            // 9216 B per array
#define ABUF (4 * APLANE)             // 36864 B per buffer

__global__ void __launch_bounds__(256) attn_mma(
    const bf16* __restrict__ Qh, const bf16* __restrict__ Ql,
    const bf16* __restrict__ Kh, const bf16* __restrict__ Kl,
    const bf16* __restrict__ Vth, const bf16* __restrict__ Vtl,
    bf16* __restrict__ Yh, bf16* __restrict__ Yl)
{
    extern __shared__ bf16 asmem[];
    const uint32_t smA = smem_u32(asmem);

    const int tid  = threadIdx.x;
    const int lane = tid & 31;
    const int wid  = tid >> 5;
    const int g    = lane >> 2;
    const int t    = lane & 3;
    const int lm_row = lane & 15;
    const int lm_col = (lane >> 4) << 3;

    const int qb = (gridDim.x - 1) - blockIdx.x;
    const int bh = blockIdx.y;
    const int b  = bh >> 4;
    const int h  = bh & 15;

    const size_t headBase = (size_t)b * TT * DD + h * HDIM;
    const size_t kRow = (size_t)b * TT;
    const size_t vRow = (size_t)b * DD + h * HDIM;
    const int rowA = qb * 128 + wid * 16 + g;

    // ---- Q fragments ----
    uint32_t qh[4][4], ql[4][4];
#pragma unroll
    for (int kf = 0; kf < 4; kf++) {
        int c0 = kf * 16 + 2 * t;
        size_t o00 = headBase + (size_t)rowA * DD + c0;
        size_t o10 = headBase + (size_t)(rowA + 8) * DD + c0;
        qh[kf][0] = *(const uint32_t*)(Qh + o00);
        qh[kf][1] = *(const uint32_t*)(Qh + o10);
        qh[kf][2] = *(const uint32_t*)(Qh + o00 + 8);
        qh[kf][3] = *(const uint32_t*)(Qh + o10 + 8);
        ql[kf][0] = *(const uint32_t*)(Ql + o00);
        ql[kf][1] = *(const uint32_t*)(Ql + o10);
        ql[kf][2] = *(const uint32_t*)(Ql + o00 + 8);
        ql[kf][3] = *(const uint32_t*)(Ql + o10 + 8);
    }

    float oa[8][4];
#pragma unroll
    for (int df = 0; df < 8; df++)
#pragma unroll
        for (int r = 0; r < 4; r++) oa[df][r] = 0.f;
    float m0 = -1e30f, m1 = -1e30f, l0 = 0.f, l1 = 0.f;

    const int lrow = tid >> 3;          // 0..31 (x2 passes -> 64 rows)
    const int lch  = tid & 7;

    // tile loader: jt -> buffer bsel
    auto load_tile = [&](int jt, int bsel) {
        const uint32_t bufB = smA + (uint32_t)bsel * ABUF;
#pragma unroll
        for (int i = 0; i < 2; i++) {
            int row = lrow + i * 32;
            uint32_t sm_off = (uint32_t)(row * AROW + lch * 16);
            size_t gk = (kRow + jt * 64 + row) * DD + h * HDIM + lch * 8;
            cpa16(bufB + sm_off,              Kh + gk);
            cpa16(bufB + APLANE + sm_off,     Kl + gk);
            size_t gv = (vRow + row) * TT + jt * 64 + lch * 8;
            cpa16(bufB + 2 * APLANE + sm_off, Vth + gv);
            cpa16(bufB + 3 * APLANE + sm_off, Vtl + gv);
        }
        cpa_commit();
    };

    const int nTiles = 2 * qb + 2;
    load_tile(0, 0);

    for (int jt = 0; jt < nTiles; jt++) {
        const uint32_t bufB = smA + (uint32_t)(jt & 1) * ABUF;

        if (jt + 1 < nTiles) {
            load_tile(jt + 1, (jt + 1) & 1);
            cpa_wait<1>();
        } else {
            cpa_wait<0>();
        }
        __syncthreads();

        // warps 0-3 are fully masked on the last diagonal tile: skip compute
        const bool skip = (jt == 2 * qb + 1) && (wid < 4);
        if (!skip) {
            // ---- S = Q K^T (split x3) ----
            float sa[8][4];
#pragma unroll
            for (int nf = 0; nf < 8; nf++)
#pragma unroll
                for (int r = 0; r < 4; r++) sa[nf][r] = 0.f;

#pragma unroll
            for (int kf = 0; kf < 4; kf++) {
                uint32_t kbh[8][2], kbl[8][2];
#pragma unroll
                for (int p = 0; p < 4; p++) {
                    uint32_t r0, r1, r2, r3;
                    uint32_t ro = (uint32_t)((p * 16 + lm_row) * AROW + (kf * 16 + lm_col) * 2);
                    ldsm4(r0, r1, r2, r3, bufB + ro);
                    kbh[2 * p][0] = r0; kbh[2 * p + 1][0] = r1;
                    kbh[2 * p][1] = r2; kbh[2 * p + 1][1] = r3;
                    ldsm4(r0, r1, r2, r3, bufB + APLANE + ro);
                    kbl[2 * p][0] = r0; kbl[2 * p + 1][0] = r1;
                    kbl[2 * p][1] = r2; kbl[2 * p + 1][1] = r3;
                }
#pragma unroll
                for (int nf = 0; nf < 8; nf++) {
                    mma16816(sa[nf], qh[kf], kbh[nf]);
                    mma16816(sa[nf], qh[kf], kbl[nf]);
                    mma16816(sa[nf], ql[kf], kbh[nf]);
                }
            }

            if (jt >= 2 * qb) {
#pragma unroll
                for (int nf = 0; nf < 8; nf++) {
                    int col = jt * 64 + nf * 8 + 2 * t;
                    if (col > rowA)         sa[nf][0] = -1e30f;
                    if (col + 1 > rowA)     sa[nf][1] = -1e30f;
                    if (col > rowA + 8)     sa[nf][2] = -1e30f;
                    if (col + 1 > rowA + 8) sa[nf][3] = -1e30f;
                }
            }

            // ---- online softmax ----
            float mx0 = -1e30f, mx1 = -1e30f;
#pragma unroll
            for (int nf = 0; nf < 8; nf++) {
                mx0 = fmaxf(mx0, fmaxf(sa[nf][0], sa[nf][1]));
                mx1 = fmaxf(mx1, fmaxf(sa[nf][2], sa[nf][3]));
            }
            mx0 = fmaxf(mx0, __shfl_xor_sync(0xffffffffu, mx0, 1));
            mx0 = fmaxf(mx0, __shfl_xor_sync(0xffffffffu, mx0, 2));
            mx1 = fmaxf(mx1, __shfl_xor_sync(0xffffffffu, mx1, 1));
            mx1 = fmaxf(mx1, __shfl_xor_sync(0xffffffffu, mx1, 2));
            float mn0 = fmaxf(m0, mx0);
            float mn1 = fmaxf(m1, mx1);
            float al0 = __expf(m0 - mn0);
            float al1 = __expf(m1 - mn1);

            float sum0 = 0.f, sum1 = 0.f;
#pragma unroll
            for (int nf = 0; nf < 8; nf++) {
                sa[nf][0] = __expf(sa[nf][0] - mn0);
                sa[nf][1] = __expf(sa[nf][1] - mn0);
                sa[nf][2] = __expf(sa[nf][2] - mn1);
                sa[nf][3] = __expf(sa[nf][3] - mn1);
                sum0 += sa[nf][0] + sa[nf][1];
                sum1 += sa[nf][2] + sa[nf][3];
            }
            sum0 += __shfl_xor_sync(0xffffffffu, sum0, 1);
            sum0 += __shfl_xor_sync(0xffffffffu, sum0, 2);
            sum1 += __shfl_xor_sync(0xffffffffu, sum1, 1);
            sum1 += __shfl_xor_sync(0xffffffffu, sum1, 2);
            l0 = l0 * al0 + sum0;
            l1 = l1 * al1 + sum1;
            m0 = mn0; m1 = mn1;
#pragma unroll
            for (int df = 0; df < 8; df++) {
                oa[df][0] *= al0; oa[df][1] *= al0;
                oa[df][2] *= al1; oa[df][3] *= al1;
            }

            // ---- O += P V (split x3) ----
#pragma unroll
            for (int kk = 0; kk < 4; kk++) {
                uint32_t pha[4], pla[4];
                split2(sa[2 * kk][0],     sa[2 * kk][1],     pha[0], pla[0]);
                split2(sa[2 * kk][2],     sa[2 * kk][3],     pha[1], pla[1]);
                split2(sa[2 * kk + 1][0], sa[2 * kk + 1][1], pha[2], pla[2]);
                split2(sa[2 * kk + 1][2], sa[2 * kk + 1][3], pha[3], pla[3]);

                uint32_t vbh[8][2], vbl[8][2];
#pragma unroll
                for (int p = 0; p < 4; p++) {
                    uint32_t r0, r1, r2, r3;
                    uint32_t ro = (uint32_t)((p * 16 + lm_row) * AROW + (kk * 16 + lm_col) * 2);
                    ldsm4(r0, r1, r2, r3, bufB + 2 * APLANE + ro);
                    vbh[2 * p][0] = r0; vbh[2 * p + 1][0] = r1;
                    vbh[2 * p][1] = r2; vbh[2 * p + 1][1] = r3;
                    ldsm4(r0, r1, r2, r3, bufB + 3 * APLANE + ro);
                    vbl[2 * p][0] = r0; vbl[2 * p + 1][0] = r1;
                    vbl[2 * p][1] = r2; vbl[2 * p + 1][1] = r3;
                }
#pragma unroll
                for (int df = 0; df < 8; df++) {
                    mma16816(oa[df], pha, vbh[df]);
                    mma16816(oa[df], pha, vbl[df]);
                    mma16816(oa[df], pla, vbh[df]);
                }
            }
        }
        __syncthreads();
    }

    float inv0 = 1.0f / l0;
    float inv1 = 1.0f / l1;
#pragma unroll
    for (int df = 0; df < 8; df++) {
        int dcol = df * 8 + 2 * t;
        size_t off0 = headBase + (size_t)rowA * DD + dcol;
        size_t off1 = headBase + (size_t)(rowA + 8) * DD + dcol;
        uint32_t hi, lo;
        split2(oa[df][0] * inv0, oa[df][1] * inv0, hi, lo);
        *(uint32_t*)&Yh[off0] = hi;
        *(uint32_t*)&Yl[off0] = lo;
        split2(oa[df][2] * inv1, oa[df][3] * inv1, hi, lo);
        *(uint32_t*)&Yh[off1] = hi;
        *(uint32_t*)&Yl[off1] = lo;
    }
}

// ---------------------------------------------------------------------------
// Launch: x, Wq, bq, Wk, bk, Wv, bv, Wo, bo (all fp32)
// ---------------------------------------------------------------------------
extern "C" void kernel_launch(void* const* d_in, const int* in_sizes, int n_in,
                              void* d_out, int out_size)
{
    const float* x  = (const float*)d_in[0];
    const float* Wq = (const float*)d_in[1];
    const float* bq = (const float*)d_in[2];
    const float* Wk = (const float*)d_in[3];
    const float* bk = (const float*)d_in[4];
    const float* Wv = (const float*)d_in[5];
    const float* bv = (const float*)d_in[6];
    const float* Wo = (const float*)d_in[7];
    const float* bo = (const float*)d_in[8];
    float* out = (float*)d_out;

    float *qf, *kf, *vf;
    bf16 *xh, *xl, *yh, *yl, *wh, *wl;
    cudaGetSymbolAddress((void**)&qf, g_q);
    cudaGetSymbolAddress((void**)&kf, g_k);
    cudaGetSymbolAddress((void**)&vf, g_v);
    cudaGetSymbolAddress((void**)&xh, g_xh);
    cudaGetSymbolAddress((void**)&xl, g_xl);
    cudaGetSymbolAddress((void**)&yh, g_yh);
    cudaGetSymbolAddress((void**)&yl, g_yl);
    cudaGetSymbolAddress((void**)&wh, g_wh);
    cudaGetSymbolAddress((void**)&wl, g_wl);

    const int nX = MROWS * DD;
    const int nW = DD * DD;

    bf16* qh  = (bf16*)qf;  bf16* ql  = qh + nX;
    bf16* kh  = (bf16*)kf;  bf16* kl  = kh + nX;
    bf16* vth = (bf16*)vf;  bf16* vtl = vth + nX;

    split_kernel<<<(nX + 255) / 256, 256>>>(x, xh, xl, nX);
    split_kernel<<<(nW + 255) / 256, 256>>>(Wq, wh + 0 * nW, wl + 0 * nW, nW);
    split_kernel<<<(nW + 255) / 256, 256>>>(Wk, wh + 1 * nW, wl + 1 * nW, nW);
    split_kernel<<<(nW + 255) / 256, 256>>>(Wv, wh + 2 * nW, wl + 2 * nW, nW);
    split_kernel<<<(nW + 255) / 256, 256>>>(Wo, wh + 3 * nW, wl + 3 * nW, nW);

    const int gemm_smem = 8 * TILEH * (int)sizeof(bf16);   // 81920 B
    cudaFuncSetAttribute(gemm_qkv, cudaFuncAttributeMaxDynamicSharedMemorySize, gemm_smem);
    cudaFuncSetAttribute(gemm_out, cudaFuncAttributeMaxDynamicSharedMemorySize, gemm_smem);

    const int attn_smem = 2 * ABUF;   // 73728 B
    cudaFuncSetAttribute(attn_mma, cudaFuncAttributeMaxDynamicSharedMemorySize, attn_smem);

    gemm_qkv<<<dim3(24, MROWS / 128), 256, gemm_smem>>>(
        xh, xl, wh, wl, bq, bk, bv, qh, ql, kh, kl, vth, vtl);

    attn_mma<<<dim3(TT / 128, BB * HH), 256, attn_smem>>>(
        qh, ql, kh, kl, vth, vtl, yh, yl);

    gemm_out<<<dim3(DD / 128, MROWS / 128), 256, gemm_smem>>>(
        yh, yl, wh + 3 * nW, wl + 3 * nW, bo, out);
}

// round 9
// speedup vs baseline: 3.4539x; 1.3780x over previous
#include <cuda_runtime.h>
#include <cuda_fp16.h>
#include <math.h>
#include <cstdint>

#define BB 4
#define TT 2048
#define DD 1024
#define HH 16
#define HDIM 64
#define MROWS (BB*TT)   // 8192
#define GK 1024

typedef __half f16;

// ---------------------------------------------------------------------------
// Scratch (device globals — no allocation allowed). fp16 planes alias floats.
// ---------------------------------------------------------------------------
__device__ float g_q[MROWS * DD];   // qh | ql (fp16 planes)
__device__ float g_k[MROWS * DD];   // kh (single plane; rest unused)
__device__ float g_v[MROWS * DD];   // vth (transposed [b][dg][t], single plane)
__device__ float g_x[MROWS * DD];   // xh | xl
__device__ float g_y[MROWS * DD];   // yh | yl
__device__ f16   g_w[4 * DD * DD];  // Wq,Wk,Wv,Wo single fp16 planes

__device__ __forceinline__ uint32_t smem_u32(const void* p) {
    return (uint32_t)__cvta_generic_to_shared(p);
}

__device__ __forceinline__ void split1h(float v, f16& h, f16& l) {
    h = __float2half_rn(v);
    l = __float2half_rn(v - __half2float(h));
}

__device__ __forceinline__ void split2h(float x, float y, uint32_t& hi, uint32_t& lo) {
    f16 hx, lx, hy, ly;
    split1h(x, hx, lx);
    split1h(y, hy, ly);
    __half2 H = __halves2half2(hx, hy);
    __half2 L = __halves2half2(lx, ly);
    hi = *reinterpret_cast<uint32_t*>(&H);
    lo = *reinterpret_cast<uint32_t*>(&L);
}

__device__ __forceinline__ void mma16816h(float* c, const uint32_t* a, const uint32_t* b) {
    asm volatile(
        "mma.sync.aligned.m16n8k16.row.col.f32.f16.f16.f32 "
        "{%0,%1,%2,%3}, {%4,%5,%6,%7}, {%8,%9}, {%0,%1,%2,%3};\n"
        : "+f"(c[0]), "+f"(c[1]), "+f"(c[2]), "+f"(c[3])
        : "r"(a[0]), "r"(a[1]), "r"(a[2]), "r"(a[3]), "r"(b[0]), "r"(b[1]));
}

__device__ __forceinline__ void ldsm4(uint32_t& r0, uint32_t& r1, uint32_t& r2, uint32_t& r3,
                                      uint32_t addr) {
    asm volatile("ldmatrix.sync.aligned.m8n8.x4.shared.b16 {%0,%1,%2,%3}, [%4];\n"
                 : "=r"(r0), "=r"(r1), "=r"(r2), "=r"(r3) : "r"(addr));
}

__device__ __forceinline__ void cpa16(uint32_t saddr, const void* g) {
    asm volatile("cp.async.ca.shared.global [%0], [%1], 16;\n" :: "r"(saddr), "l"(g));
}
__device__ __forceinline__ void cpa_commit() {
    asm volatile("cp.async.commit_group;\n");
}
template <int N>
__device__ __forceinline__ void cpa_wait() {
    asm volatile("cp.async.wait_group %0;\n" :: "n"(N));
}

// ---------------------------------------------------------------------------
// Splits / converts
// ---------------------------------------------------------------------------
__global__ void splith_kernel(const float* __restrict__ src,
                              f16* __restrict__ hi, f16* __restrict__ lo, int n)
{
    int i = blockIdx.x * blockDim.x + threadIdx.x;
    if (i < n) {
        float v = src[i];
        f16 h = __float2half_rn(v);
        hi[i] = h;
        lo[i] = __float2half_rn(v - __half2float(h));
    }
}

__global__ void convh_kernel(const float* __restrict__ src, f16* __restrict__ dst, int n)
{
    int i = blockIdx.x * blockDim.x + threadIdx.x;
    if (i < n) dst[i] = __float2half_rn(src[i]);
}

// ---------------------------------------------------------------------------
// GEMM mainloop: C = (Ah+Al) * Wh^T, 2 mmas per k-step. BK=32, 2-stage
// cp.async pipeline. 3 smem planes (sAh, sAl, sBh), 2 stages each.
// ---------------------------------------------------------------------------
#define BK 32
#define SSTR 40
#define TILEH (128 * SSTR)

#define GEMM_MAINLOOP_H(AhP, AlP, WhP)                                         \
    f16* sAh = smg;                                                            \
    f16* sAl = smg + 2 * TILEH;                                                \
    f16* sBh = smg + 4 * TILEH;                                                \
    const int lr = tid >> 1;                                                   \
    const int lc = (tid & 1) * 16;                                             \
    const f16* gAh = (AhP) + (size_t)(rowBase + lr) * GK + lc;                 \
    const f16* gAl = (AlP) + (size_t)(rowBase + lr) * GK + lc;                 \
    const f16* gWh = (WhP) + (size_t)(colBase + lr) * GK + lc;                 \
    const uint32_t soff = (uint32_t)((lr * SSTR + lc) * 2);                    \
    const uint32_t sAhB = smem_u32(sAh);                                       \
    const uint32_t sAlB = smem_u32(sAl);                                       \
    const uint32_t sBhB = smem_u32(sBh);                                       \
    const int lm_row = (lane & 15);                                            \
    const int lm_col = ((lane >> 4) << 3);                                     \
    float acc[4][4][4];                                                        \
    _Pragma("unroll")                                                          \
    for (int mf = 0; mf < 4; mf++)                                             \
        _Pragma("unroll")                                                      \
        for (int nf = 0; nf < 4; nf++)                                         \
            _Pragma("unroll")                                                  \
            for (int r = 0; r < 4; r++) acc[mf][nf][r] = 0.f;                  \
    const int nIter = GK / BK;                                                 \
    {                                                                          \
        cpa16(sAhB + soff,      gAh);  cpa16(sAhB + soff + 16, gAh + 8);       \
        cpa16(sAlB + soff,      gAl);  cpa16(sAlB + soff + 16, gAl + 8);       \
        cpa16(sBhB + soff,      gWh);  cpa16(sBhB + soff + 16, gWh + 8);       \
        cpa_commit();                                                          \
    }                                                                          \
    for (int iter = 0; iter < nIter; iter++) {                                 \
        const int buf = iter & 1;                                              \
        if (iter + 1 < nIter) {                                                \
            const uint32_t sb = (uint32_t)(((iter + 1) & 1) * TILEH * 2);      \
            const int k0 = (iter + 1) * BK;                                    \
            cpa16(sAhB + sb + soff,      gAh + k0);                            \
            cpa16(sAhB + sb + soff + 16, gAh + k0 + 8);                        \
            cpa16(sAlB + sb + soff,      gAl + k0);                            \
            cpa16(sAlB + sb + soff + 16, gAl + k0 + 8);                        \
            cpa16(sBhB + sb + soff,      gWh + k0);                            \
            cpa16(sBhB + sb + soff + 16, gWh + k0 + 8);                        \
            cpa_commit();                                                      \
            cpa_wait<1>();                                                     \
        } else {                                                               \
            cpa_wait<0>();                                                     \
        }                                                                      \
        __syncthreads();                                                       \
        _Pragma("unroll")                                                      \
        for (int ks = 0; ks < BK; ks += 16) {                                  \
            uint32_t ah[4][4], al[4][4];                                       \
            _Pragma("unroll")                                                  \
            for (int mf = 0; mf < 4; mf++) {                                   \
                int roff = (warpM * 64 + mf * 16 + lm_row) * SSTR + ks + lm_col; \
                ldsm4(ah[mf][0], ah[mf][1], ah[mf][2], ah[mf][3],              \
                      sAhB + (uint32_t)((buf * TILEH + roff) * 2));            \
                ldsm4(al[mf][0], al[mf][1], al[mf][2], al[mf][3],              \
                      sAlB + (uint32_t)((buf * TILEH + roff) * 2));            \
            }                                                                  \
            uint32_t bh[4][2];                                                 \
            _Pragma("unroll")                                                  \
            for (int p = 0; p < 2; p++) {                                      \
                int roff = (warpN * 32 + p * 16 + lm_row) * SSTR + ks + lm_col; \
                uint32_t r0, r1, r2, r3;                                       \
                ldsm4(r0, r1, r2, r3, sBhB + (uint32_t)((buf * TILEH + roff) * 2)); \
                bh[2 * p][0] = r0; bh[2 * p + 1][0] = r1;                      \
                bh[2 * p][1] = r2; bh[2 * p + 1][1] = r3;                      \
            }                                                                  \
            _Pragma("unroll")                                                  \
            for (int mf = 0; mf < 4; mf++)                                     \
                _Pragma("unroll")                                              \
                for (int nf = 0; nf < 4; nf++) {                               \
                    mma16816h(acc[mf][nf], ah[mf], bh[nf]);                    \
                    mma16816h(acc[mf][nf], al[mf], bh[nf]);                    \
                }                                                              \
        }                                                                      \
        __syncthreads();                                                       \
    }

// ---------------------------------------------------------------------------
// Fused QKV GEMM + bias + RoPE + fp16 outputs (+ V transposed).
// Grid (24, 64): bx 0-7 -> q (split x2), 8-15 -> k (single), 16-23 -> v (single, T).
// ---------------------------------------------------------------------------
__global__ void __launch_bounds__(256) gemm_qkv(
    const f16* __restrict__ Ah, const f16* __restrict__ Al,
    const f16* __restrict__ Wh,
    const float* __restrict__ bq, const float* __restrict__ bk,
    const float* __restrict__ bv,
    f16* __restrict__ qh_, f16* __restrict__ ql_,
    f16* __restrict__ kh_, f16* __restrict__ vth_)
{
    extern __shared__ f16 smg[];
    const int tid  = threadIdx.x;
    const int lane = tid & 31;
    const int wid  = tid >> 5;
    const int warpM = wid >> 2;
    const int warpN = wid & 3;
    const int bx = blockIdx.x;
    const int rowBase = blockIdx.y * 128;
    const int colBase = bx * 128;

    GEMM_MAINLOOP_H(Ah, Al, Wh)

    // ---- epilogue: stage to smem fp32 with bias ----
    float* Csm = (float*)smg;   // [128][132]
    const float* biasp = (bx < 8) ? (bq + bx * 128)
                       : (bx < 16) ? (bk + (bx - 8) * 128)
                                   : (bv + (bx - 16) * 128);
#pragma unroll
    for (int mf = 0; mf < 4; mf++)
#pragma unroll
        for (int nf = 0; nf < 4; nf++) {
            int r0 = warpM * 64 + mf * 16 + (lane >> 2);
            int c0 = warpN * 32 + nf * 8 + (lane & 3) * 2;
            Csm[r0 * 132 + c0]           = acc[mf][nf][0] + biasp[c0];
            Csm[r0 * 132 + c0 + 1]       = acc[mf][nf][1] + biasp[c0 + 1];
            Csm[(r0 + 8) * 132 + c0]     = acc[mf][nf][2] + biasp[c0];
            Csm[(r0 + 8) * 132 + c0 + 1] = acc[mf][nf][3] + biasp[c0 + 1];
        }
    __syncthreads();

    const int bB = rowBase >> 11;       // batch
    const int t0 = rowBase & 2047;      // time offset within batch

    if (bx < 8) {
        // q: RoPE + scale + split x2
        const int colB = bx * 128;
        const float lnc = logf(10000.f) / 32.f;
        for (int idx = tid; idx < 128 * 64; idx += 256) {
            int r  = idx >> 6;
            int pp = idx & 63;
            int hl = pp >> 5, dd = pp & 31;
            int c1 = hl * 64 + dd, c2 = c1 + 32;
            float x1 = Csm[r * 132 + c1];
            float x2 = Csm[r * 132 + c2];
            float theta = expf(-(float)dd * lnc);
            float ang = (float)(t0 + r + 1) * theta;
            float s, c;
            sincosf(ang, &s, &c);
            float y1 = (x1 * c - x2 * s) * 0.125f;
            float y2 = (x2 * c + x1 * s) * 0.125f;
            size_t gr = (size_t)(rowBase + r) * DD + colB;
            f16 hh, ll;
            split1h(y1, hh, ll); qh_[gr + c1] = hh; ql_[gr + c1] = ll;
            split1h(y2, hh, ll); qh_[gr + c2] = hh; ql_[gr + c2] = ll;
        }
    } else if (bx < 16) {
        // k: RoPE + single fp16
        const int colB = (bx - 8) * 128;
        const float lnc = logf(10000.f) / 32.f;
        for (int idx = tid; idx < 128 * 64; idx += 256) {
            int r  = idx >> 6;
            int pp = idx & 63;
            int hl = pp >> 5, dd = pp & 31;
            int c1 = hl * 64 + dd, c2 = c1 + 32;
            float x1 = Csm[r * 132 + c1];
            float x2 = Csm[r * 132 + c2];
            float theta = expf(-(float)dd * lnc);
            float ang = (float)(t0 + r + 1) * theta;
            float s, c;
            sincosf(ang, &s, &c);
            size_t gr = (size_t)(rowBase + r) * DD + colB;
            kh_[gr + c1] = __float2half_rn(x1 * c - x2 * s);
            kh_[gr + c2] = __float2half_rn(x2 * c + x1 * s);
        }
    } else {
        // v: single fp16, transposed store vt[b][dg][t]
        const int cb = bx - 16;
#pragma unroll
        for (int pass = 0; pass < 4; pass++) {
            int c  = pass * 32 + (wid << 2) + (lane >> 3);
            int rb = (lane & 7) * 16;
            __align__(16) f16 bh2[16];
#pragma unroll
            for (int i = 0; i < 16; i++)
                bh2[i] = __float2half_rn(Csm[(rb + i) * 132 + c]);
            size_t vb = ((size_t)bB * DD + cb * 128 + c) * TT + t0 + rb;
            *(uint4*)(vth_ + vb)     = *(uint4*)&bh2[0];
            *(uint4*)(vth_ + vb + 8) = *(uint4*)&bh2[8];
        }
    }
}

// ---------------------------------------------------------------------------
// Output-projection GEMM: C = (Yh+Yl) Wo^T + bias, fp32 out.
// ---------------------------------------------------------------------------
__global__ void __launch_bounds__(256) gemm_out(
    const f16* __restrict__ Ah, const f16* __restrict__ Al,
    const f16* __restrict__ Wh,
    const float* __restrict__ bias, float* __restrict__ C)
{
    extern __shared__ f16 smg[];
    const int tid  = threadIdx.x;
    const int lane = tid & 31;
    const int wid  = tid >> 5;
    const int warpM = wid >> 2;
    const int warpN = wid & 3;
    const int rowBase = blockIdx.y * 128;
    const int colBase = blockIdx.x * 128;

    GEMM_MAINLOOP_H(Ah, Al, Wh)

#pragma unroll
    for (int mf = 0; mf < 4; mf++)
#pragma unroll
        for (int nf = 0; nf < 4; nf++) {
            int m0 = rowBase + warpM * 64 + mf * 16 + (lane >> 2);
            int n0 = colBase + warpN * 32 + nf * 8 + (lane & 3) * 2;
            float b0 = bias[n0], b1 = bias[n0 + 1];
            float2 o0 = make_float2(acc[mf][nf][0] + b0, acc[mf][nf][1] + b1);
            float2 o1 = make_float2(acc[mf][nf][2] + b0, acc[mf][nf][3] + b1);
            *(float2*)&C[(size_t)m0 * DD + n0]       = o0;
            *(float2*)&C[(size_t)(m0 + 8) * DD + n0] = o1;
        }
}

// ---------------------------------------------------------------------------
// Flash attention, fp16 x2 one-sided split.
// K/V single planes, double-buffered; Q split x2; P split x2.
// Buffer (per buf, 18432 B): Kh | Vh, each 64 rows x 144 B.
// ---------------------------------------------------------------------------
#define AROW 144
#define APLANE (64 * AROW)
#define ABUF (2 * APLANE)

__global__ void __launch_bounds__(256) attn_mma(
    const f16* __restrict__ Qh, const f16* __restrict__ Ql,
    const f16* __restrict__ Kh, const f16* __restrict__ Vth,
    f16* __restrict__ Yh, f16* __restrict__ Yl)
{
    extern __shared__ f16 asmem[];
    const uint32_t smA = smem_u32(asmem);

    const int tid  = threadIdx.x;
    const int lane = tid & 31;
    const int wid  = tid >> 5;
    const int g    = lane >> 2;
    const int t    = lane & 3;
    const int lm_row = lane & 15;
    const int lm_col = (lane >> 4) << 3;

    const int qb = (gridDim.x - 1) - blockIdx.x;
    const int bh = blockIdx.y;
    const int b  = bh >> 4;
    const int h  = bh & 15;

    const size_t headBase = (size_t)b * TT * DD + h * HDIM;
    const size_t kRow = (size_t)b * TT;
    const size_t vRow = (size_t)b * DD + h * HDIM;
    const int rowA = qb * 128 + wid * 16 + g;

    // ---- Q fragments ----
    uint32_t qh[4][4], ql[4][4];
#pragma unroll
    for (int kf = 0; kf < 4; kf++) {
        int c0 = kf * 16 + 2 * t;
        size_t o00 = headBase + (size_t)rowA * DD + c0;
        size_t o10 = headBase + (size_t)(rowA + 8) * DD + c0;
        qh[kf][0] = *(const uint32_t*)(Qh + o00);
        qh[kf][1] = *(const uint32_t*)(Qh + o10);
        qh[kf][2] = *(const uint32_t*)(Qh + o00 + 8);
        qh[kf][3] = *(const uint32_t*)(Qh + o10 + 8);
        ql[kf][0] = *(const uint32_t*)(Ql + o00);
        ql[kf][1] = *(const uint32_t*)(Ql + o10);
        ql[kf][2] = *(const uint32_t*)(Ql + o00 + 8);
        ql[kf][3] = *(const uint32_t*)(Ql + o10 + 8);
    }

    float oa[8][4];
#pragma unroll
    for (int df = 0; df < 8; df++)
#pragma unroll
        for (int r = 0; r < 4; r++) oa[df][r] = 0.f;
    float m0 = -1e30f, m1 = -1e30f, l0 = 0.f, l1 = 0.f;

    const int lrow = tid >> 3;          // 0..31 (x2 -> 64 rows)
    const int lch  = tid & 7;

    auto load_tile = [&](int jt, int bsel) {
        const uint32_t bufB = smA + (uint32_t)bsel * ABUF;
#pragma unroll
        for (int i = 0; i < 2; i++) {
            int row = lrow + i * 32;
            uint32_t sm_off = (uint32_t)(row * AROW + lch * 16);
            size_t gk = (kRow + jt * 64 + row) * DD + h * HDIM + lch * 8;
            cpa16(bufB + sm_off,          Kh + gk);
            size_t gv = (vRow + row) * TT + jt * 64 + lch * 8;
            cpa16(bufB + APLANE + sm_off, Vth + gv);
        }
        cpa_commit();
    };

    const int nTiles = 2 * qb + 2;
    load_tile(0, 0);

    for (int jt = 0; jt < nTiles; jt++) {
        const uint32_t bufB = smA + (uint32_t)(jt & 1) * ABUF;

        if (jt + 1 < nTiles) {
            load_tile(jt + 1, (jt + 1) & 1);
            cpa_wait<1>();
        } else {
            cpa_wait<0>();
        }
        __syncthreads();

        const bool skip = (jt == 2 * qb + 1) && (wid < 4);
        if (!skip) {
            // ---- S = Q K^T (2 mmas) ----
            float sa[8][4];
#pragma unroll
            for (int nf = 0; nf < 8; nf++)
#pragma unroll
                for (int r = 0; r < 4; r++) sa[nf][r] = 0.f;

#pragma unroll
            for (int kf = 0; kf < 4; kf++) {
                uint32_t kbh[8][2];
#pragma unroll
                for (int p = 0; p < 4; p++) {
                    uint32_t r0, r1, r2, r3;
                    uint32_t ro = (uint32_t)((p * 16 + lm_row) * AROW + (kf * 16 + lm_col) * 2);
                    ldsm4(r0, r1, r2, r3, bufB + ro);
                    kbh[2 * p][0] = r0; kbh[2 * p + 1][0] = r1;
                    kbh[2 * p][1] = r2; kbh[2 * p + 1][1] = r3;
                }
#pragma unroll
                for (int nf = 0; nf < 8; nf++) {
                    mma16816h(sa[nf], qh[kf], kbh[nf]);
                    mma16816h(sa[nf], ql[kf], kbh[nf]);
                }
            }

            if (jt >= 2 * qb) {
#pragma unroll
                for (int nf = 0; nf < 8; nf++) {
                    int col = jt * 64 + nf * 8 + 2 * t;
                    if (col > rowA)         sa[nf][0] = -1e30f;
                    if (col + 1 > rowA)     sa[nf][1] = -1e30f;
                    if (col > rowA + 8)     sa[nf][2] = -1e30f;
                    if (col + 1 > rowA + 8) sa[nf][3] = -1e30f;
                }
            }

            // ---- online softmax ----
            float mx0 = -1e30f, mx1 = -1e30f;
#pragma unroll
            for (int nf = 0; nf < 8; nf++) {
                mx0 = fmaxf(mx0, fmaxf(sa[nf][0], sa[nf][1]));
                mx1 = fmaxf(mx1, fmaxf(sa[nf][2], sa[nf][3]));
            }
            mx0 = fmaxf(mx0, __shfl_xor_sync(0xffffffffu, mx0, 1));
            mx0 = fmaxf(mx0, __shfl_xor_sync(0xffffffffu, mx0, 2));
            mx1 = fmaxf(mx1, __shfl_xor_sync(0xffffffffu, mx1, 1));
            mx1 = fmaxf(mx1, __shfl_xor_sync(0xffffffffu, mx1, 2));
            float mn0 = fmaxf(m0, mx0);
            float mn1 = fmaxf(m1, mx1);
            float al0 = __expf(m0 - mn0);
            float al1 = __expf(m1 - mn1);

            float sum0 = 0.f, sum1 = 0.f;
#pragma unroll
            for (int nf = 0; nf < 8; nf++) {
                sa[nf][0] = __expf(sa[nf][0] - mn0);
                sa[nf][1] = __expf(sa[nf][1] - mn0);
                sa[nf][2] = __expf(sa[nf][2] - mn1);
                sa[nf][3] = __expf(sa[nf][3] - mn1);
                sum0 += sa[nf][0] + sa[nf][1];
                sum1 += sa[nf][2] + sa[nf][3];
            }
            sum0 += __shfl_xor_sync(0xffffffffu, sum0, 1);
            sum0 += __shfl_xor_sync(0xffffffffu, sum0, 2);
            sum1 += __shfl_xor_sync(0xffffffffu, sum1, 1);
            sum1 += __shfl_xor_sync(0xffffffffu, sum1, 2);
            l0 = l0 * al0 + sum0;
            l1 = l1 * al1 + sum1;
            m0 = mn0; m1 = mn1;
#pragma unroll
            for (int df = 0; df < 8; df++) {
                oa[df][0] *= al0; oa[df][1] *= al0;
                oa[df][2] *= al1; oa[df][3] *= al1;
            }

            // ---- O += P V (2 mmas, P split x2) ----
#pragma unroll
            for (int kk = 0; kk < 4; kk++) {
                uint32_t pha[4], pla[4];
                split2h(sa[2 * kk][0],     sa[2 * kk][1],     pha[0], pla[0]);
                split2h(sa[2 * kk][2],     sa[2 * kk][3],     pha[1], pla[1]);
                split2h(sa[2 * kk + 1][0], sa[2 * kk + 1][1], pha[2], pla[2]);
                split2h(sa[2 * kk + 1][2], sa[2 * kk + 1][3], pha[3], pla[3]);

                uint32_t vbh[8][2];
#pragma unroll
                for (int p = 0; p < 4; p++) {
                    uint32_t r0, r1, r2, r3;
                    uint32_t ro = (uint32_t)((p * 16 + lm_row) * AROW + (kk * 16 + lm_col) * 2);
                    ldsm4(r0, r1, r2, r3, bufB + APLANE + ro);
                    vbh[2 * p][0] = r0; vbh[2 * p + 1][0] = r1;
                    vbh[2 * p][1] = r2; vbh[2 * p + 1][1] = r3;
                }
#pragma unroll
                for (int df = 0; df < 8; df++) {
                    mma16816h(oa[df], pha, vbh[df]);
                    mma16816h(oa[df], pla, vbh[df]);
                }
            }
        }
        __syncthreads();
    }

    float inv0 = 1.0f / l0;
    float inv1 = 1.0f / l1;
#pragma unroll
    for (int df = 0; df < 8; df++) {
        int dcol = df * 8 + 2 * t;
        size_t off0 = headBase + (size_t)rowA * DD + dcol;
        size_t off1 = headBase + (size_t)(rowA + 8) * DD + dcol;
        uint32_t hi, lo;
        split2h(oa[df][0] * inv0, oa[df][1] * inv0, hi, lo);
        *(uint32_t*)&Yh[off0] = hi;
        *(uint32_t*)&Yl[off0] = lo;
        split2h(oa[df][2] * inv1, oa[df][3] * inv1, hi, lo);
        *(uint32_t*)&Yh[off1] = hi;
        *(uint32_t*)&Yl[off1] = lo;
    }
}

// ---------------------------------------------------------------------------
// Launch: x, Wq, bq, Wk, bk, Wv, bv, Wo, bo (all fp32)
// ---------------------------------------------------------------------------
extern "C" void kernel_launch(void* const* d_in, const int* in_sizes, int n_in,
                              void* d_out, int out_size)
{
    const float* x  = (const float*)d_in[0];
    const float* Wq = (const float*)d_in[1];
    const float* bq = (const float*)d_in[2];
    const float* Wk = (const float*)d_in[3];
    const float* bk = (const float*)d_in[4];
    const float* Wv = (const float*)d_in[5];
    const float* bv = (const float*)d_in[6];
    const float* Wo = (const float*)d_in[7];
    const float* bo = (const float*)d_in[8];
    float* out = (float*)d_out;

    float *qf, *kf, *vf, *xf, *yf;
    f16 *wp;
    cudaGetSymbolAddress((void**)&qf, g_q);
    cudaGetSymbolAddress((void**)&kf, g_k);
    cudaGetSymbolAddress((void**)&vf, g_v);
    cudaGetSymbolAddress((void**)&xf, g_x);
    cudaGetSymbolAddress((void**)&yf, g_y);
    cudaGetSymbolAddress((void**)&wp, g_w);

    const int nX = MROWS * DD;
    const int nW = DD * DD;

    f16* xh  = (f16*)xf;  f16* xl  = xh + nX;
    f16* yh  = (f16*)yf;  f16* yl  = yh + nX;
    f16* qh  = (f16*)qf;  f16* ql  = qh + nX;
    f16* kh  = (f16*)kf;
    f16* vth = (f16*)vf;

    splith_kernel<<<(nX + 255) / 256, 256>>>(x, xh, xl, nX);
    convh_kernel<<<(nW + 255) / 256, 256>>>(Wq, wp + 0 * nW, nW);
    convh_kernel<<<(nW + 255) / 256, 256>>>(Wk, wp + 1 * nW, nW);
    convh_kernel<<<(nW + 255) / 256, 256>>>(Wv, wp + 2 * nW, nW);
    convh_kernel<<<(nW + 255) / 256, 256>>>(Wo, wp + 3 * nW, nW);

    const int gemm_smem = 128 * 132 * 4;   // 67584 B (>= 6*TILEH*2 = 61440)
    cudaFuncSetAttribute(gemm_qkv, cudaFuncAttributeMaxDynamicSharedMemorySize, gemm_smem);
    cudaFuncSetAttribute(gemm_out, cudaFuncAttributeMaxDynamicSharedMemorySize, gemm_smem);

    const int attn_smem = 2 * ABUF;   // 36864 B
    cudaFuncSetAttribute(attn_mma, cudaFuncAttributeMaxDynamicSharedMemorySize, attn_smem);

    gemm_qkv<<<dim3(24, MROWS / 128), 256, gemm_smem>>>(
        xh, xl, wp, bq, bk, bv, qh, ql, kh, vth);

    attn_mma<<<dim3(TT / 128, BB * HH), 256, attn_smem>>>(
        qh, ql, kh, vth, yh, yl);

    gemm_out<<<dim3(DD / 128, MROWS / 128), 256, gemm_smem>>>(
        yh, yl, wp + 3 * nW, bo, out);
}

// round 10
// speedup vs baseline: 3.9347x; 1.1392x over previous
#include <cuda_runtime.h>
#include <cuda_fp16.h>
#include <math.h>
#include <cstdint>

#define BB 4
#define TT 2048
#define DD 1024
#define HH 16
#define HDIM 64
#define MROWS (BB*TT)   // 8192
#define GK 1024

typedef __half f16;

// ---------------------------------------------------------------------------
// Scratch (device globals — no allocation allowed). fp16 planes alias floats.
// ---------------------------------------------------------------------------
__device__ float g_q[MROWS * DD];   // qh | ql (fp16 planes)
__device__ float g_k[MROWS * DD];   // kh (single plane)
__device__ float g_v[MROWS * DD];   // vth (transposed [b][dg][t], single plane)
__device__ float g_x[MROWS * DD];   // xh | xl
__device__ float g_y[MROWS * DD];   // yh | yl
__device__ f16   g_w[4 * DD * DD];  // Wq,Wk,Wv,Wo single fp16 planes

__device__ __forceinline__ uint32_t smem_u32(const void* p) {
    return (uint32_t)__cvta_generic_to_shared(p);
}

__device__ __forceinline__ void split1h(float v, f16& h, f16& l) {
    h = __float2half_rn(v);
    l = __float2half_rn(v - __half2float(h));
}

__device__ __forceinline__ void split2h(float x, float y, uint32_t& hi, uint32_t& lo) {
    f16 hx, lx, hy, ly;
    split1h(x, hx, lx);
    split1h(y, hy, ly);
    __half2 H = __halves2half2(hx, hy);
    __half2 L = __halves2half2(lx, ly);
    hi = *reinterpret_cast<uint32_t*>(&H);
    lo = *reinterpret_cast<uint32_t*>(&L);
}

__device__ __forceinline__ uint32_t pack2h(float x, float y) {
    __half2 H = __floats2half2_rn(x, y);
    return *reinterpret_cast<uint32_t*>(&H);
}

__device__ __forceinline__ void mma16816h(float* c, const uint32_t* a, const uint32_t* b) {
    asm volatile(
        "mma.sync.aligned.m16n8k16.row.col.f32.f16.f16.f32 "
        "{%0,%1,%2,%3}, {%4,%5,%6,%7}, {%8,%9}, {%0,%1,%2,%3};\n"
        : "+f"(c[0]), "+f"(c[1]), "+f"(c[2]), "+f"(c[3])
        : "r"(a[0]), "r"(a[1]), "r"(a[2]), "r"(a[3]), "r"(b[0]), "r"(b[1]));
}

__device__ __forceinline__ void ldsm4(uint32_t& r0, uint32_t& r1, uint32_t& r2, uint32_t& r3,
                                      uint32_t addr) {
    asm volatile("ldmatrix.sync.aligned.m8n8.x4.shared.b16 {%0,%1,%2,%3}, [%4];\n"
                 : "=r"(r0), "=r"(r1), "=r"(r2), "=r"(r3) : "r"(addr));
}

__device__ __forceinline__ void cpa16(uint32_t saddr, const void* g) {
    asm volatile("cp.async.ca.shared.global [%0], [%1], 16;\n" :: "r"(saddr), "l"(g));
}
__device__ __forceinline__ void cpa_commit() {
    asm volatile("cp.async.commit_group;\n");
}
template <int N>
__device__ __forceinline__ void cpa_wait() {
    asm volatile("cp.async.wait_group %0;\n" :: "n"(N));
}

// ---------------------------------------------------------------------------
// Splits / converts
// ---------------------------------------------------------------------------
__global__ void splith_kernel(const float* __restrict__ src,
                              f16* __restrict__ hi, f16* __restrict__ lo, int n)
{
    int i = blockIdx.x * blockDim.x + threadIdx.x;
    if (i < n) {
        float v = src[i];
        f16 h = __float2half_rn(v);
        hi[i] = h;
        lo[i] = __float2half_rn(v - __half2float(h));
    }
}

// Convert all 4 weight matrices in one launch. srcs laid out by quadrant.
__global__ void convh4_kernel(const float* __restrict__ s0, const float* __restrict__ s1,
                              const float* __restrict__ s2, const float* __restrict__ s3,
                              f16* __restrict__ dst, int nW)
{
    int i = blockIdx.x * blockDim.x + threadIdx.x;
    int seg = i / nW;
    int off = i - seg * nW;
    const float* s = (seg == 0) ? s0 : (seg == 1) ? s1 : (seg == 2) ? s2 : s3;
    dst[i] = __float2half_rn(s[off]);
}

// ---------------------------------------------------------------------------
// GEMM mainloop: C = (Ah [+ Al]) * Wh^T. DOAL selects split-x2 vs single-A
// (block-uniform flag). BK=32, 2-stage cp.async pipeline.
// ---------------------------------------------------------------------------
#define BK 32
#define SSTR 40
#define TILEH (128 * SSTR)

#define GEMM_MAINLOOP_H(AhP, AlP, WhP, DOAL)                                   \
    f16* sAh = smg;                                                            \
    f16* sAl = smg + 2 * TILEH;                                                \
    f16* sBh = smg + 4 * TILEH;                                                \
    const bool doAl = (DOAL);                                                  \
    const int lr = tid >> 1;                                                   \
    const int lc = (tid & 1) * 16;                                             \
    const f16* gAh = (AhP) + (size_t)(rowBase + lr) * GK + lc;                 \
    const f16* gAl = (AlP) + (size_t)(rowBase + lr) * GK + lc;                 \
    const f16* gWh = (WhP) + (size_t)(colBase + lr) * GK + lc;                 \
    const uint32_t soff = (uint32_t)((lr * SSTR + lc) * 2);                    \
    const uint32_t sAhB = smem_u32(sAh);                                       \
    const uint32_t sAlB = smem_u32(sAl);                                       \
    const uint32_t sBhB = smem_u32(sBh);                                       \
    const int lm_row = (lane & 15);                                            \
    const int lm_col = ((lane >> 4) << 3);                                     \
    float acc[4][4][4];                                                        \
    _Pragma("unroll")                                                          \
    for (int mf = 0; mf < 4; mf++)                                             \
        _Pragma("unroll")                                                      \
        for (int nf = 0; nf < 4; nf++)                                         \
            _Pragma("unroll")                                                  \
            for (int r = 0; r < 4; r++) acc[mf][nf][r] = 0.f;                  \
    const int nIter = GK / BK;                                                 \
    {                                                                          \
        cpa16(sAhB + soff,      gAh);  cpa16(sAhB + soff + 16, gAh + 8);       \
        if (doAl) { cpa16(sAlB + soff, gAl); cpa16(sAlB + soff + 16, gAl + 8); } \
        cpa16(sBhB + soff,      gWh);  cpa16(sBhB + soff + 16, gWh + 8);       \
        cpa_commit();                                                          \
    }                                                                          \
    for (int iter = 0; iter < nIter; iter++) {                                 \
        const int buf = iter & 1;                                              \
        if (iter + 1 < nIter) {                                                \
            const uint32_t sb = (uint32_t)(((iter + 1) & 1) * TILEH * 2);      \
            const int k0 = (iter + 1) * BK;                                    \
            cpa16(sAhB + sb + soff,      gAh + k0);                            \
            cpa16(sAhB + sb + soff + 16, gAh + k0 + 8);                        \
            if (doAl) {                                                        \
                cpa16(sAlB + sb + soff,      gAl + k0);                        \
                cpa16(sAlB + sb + soff + 16, gAl + k0 + 8);                    \
            }                                                                  \
            cpa16(sBhB + sb + soff,      gWh + k0);                            \
            cpa16(sBhB + sb + soff + 16, gWh + k0 + 8);                        \
            cpa_commit();                                                      \
            cpa_wait<1>();                                                     \
        } else {                                                               \
            cpa_wait<0>();                                                     \
        }                                                                      \
        __syncthreads();                                                       \
        _Pragma("unroll")                                                      \
        for (int ks = 0; ks < BK; ks += 16) {                                  \
            uint32_t ah[4][4], al[4][4];                                       \
            _Pragma("unroll")                                                  \
            for (int mf = 0; mf < 4; mf++) {                                   \
                int roff = (warpM * 64 + mf * 16 + lm_row) * SSTR + ks + lm_col; \
                ldsm4(ah[mf][0], ah[mf][1], ah[mf][2], ah[mf][3],              \
                      sAhB + (uint32_t)((buf * TILEH + roff) * 2));            \
                if (doAl)                                                      \
                    ldsm4(al[mf][0], al[mf][1], al[mf][2], al[mf][3],          \
                          sAlB + (uint32_t)((buf * TILEH + roff) * 2));        \
            }                                                                  \
            uint32_t bh[4][2];                                                 \
            _Pragma("unroll")                                                  \
            for (int p = 0; p < 2; p++) {                                      \
                int roff = (warpN * 32 + p * 16 + lm_row) * SSTR + ks + lm_col; \
                uint32_t r0, r1, r2, r3;                                       \
                ldsm4(r0, r1, r2, r3, sBhB + (uint32_t)((buf * TILEH + roff) * 2)); \
                bh[2 * p][0] = r0; bh[2 * p + 1][0] = r1;                      \
                bh[2 * p][1] = r2; bh[2 * p + 1][1] = r3;                      \
            }                                                                  \
            _Pragma("unroll")                                                  \
            for (int mf = 0; mf < 4; mf++)                                     \
                _Pragma("unroll")                                              \
                for (int nf = 0; nf < 4; nf++) {                               \
                    mma16816h(acc[mf][nf], ah[mf], bh[nf]);                    \
                    if (doAl) mma16816h(acc[mf][nf], al[mf], bh[nf]);          \
                }                                                              \
        }                                                                      \
        __syncthreads();                                                       \
    }

// ---------------------------------------------------------------------------
// Fused QKV GEMM + bias + RoPE + fp16 outputs (+ V transposed).
// Grid (24, 64): bx 0-7 -> q (x split x2), 8-15 -> k (x split x2),
// 16-23 -> v (x single fp16, transposed store).
// ---------------------------------------------------------------------------
__global__ void __launch_bounds__(256) gemm_qkv(
    const f16* __restrict__ Ah, const f16* __restrict__ Al,
    const f16* __restrict__ Wh,
    const float* __restrict__ bq, const float* __restrict__ bk,
    const float* __restrict__ bv,
    f16* __restrict__ qh_, f16* __restrict__ ql_,
    f16* __restrict__ kh_, f16* __restrict__ vth_)
{
    extern __shared__ f16 smg[];
    const int tid  = threadIdx.x;
    const int lane = tid & 31;
    const int wid  = tid >> 5;
    const int warpM = wid >> 2;
    const int warpN = wid & 3;
    const int bx = blockIdx.x;
    const int rowBase = blockIdx.y * 128;
    const int colBase = bx * 128;

    GEMM_MAINLOOP_H(Ah, Al, Wh, bx < 16)

    // ---- epilogue: stage to smem fp32 with bias ----
    float* Csm = (float*)smg;   // [128][132]
    const float* biasp = (bx < 8) ? (bq + bx * 128)
                       : (bx < 16) ? (bk + (bx - 8) * 128)
                                   : (bv + (bx - 16) * 128);
#pragma unroll
    for (int mf = 0; mf < 4; mf++)
#pragma unroll
        for (int nf = 0; nf < 4; nf++) {
            int r0 = warpM * 64 + mf * 16 + (lane >> 2);
            int c0 = warpN * 32 + nf * 8 + (lane & 3) * 2;
            Csm[r0 * 132 + c0]           = acc[mf][nf][0] + biasp[c0];
            Csm[r0 * 132 + c0 + 1]       = acc[mf][nf][1] + biasp[c0 + 1];
            Csm[(r0 + 8) * 132 + c0]     = acc[mf][nf][2] + biasp[c0];
            Csm[(r0 + 8) * 132 + c0 + 1] = acc[mf][nf][3] + biasp[c0 + 1];
        }
    __syncthreads();

    const int bB = rowBase >> 11;       // batch
    const int t0 = rowBase & 2047;      // time offset within batch

    if (bx < 8) {
        // q: RoPE + scale + split x2
        const int colB = bx * 128;
        const float lnc = logf(10000.f) / 32.f;
        for (int idx = tid; idx < 128 * 64; idx += 256) {
            int r  = idx >> 6;
            int pp = idx & 63;
            int hl = pp >> 5, dd = pp & 31;
            int c1 = hl * 64 + dd, c2 = c1 + 32;
            float x1 = Csm[r * 132 + c1];
            float x2 = Csm[r * 132 + c2];
            float theta = expf(-(float)dd * lnc);
            float ang = (float)(t0 + r + 1) * theta;
            float s, c;
            sincosf(ang, &s, &c);
            float y1 = (x1 * c - x2 * s) * 0.125f;
            float y2 = (x2 * c + x1 * s) * 0.125f;
            size_t gr = (size_t)(rowBase + r) * DD + colB;
            f16 hh, ll;
            split1h(y1, hh, ll); qh_[gr + c1] = hh; ql_[gr + c1] = ll;
            split1h(y2, hh, ll); qh_[gr + c2] = hh; ql_[gr + c2] = ll;
        }
    } else if (bx < 16) {
        // k: RoPE + single fp16
        const int colB = (bx - 8) * 128;
        const float lnc = logf(10000.f) / 32.f;
        for (int idx = tid; idx < 128 * 64; idx += 256) {
            int r  = idx >> 6;
            int pp = idx & 63;
            int hl = pp >> 5, dd = pp & 31;
            int c1 = hl * 64 + dd, c2 = c1 + 32;
            float x1 = Csm[r * 132 + c1];
            float x2 = Csm[r * 132 + c2];
            float theta = expf(-(float)dd * lnc);
            float ang = (float)(t0 + r + 1) * theta;
            float s, c;
            sincosf(ang, &s, &c);
            size_t gr = (size_t)(rowBase + r) * DD + colB;
            kh_[gr + c1] = __float2half_rn(x1 * c - x2 * s);
            kh_[gr + c2] = __float2half_rn(x2 * c + x1 * s);
        }
    } else {
        // v: single fp16, transposed store vt[b][dg][t]
        const int cb = bx - 16;
#pragma unroll
        for (int pass = 0; pass < 4; pass++) {
            int c  = pass * 32 + (wid << 2) + (lane >> 3);
            int rb = (lane & 7) * 16;
            __align__(16) f16 bh2[16];
#pragma unroll
            for (int i = 0; i < 16; i++)
                bh2[i] = __float2half_rn(Csm[(rb + i) * 132 + c]);
            size_t vb = ((size_t)bB * DD + cb * 128 + c) * TT + t0 + rb;
            *(uint4*)(vth_ + vb)     = *(uint4*)&bh2[0];
            *(uint4*)(vth_ + vb + 8) = *(uint4*)&bh2[8];
        }
    }
}

// ---------------------------------------------------------------------------
// Output-projection GEMM: C = (Yh+Yl) Wo^T + bias, fp32 out.
// ---------------------------------------------------------------------------
__global__ void __launch_bounds__(256) gemm_out(
    const f16* __restrict__ Ah, const f16* __restrict__ Al,
    const f16* __restrict__ Wh,
    const float* __restrict__ bias, float* __restrict__ C)
{
    extern __shared__ f16 smg[];
    const int tid  = threadIdx.x;
    const int lane = tid & 31;
    const int wid  = tid >> 5;
    const int warpM = wid >> 2;
    const int warpN = wid & 3;
    const int rowBase = blockIdx.y * 128;
    const int colBase = blockIdx.x * 128;

    GEMM_MAINLOOP_H(Ah, Al, Wh, true)

#pragma unroll
    for (int mf = 0; mf < 4; mf++)
#pragma unroll
        for (int nf = 0; nf < 4; nf++) {
            int m0 = rowBase + warpM * 64 + mf * 16 + (lane >> 2);
            int n0 = colBase + warpN * 32 + nf * 8 + (lane & 3) * 2;
            float b0 = bias[n0], b1 = bias[n0 + 1];
            float2 o0 = make_float2(acc[mf][nf][0] + b0, acc[mf][nf][1] + b1);
            float2 o1 = make_float2(acc[mf][nf][2] + b0, acc[mf][nf][3] + b1);
            *(float2*)&C[(size_t)m0 * DD + n0]       = o0;
            *(float2*)&C[(size_t)(m0 + 8) * DD + n0] = o1;
        }
}

// ---------------------------------------------------------------------------
// Flash attention: S = (Qh+Ql) K^T (2 mmas), P·V single-plane (1 mma).
// K/V single fp16, double-buffered. Buffer (18432 B): Kh | Vh, 64 x 144 B.
// ---------------------------------------------------------------------------
#define AROW 144
#define APLANE (64 * AROW)
#define ABUF (2 * APLANE)

__global__ void __launch_bounds__(256) attn_mma(
    const f16* __restrict__ Qh, const f16* __restrict__ Ql,
    const f16* __restrict__ Kh, const f16* __restrict__ Vth,
    f16* __restrict__ Yh, f16* __restrict__ Yl)
{
    extern __shared__ f16 asmem[];
    const uint32_t smA = smem_u32(asmem);

    const int tid  = threadIdx.x;
    const int lane = tid & 31;
    const int wid  = tid >> 5;
    const int g    = lane >> 2;
    const int t    = lane & 3;
    const int lm_row = lane & 15;
    const int lm_col = (lane >> 4) << 3;

    const int qb = (gridDim.x - 1) - blockIdx.x;
    const int bh = blockIdx.y;
    const int b  = bh >> 4;
    const int h  = bh & 15;

    const size_t headBase = (size_t)b * TT * DD + h * HDIM;
    const size_t kRow = (size_t)b * TT;
    const size_t vRow = (size_t)b * DD + h * HDIM;
    const int rowA = qb * 128 + wid * 16 + g;

    // ---- Q fragments ----
    uint32_t qh[4][4], ql[4][4];
#pragma unroll
    for (int kf = 0; kf < 4; kf++) {
        int c0 = kf * 16 + 2 * t;
        size_t o00 = headBase + (size_t)rowA * DD + c0;
        size_t o10 = headBase + (size_t)(rowA + 8) * DD + c0;
        qh[kf][0] = *(const uint32_t*)(Qh + o00);
        qh[kf][1] = *(const uint32_t*)(Qh + o10);
        qh[kf][2] = *(const uint32_t*)(Qh + o00 + 8);
        qh[kf][3] = *(const uint32_t*)(Qh + o10 + 8);
        ql[kf][0] = *(const uint32_t*)(Ql + o00);
        ql[kf][1] = *(const uint32_t*)(Ql + o10);
        ql[kf][2] = *(const uint32_t*)(Ql + o00 + 8);
        ql[kf][3] = *(const uint32_t*)(Ql + o10 + 8);
    }

    float oa[8][4];
#pragma unroll
    for (int df = 0; df < 8; df++)
#pragma unroll
        for (int r = 0; r < 4; r++) oa[df][r] = 0.f;
    float m0 = -1e30f, m1 = -1e30f, l0 = 0.f, l1 = 0.f;

    const int lrow = tid >> 3;          // 0..31 (x2 -> 64 rows)
    const int lch  = tid & 7;

    auto load_tile = [&](int jt, int bsel) {
        const uint32_t bufB = smA + (uint32_t)bsel * ABUF;
#pragma unroll
        for (int i = 0; i < 2; i++) {
            int row = lrow + i * 32;
            uint32_t sm_off = (uint32_t)(row * AROW + lch * 16);
            size_t gk = (kRow + jt * 64 + row) * DD + h * HDIM + lch * 8;
            cpa16(bufB + sm_off,          Kh + gk);
            size_t gv = (vRow + row) * TT + jt * 64 + lch * 8;
            cpa16(bufB + APLANE + sm_off, Vth + gv);
        }
        cpa_commit();
    };

    const int nTiles = 2 * qb + 2;
    load_tile(0, 0);

    for (int jt = 0; jt < nTiles; jt++) {
        const uint32_t bufB = smA + (uint32_t)(jt & 1) * ABUF;

        if (jt + 1 < nTiles) {
            load_tile(jt + 1, (jt + 1) & 1);
            cpa_wait<1>();
        } else {
            cpa_wait<0>();
        }
        __syncthreads();

        const bool skip = (jt == 2 * qb + 1) && (wid < 4);
        if (!skip) {
            // ---- S = Q K^T (Q split x2) ----
            float sa[8][4];
#pragma unroll
            for (int nf = 0; nf < 8; nf++)
#pragma unroll
                for (int r = 0; r < 4; r++) sa[nf][r] = 0.f;

#pragma unroll
            for (int kf = 0; kf < 4; kf++) {
                uint32_t kbh[8][2];
#pragma unroll
                for (int p = 0; p < 4; p++) {
                    uint32_t r0, r1, r2, r3;
                    uint32_t ro = (uint32_t)((p * 16 + lm_row) * AROW + (kf * 16 + lm_col) * 2);
                    ldsm4(r0, r1, r2, r3, bufB + ro);
                    kbh[2 * p][0] = r0; kbh[2 * p + 1][0] = r1;
                    kbh[2 * p][1] = r2; kbh[2 * p + 1][1] = r3;
                }
#pragma unroll
                for (int nf = 0; nf < 8; nf++) {
                    mma16816h(sa[nf], qh[kf], kbh[nf]);
                    mma16816h(sa[nf], ql[kf], kbh[nf]);
                }
            }

            if (jt >= 2 * qb) {
#pragma unroll
                for (int nf = 0; nf < 8; nf++) {
                    int col = jt * 64 + nf * 8 + 2 * t;
                    if (col > rowA)         sa[nf][0] = -1e30f;
                    if (col + 1 > rowA)     sa[nf][1] = -1e30f;
                    if (col > rowA + 8)     sa[nf][2] = -1e30f;
                    if (col + 1 > rowA + 8) sa[nf][3] = -1e30f;
                }
            }

            // ---- online softmax ----
            float mx0 = -1e30f, mx1 = -1e30f;
#pragma unroll
            for (int nf = 0; nf < 8; nf++) {
                mx0 = fmaxf(mx0, fmaxf(sa[nf][0], sa[nf][1]));
                mx1 = fmaxf(mx1, fmaxf(sa[nf][2], sa[nf][3]));
            }
            mx0 = fmaxf(mx0, __shfl_xor_sync(0xffffffffu, mx0, 1));
            mx0 = fmaxf(mx0, __shfl_xor_sync(0xffffffffu, mx0, 2));
            mx1 = fmaxf(mx1, __shfl_xor_sync(0xffffffffu, mx1, 1));
            mx1 = fmaxf(mx1, __shfl_xor_sync(0xffffffffu, mx1, 2));
            float mn0 = fmaxf(m0, mx0);
            float mn1 = fmaxf(m1, mx1);
            float al0 = __expf(m0 - mn0);
            float al1 = __expf(m1 - mn1);

            float sum0 = 0.f, sum1 = 0.f;
#pragma unroll
            for (int nf = 0; nf < 8; nf++) {
                sa[nf][0] = __expf(sa[nf][0] - mn0);
                sa[nf][1] = __expf(sa[nf][1] - mn0);
                sa[nf][2] = __expf(sa[nf][2] - mn1);
                sa[nf][3] = __expf(sa[nf][3] - mn1);
                sum0 += sa[nf][0] + sa[nf][1];
                sum1 += sa[nf][2] + sa[nf][3];
            }
            sum0 += __shfl_xor_sync(0xffffffffu, sum0, 1);
            sum0 += __shfl_xor_sync(0xffffffffu, sum0, 2);
            sum1 += __shfl_xor_sync(0xffffffffu, sum1, 1);
            sum1 += __shfl_xor_sync(0xffffffffu, sum1, 2);
            l0 = l0 * al0 + sum0;
            l1 = l1 * al1 + sum1;
            m0 = mn0; m1 = mn1;
#pragma unroll
            for (int df = 0; df < 8; df++) {
                oa[df][0] *= al0; oa[df][1] *= al0;
                oa[df][2] *= al1; oa[df][3] *= al1;
            }

            // ---- O += P V (single-plane P) ----
#pragma unroll
            for (int kk = 0; kk < 4; kk++) {
                uint32_t pha[4];
                pha[0] = pack2h(sa[2 * kk][0],     sa[2 * kk][1]);
                pha[1] = pack2h(sa[2 * kk][2],     sa[2 * kk][3]);
                pha[2] = pack2h(sa[2 * kk + 1][0], sa[2 * kk + 1][1]);
                pha[3] = pack2h(sa[2 * kk + 1][2], sa[2 * kk + 1][3]);

                uint32_t vbh[8][2];
#pragma unroll
                for (int p = 0; p < 4; p++) {
                    uint32_t r0, r1, r2, r3;
                    uint32_t ro = (uint32_t)((p * 16 + lm_row) * AROW + (kk * 16 + lm_col) * 2);
                    ldsm4(r0, r1, r2, r3, bufB + APLANE + ro);
                    vbh[2 * p][0] = r0; vbh[2 * p + 1][0] = r1;
                    vbh[2 * p][1] = r2; vbh[2 * p + 1][1] = r3;
                }
#pragma unroll
                for (int df = 0; df < 8; df++)
                    mma16816h(oa[df], pha, vbh[df]);
            }
        }
        __syncthreads();
    }

    float inv0 = 1.0f / l0;
    float inv1 = 1.0f / l1;
#pragma unroll
    for (int df = 0; df < 8; df++) {
        int dcol = df * 8 + 2 * t;
        size_t off0 = headBase + (size_t)rowA * DD + dcol;
        size_t off1 = headBase + (size_t)(rowA + 8) * DD + dcol;
        uint32_t hi, lo;
        split2h(oa[df][0] * inv0, oa[df][1] * inv0, hi, lo);
        *(uint32_t*)&Yh[off0] = hi;
        *(uint32_t*)&Yl[off0] = lo;
        split2h(oa[df][2] * inv1, oa[df][3] * inv1, hi, lo);
        *(uint32_t*)&Yh[off1] = hi;
        *(uint32_t*)&Yl[off1] = lo;
    }
}

// ---------------------------------------------------------------------------
// Launch: x, Wq, bq, Wk, bk, Wv, bv, Wo, bo (all fp32)
// ---------------------------------------------------------------------------
extern "C" void kernel_launch(void* const* d_in, const int* in_sizes, int n_in,
                              void* d_out, int out_size)
{
    const float* x  = (const float*)d_in[0];
    const float* Wq = (const float*)d_in[1];
    const float* bq = (const float*)d_in[2];
    const float* Wk = (const float*)d_in[3];
    const float* bk = (const float*)d_in[4];
    const float* Wv = (const float*)d_in[5];
    const float* bv = (const float*)d_in[6];
    const float* Wo = (const float*)d_in[7];
    const float* bo = (const float*)d_in[8];
    float* out = (float*)d_out;

    float *qf, *kf, *vf, *xf, *yf;
    f16 *wp;
    cudaGetSymbolAddress((void**)&qf, g_q);
    cudaGetSymbolAddress((void**)&kf, g_k);
    cudaGetSymbolAddress((void**)&vf, g_v);
    cudaGetSymbolAddress((void**)&xf, g_x);
    cudaGetSymbolAddress((void**)&yf, g_y);
    cudaGetSymbolAddress((void**)&wp, g_w);

    const int nX = MROWS * DD;
    const int nW = DD * DD;

    f16* xh  = (f16*)xf;  f16* xl  = xh + nX;
    f16* yh  = (f16*)yf;  f16* yl  = yh + nX;
    f16* qh  = (f16*)qf;  f16* ql  = qh + nX;
    f16* kh  = (f16*)kf;
    f16* vth = (f16*)vf;

    splith_kernel<<<(nX + 255) / 256, 256>>>(x, xh, xl, nX);
    convh4_kernel<<<(4 * nW + 255) / 256, 256>>>(Wq, Wk, Wv, Wo, wp, nW);

    const int gemm_smem = 128 * 132 * 4;   // 67584 B
    cudaFuncSetAttribute(gemm_qkv, cudaFuncAttributeMaxDynamicSharedMemorySize, gemm_smem);
    cudaFuncSetAttribute(gemm_out, cudaFuncAttributeMaxDynamicSharedMemorySize, gemm_smem);

    const int attn_smem = 2 * ABUF;   // 36864 B
    cudaFuncSetAttribute(attn_mma, cudaFuncAttributeMaxDynamicSharedMemorySize, attn_smem);

    gemm_qkv<<<dim3(24, MROWS / 128), 256, gemm_smem>>>(
        xh, xl, wp, bq, bk, bv, qh, ql, kh, vth);

    attn_mma<<<dim3(TT / 128, BB * HH), 256, attn_smem>>>(
        qh, ql, kh, vth, yh, yl);

    gemm_out<<<dim3(DD / 128, MROWS / 128), 256, gemm_smem>>>(
        yh, yl, wp + 3 * nW, bo, out);
}

// round 11
// speedup vs baseline: 4.4163x; 1.1224x over previous
#include <cuda_runtime.h>
#include <cuda_fp16.h>
#include <math.h>
#include <cstdint>

#define BB 4
#define TT 2048
#define DD 1024
#define HH 16
#define HDIM 64
#define MROWS (BB*TT)   // 8192
#define GK 1024

typedef __half f16;

// ---------------------------------------------------------------------------
// Scratch (device globals — no allocation allowed). fp16 planes alias floats.
// ---------------------------------------------------------------------------
__device__ float g_q[MROWS * DD];   // qh | ql (fp16 planes)
__device__ float g_k[MROWS * DD];   // kh (single plane)
__device__ float g_v[MROWS * DD];   // vth (transposed [b][dg][t], single plane)
__device__ float g_x[MROWS * DD];   // xh | xl
__device__ float g_y[MROWS * DD];   // yh (single plane)
__device__ f16   g_w[4 * DD * DD];  // Wq,Wk,Wv,Wo single fp16 planes

__device__ __forceinline__ uint32_t smem_u32(const void* p) {
    return (uint32_t)__cvta_generic_to_shared(p);
}

__device__ __forceinline__ void split1h(float v, f16& h, f16& l) {
    h = __float2half_rn(v);
    l = __float2half_rn(v - __half2float(h));
}

__device__ __forceinline__ uint32_t pack2h(float x, float y) {
    __half2 H = __floats2half2_rn(x, y);
    return *reinterpret_cast<uint32_t*>(&H);
}

__device__ __forceinline__ void mma16816h(float* c, const uint32_t* a, const uint32_t* b) {
    asm volatile(
        "mma.sync.aligned.m16n8k16.row.col.f32.f16.f16.f32 "
        "{%0,%1,%2,%3}, {%4,%5,%6,%7}, {%8,%9}, {%0,%1,%2,%3};\n"
        : "+f"(c[0]), "+f"(c[1]), "+f"(c[2]), "+f"(c[3])
        : "r"(a[0]), "r"(a[1]), "r"(a[2]), "r"(a[3]), "r"(b[0]), "r"(b[1]));
}

__device__ __forceinline__ void ldsm4(uint32_t& r0, uint32_t& r1, uint32_t& r2, uint32_t& r3,
                                      uint32_t addr) {
    asm volatile("ldmatrix.sync.aligned.m8n8.x4.shared.b16 {%0,%1,%2,%3}, [%4];\n"
                 : "=r"(r0), "=r"(r1), "=r"(r2), "=r"(r3) : "r"(addr));
}

__device__ __forceinline__ void cpa16(uint32_t saddr, const void* g) {
    asm volatile("cp.async.ca.shared.global [%0], [%1], 16;\n" :: "r"(saddr), "l"(g));
}
__device__ __forceinline__ void cpa_commit() {
    asm volatile("cp.async.commit_group;\n");
}
template <int N>
__device__ __forceinline__ void cpa_wait() {
    asm volatile("cp.async.wait_group %0;\n" :: "n"(N));
}

// ---------------------------------------------------------------------------
// Splits / converts
// ---------------------------------------------------------------------------
__global__ void splith_kernel(const float* __restrict__ src,
                              f16* __restrict__ hi, f16* __restrict__ lo, int n)
{
    int i = blockIdx.x * blockDim.x + threadIdx.x;
    if (i < n) {
        float v = src[i];
        f16 h = __float2half_rn(v);
        hi[i] = h;
        lo[i] = __float2half_rn(v - __half2float(h));
    }
}

__global__ void convh4_kernel(const float* __restrict__ s0, const float* __restrict__ s1,
                              const float* __restrict__ s2, const float* __restrict__ s3,
                              f16* __restrict__ dst, int nW)
{
    int i = blockIdx.x * blockDim.x + threadIdx.x;
    int seg = i / nW;
    int off = i - seg * nW;
    const float* s = (seg == 0) ? s0 : (seg == 1) ? s1 : (seg == 2) ? s2 : s3;
    dst[i] = __float2half_rn(s[off]);
}

// ---------------------------------------------------------------------------
// GEMM mainloop: C = (Ah [+ Al]) * Wh^T. BK=32, 2-stage cp.async pipeline.
// ---------------------------------------------------------------------------
#define BK 32
#define SSTR 40
#define TILEH (128 * SSTR)

#define GEMM_MAINLOOP_H(AhP, AlP, WhP, DOAL)                                   \
    f16* sAh = smg;                                                            \
    f16* sAl = smg + 2 * TILEH;                                                \
    f16* sBh = smg + 4 * TILEH;                                                \
    const bool doAl = (DOAL);                                                  \
    const int lr = tid >> 1;                                                   \
    const int lc = (tid & 1) * 16;                                             \
    const f16* gAh = (AhP) + (size_t)(rowBase + lr) * GK + lc;                 \
    const f16* gAl = (AlP) + (size_t)(rowBase + lr) * GK + lc;                 \
    const f16* gWh = (WhP) + (size_t)(colBase + lr) * GK + lc;                 \
    const uint32_t soff = (uint32_t)((lr * SSTR + lc) * 2);                    \
    const uint32_t sAhB = smem_u32(sAh);                                       \
    const uint32_t sAlB = smem_u32(sAl);                                       \
    const uint32_t sBhB = smem_u32(sBh);                                       \
    const int lm_row = (lane & 15);                                            \
    const int lm_col = ((lane >> 4) << 3);                                     \
    float acc[4][4][4];                                                        \
    _Pragma("unroll")                                                          \
    for (int mf = 0; mf < 4; mf++)                                             \
        _Pragma("unroll")                                                      \
        for (int nf = 0; nf < 4; nf++)                                         \
            _Pragma("unroll")                                                  \
            for (int r = 0; r < 4; r++) acc[mf][nf][r] = 0.f;                  \
    const int nIter = GK / BK;                                                 \
    {                                                                          \
        cpa16(sAhB + soff,      gAh);  cpa16(sAhB + soff + 16, gAh + 8);       \
        if (doAl) { cpa16(sAlB + soff, gAl); cpa16(sAlB + soff + 16, gAl + 8); } \
        cpa16(sBhB + soff,      gWh);  cpa16(sBhB + soff + 16, gWh + 8);       \
        cpa_commit();                                                          \
    }                                                                          \
    for (int iter = 0; iter < nIter; iter++) {                                 \
        const int buf = iter & 1;                                              \
        if (iter + 1 < nIter) {                                                \
            const uint32_t sb = (uint32_t)(((iter + 1) & 1) * TILEH * 2);      \
            const int k0 = (iter + 1) * BK;                                    \
            cpa16(sAhB + sb + soff,      gAh + k0);                            \
            cpa16(sAhB + sb + soff + 16, gAh + k0 + 8);                        \
            if (doAl) {                                                        \
                cpa16(sAlB + sb + soff,      gAl + k0);                        \
                cpa16(sAlB + sb + soff + 16, gAl + k0 + 8);                    \
            }                                                                  \
            cpa16(sBhB + sb + soff,      gWh + k0);                            \
            cpa16(sBhB + sb + soff + 16, gWh + k0 + 8);                        \
            cpa_commit();                                                      \
            cpa_wait<1>();                                                     \
        } else {                                                               \
            cpa_wait<0>();                                                     \
        }                                                                      \
        __syncthreads();                                                       \
        _Pragma("unroll")                                                      \
        for (int ks = 0; ks < BK; ks += 16) {                                  \
            uint32_t ah[4][4], al[4][4];                                       \
            _Pragma("unroll")                                                  \
            for (int mf = 0; mf < 4; mf++) {                                   \
                int roff = (warpM * 64 + mf * 16 + lm_row) * SSTR + ks + lm_col; \
                ldsm4(ah[mf][0], ah[mf][1], ah[mf][2], ah[mf][3],              \
                      sAhB + (uint32_t)((buf * TILEH + roff) * 2));            \
                if (doAl)                                                      \
                    ldsm4(al[mf][0], al[mf][1], al[mf][2], al[mf][3],          \
                          sAlB + (uint32_t)((buf * TILEH + roff) * 2));        \
            }                                                                  \
            uint32_t bh[4][2];                                                 \
            _Pragma("unroll")                                                  \
            for (int p = 0; p < 2; p++) {                                      \
                int roff = (warpN * 32 + p * 16 + lm_row) * SSTR + ks + lm_col; \
                uint32_t r0, r1, r2, r3;                                       \
                ldsm4(r0, r1, r2, r3, sBhB + (uint32_t)((buf * TILEH + roff) * 2)); \
                bh[2 * p][0] = r0; bh[2 * p + 1][0] = r1;                      \
                bh[2 * p][1] = r2; bh[2 * p + 1][1] = r3;                      \
            }                                                                  \
            _Pragma("unroll")                                                  \
            for (int mf = 0; mf < 4; mf++)                                     \
                _Pragma("unroll")                                              \
                for (int nf = 0; nf < 4; nf++) {                               \
                    mma16816h(acc[mf][nf], ah[mf], bh[nf]);                    \
                    if (doAl) mma16816h(acc[mf][nf], al[mf], bh[nf]);          \
                }                                                              \
        }                                                                      \
        __syncthreads();                                                       \
    }

// ---------------------------------------------------------------------------
// Fused QKV GEMM + bias + RoPE + fp16 outputs (+ V transposed).
// Grid (24, 64): bx 0-7 -> q (x split x2, log2e folded into scale),
// 8-15 -> k (x split x2), 16-23 -> v (x single fp16, transposed store).
// ---------------------------------------------------------------------------
__global__ void __launch_bounds__(256) gemm_qkv(
    const f16* __restrict__ Ah, const f16* __restrict__ Al,
    const f16* __restrict__ Wh,
    const float* __restrict__ bq, const float* __restrict__ bk,
    const float* __restrict__ bv,
    f16* __restrict__ qh_, f16* __restrict__ ql_,
    f16* __restrict__ kh_, f16* __restrict__ vth_)
{
    extern __shared__ f16 smg[];
    const int tid  = threadIdx.x;
    const int lane = tid & 31;
    const int wid  = tid >> 5;
    const int warpM = wid >> 2;
    const int warpN = wid & 3;
    const int bx = blockIdx.x;
    const int rowBase = blockIdx.y * 128;
    const int colBase = bx * 128;

    GEMM_MAINLOOP_H(Ah, Al, Wh, bx < 16)

    // ---- epilogue: stage to smem fp32 with bias ----
    float* Csm = (float*)smg;   // [128][132]
    const float* biasp = (bx < 8) ? (bq + bx * 128)
                       : (bx < 16) ? (bk + (bx - 8) * 128)
                                   : (bv + (bx - 16) * 128);
#pragma unroll
    for (int mf = 0; mf < 4; mf++)
#pragma unroll
        for (int nf = 0; nf < 4; nf++) {
            int r0 = warpM * 64 + mf * 16 + (lane >> 2);
            int c0 = warpN * 32 + nf * 8 + (lane & 3) * 2;
            Csm[r0 * 132 + c0]           = acc[mf][nf][0] + biasp[c0];
            Csm[r0 * 132 + c0 + 1]       = acc[mf][nf][1] + biasp[c0 + 1];
            Csm[(r0 + 8) * 132 + c0]     = acc[mf][nf][2] + biasp[c0];
            Csm[(r0 + 8) * 132 + c0 + 1] = acc[mf][nf][3] + biasp[c0 + 1];
        }
    __syncthreads();

    const int bB = rowBase >> 11;       // batch
    const int t0 = rowBase & 2047;      // time offset within batch

    if (bx < 8) {
        // q: RoPE + scale (0.125 * log2e, softmax runs in exp2 domain) + split x2
        const int colB = bx * 128;
        const float scale = 0.125f * 1.4426950408889634f;
        const float lnc = logf(10000.f) / 32.f;
        for (int idx = tid; idx < 128 * 64; idx += 256) {
            int r  = idx >> 6;
            int pp = idx & 63;
            int hl = pp >> 5, dd = pp & 31;
            int c1 = hl * 64 + dd, c2 = c1 + 32;
            float x1 = Csm[r * 132 + c1];
            float x2 = Csm[r * 132 + c2];
            float theta = expf(-(float)dd * lnc);
            float ang = (float)(t0 + r + 1) * theta;
            float s, c;
            sincosf(ang, &s, &c);
            float y1 = (x1 * c - x2 * s) * scale;
            float y2 = (x2 * c + x1 * s) * scale;
            size_t gr = (size_t)(rowBase + r) * DD + colB;
            f16 hh, ll;
            split1h(y1, hh, ll); qh_[gr + c1] = hh; ql_[gr + c1] = ll;
            split1h(y2, hh, ll); qh_[gr + c2] = hh; ql_[gr + c2] = ll;
        }
    } else if (bx < 16) {
        // k: RoPE + single fp16
        const int colB = (bx - 8) * 128;
        const float lnc = logf(10000.f) / 32.f;
        for (int idx = tid; idx < 128 * 64; idx += 256) {
            int r  = idx >> 6;
            int pp = idx & 63;
            int hl = pp >> 5, dd = pp & 31;
            int c1 = hl * 64 + dd, c2 = c1 + 32;
            float x1 = Csm[r * 132 + c1];
            float x2 = Csm[r * 132 + c2];
            float theta = expf(-(float)dd * lnc);
            float ang = (float)(t0 + r + 1) * theta;
            float s, c;
            sincosf(ang, &s, &c);
            size_t gr = (size_t)(rowBase + r) * DD + colB;
            kh_[gr + c1] = __float2half_rn(x1 * c - x2 * s);
            kh_[gr + c2] = __float2half_rn(x2 * c + x1 * s);
        }
    } else {
        // v: single fp16, transposed store vt[b][dg][t]
        const int cb = bx - 16;
#pragma unroll
        for (int pass = 0; pass < 4; pass++) {
            int c  = pass * 32 + (wid << 2) + (lane >> 3);
            int rb = (lane & 7) * 16;
            __align__(16) f16 bh2[16];
#pragma unroll
            for (int i = 0; i < 16; i++)
                bh2[i] = __float2half_rn(Csm[(rb + i) * 132 + c]);
            size_t vb = ((size_t)bB * DD + cb * 128 + c) * TT + t0 + rb;
            *(uint4*)(vth_ + vb)     = *(uint4*)&bh2[0];
            *(uint4*)(vth_ + vb + 8) = *(uint4*)&bh2[8];
        }
    }
}

// ---------------------------------------------------------------------------
// Output-projection GEMM: C = Yh Wo^T + bias, fp32 out (single-plane A).
// ---------------------------------------------------------------------------
__global__ void __launch_bounds__(256) gemm_out(
    const f16* __restrict__ Ah, const f16* __restrict__ Wh,
    const float* __restrict__ bias, float* __restrict__ C)
{
    extern __shared__ f16 smg[];
    const int tid  = threadIdx.x;
    const int lane = tid & 31;
    const int wid  = tid >> 5;
    const int warpM = wid >> 2;
    const int warpN = wid & 3;
    const int rowBase = blockIdx.y * 128;
    const int colBase = blockIdx.x * 128;

    GEMM_MAINLOOP_H(Ah, Ah, Wh, false)

#pragma unroll
    for (int mf = 0; mf < 4; mf++)
#pragma unroll
        for (int nf = 0; nf < 4; nf++) {
            int m0 = rowBase + warpM * 64 + mf * 16 + (lane >> 2);
            int n0 = colBase + warpN * 32 + nf * 8 + (lane & 3) * 2;
            float b0 = bias[n0], b1 = bias[n0 + 1];
            float2 o0 = make_float2(acc[mf][nf][0] + b0, acc[mf][nf][1] + b1);
            float2 o1 = make_float2(acc[mf][nf][2] + b0, acc[mf][nf][3] + b1);
            *(float2*)&C[(size_t)m0 * DD + n0]       = o0;
            *(float2*)&C[(size_t)(m0 + 8) * DD + n0] = o1;
        }
}

// ---------------------------------------------------------------------------
// Flash attention: 128 threads / 64 Q-rows per CTA (4 CTAs/SM for overlap).
// S = (Qh+Ql) K^T (2 mmas, log2 domain), softmax via exp2f, P·V 1 mma.
// K/V single fp16, double-buffered. Buffer (18432 B): Kh | Vh, 64 x 144 B.
// ---------------------------------------------------------------------------
#define AROW 144
#define APLANE (64 * AROW)
#define ABUF (2 * APLANE)

__global__ void __launch_bounds__(128, 4) attn_mma(
    const f16* __restrict__ Qh, const f16* __restrict__ Ql,
    const f16* __restrict__ Kh, const f16* __restrict__ Vth,
    f16* __restrict__ Yh)
{
    extern __shared__ f16 asmem[];
    const uint32_t smA = smem_u32(asmem);

    const int tid  = threadIdx.x;
    const int lane = tid & 31;
    const int wid  = tid >> 5;           // 0..3
    const int g    = lane >> 2;
    const int t    = lane & 3;
    const int lm_row = lane & 15;
    const int lm_col = (lane >> 4) << 3;

    const int qb = (gridDim.x - 1) - blockIdx.x;   // 0..31, heavy first
    const int bh = blockIdx.y;
    const int b  = bh >> 4;
    const int h  = bh & 15;

    const size_t headBase = (size_t)b * TT * DD + h * HDIM;
    const size_t kRow = (size_t)b * TT;
    const size_t vRow = (size_t)b * DD + h * HDIM;
    const int rowA = qb * 64 + wid * 16 + g;

    // ---- Q fragments (pre-scaled by 0.125*log2e) ----
    uint32_t qh[4][4], ql[4][4];
#pragma unroll
    for (int kf = 0; kf < 4; kf++) {
        int c0 = kf * 16 + 2 * t;
        size_t o00 = headBase + (size_t)rowA * DD + c0;
        size_t o10 = headBase + (size_t)(rowA + 8) * DD + c0;
        qh[kf][0] = *(const uint32_t*)(Qh + o00);
        qh[kf][1] = *(const uint32_t*)(Qh + o10);
        qh[kf][2] = *(const uint32_t*)(Qh + o00 + 8);
        qh[kf][3] = *(const uint32_t*)(Qh + o10 + 8);
        ql[kf][0] = *(const uint32_t*)(Ql + o00);
        ql[kf][1] = *(const uint32_t*)(Ql + o10);
        ql[kf][2] = *(const uint32_t*)(Ql + o00 + 8);
        ql[kf][3] = *(const uint32_t*)(Ql + o10 + 8);
    }

    float oa[8][4];
#pragma unroll
    for (int df = 0; df < 8; df++)
#pragma unroll
        for (int r = 0; r < 4; r++) oa[df][r] = 0.f;
    float m0 = -1e30f, m1 = -1e30f, l0 = 0.f, l1 = 0.f;

    const int lrow = tid >> 3;          // 0..15 (x4 -> 64 rows)
    const int lch  = tid & 7;

    auto load_tile = [&](int jt, int bsel) {
        const uint32_t bufB = smA + (uint32_t)bsel * ABUF;
#pragma unroll
        for (int i = 0; i < 4; i++) {
            int row = lrow + i * 16;
            uint32_t sm_off = (uint32_t)(row * AROW + lch * 16);
            size_t gk = (kRow + jt * 64 + row) * DD + h * HDIM + lch * 8;
            cpa16(bufB + sm_off,          Kh + gk);
            size_t gv = (vRow + row) * TT + jt * 64 + lch * 8;
            cpa16(bufB + APLANE + sm_off, Vth + gv);
        }
        cpa_commit();
    };

    const int nTiles = qb + 1;
    load_tile(0, 0);

    for (int jt = 0; jt < nTiles; jt++) {
        const uint32_t bufB = smA + (uint32_t)(jt & 1) * ABUF;

        if (jt + 1 < nTiles) {
            load_tile(jt + 1, (jt + 1) & 1);
            cpa_wait<1>();
        } else {
            cpa_wait<0>();
        }
        __syncthreads();

        // ---- S = Q K^T (Q split x2, log2 domain) ----
        float sa[8][4];
#pragma unroll
        for (int nf = 0; nf < 8; nf++)
#pragma unroll
            for (int r = 0; r < 4; r++) sa[nf][r] = 0.f;

#pragma unroll
        for (int kf = 0; kf < 4; kf++) {
            uint32_t kbh[8][2];
#pragma unroll
            for (int p = 0; p < 4; p++) {
                uint32_t r0, r1, r2, r3;
                uint32_t ro = (uint32_t)((p * 16 + lm_row) * AROW + (kf * 16 + lm_col) * 2);
                ldsm4(r0, r1, r2, r3, bufB + ro);
                kbh[2 * p][0] = r0; kbh[2 * p + 1][0] = r1;
                kbh[2 * p][1] = r2; kbh[2 * p + 1][1] = r3;
            }
#pragma unroll
            for (int nf = 0; nf < 8; nf++) {
                mma16816h(sa[nf], qh[kf], kbh[nf]);
                mma16816h(sa[nf], ql[kf], kbh[nf]);
            }
        }

        // causal mask on the diagonal tile
        if (jt == qb) {
#pragma unroll
            for (int nf = 0; nf < 8; nf++) {
                int col = jt * 64 + nf * 8 + 2 * t;
                if (col > rowA)         sa[nf][0] = -1e30f;
                if (col + 1 > rowA)     sa[nf][1] = -1e30f;
                if (col > rowA + 8)     sa[nf][2] = -1e30f;
                if (col + 1 > rowA + 8) sa[nf][3] = -1e30f;
            }
        }

        // ---- online softmax (exp2 domain) ----
        float mx0 = -1e30f, mx1 = -1e30f;
#pragma unroll
        for (int nf = 0; nf < 8; nf++) {
            mx0 = fmaxf(mx0, fmaxf(sa[nf][0], sa[nf][1]));
            mx1 = fmaxf(mx1, fmaxf(sa[nf][2], sa[nf][3]));
        }
        mx0 = fmaxf(mx0, __shfl_xor_sync(0xffffffffu, mx0, 1));
        mx0 = fmaxf(mx0, __shfl_xor_sync(0xffffffffu, mx0, 2));
        mx1 = fmaxf(mx1, __shfl_xor_sync(0xffffffffu, mx1, 1));
        mx1 = fmaxf(mx1, __shfl_xor_sync(0xffffffffu, mx1, 2));
        float mn0 = fmaxf(m0, mx0);
        float mn1 = fmaxf(m1, mx1);
        float al0 = exp2f(m0 - mn0);
        float al1 = exp2f(m1 - mn1);

        float sum0 = 0.f, sum1 = 0.f;
#pragma unroll
        for (int nf = 0; nf < 8; nf++) {
            sa[nf][0] = exp2f(sa[nf][0] - mn0);
            sa[nf][1] = exp2f(sa[nf][1] - mn0);
            sa[nf][2] = exp2f(sa[nf][2] - mn1);
            sa[nf][3] = exp2f(sa[nf][3] - mn1);
            sum0 += sa[nf][0] + sa[nf][1];
            sum1 += sa[nf][2] + sa[nf][3];
        }
        sum0 += __shfl_xor_sync(0xffffffffu, sum0, 1);
        sum0 += __shfl_xor_sync(0xffffffffu, sum0, 2);
        sum1 += __shfl_xor_sync(0xffffffffu, sum1, 1);
        sum1 += __shfl_xor_sync(0xffffffffu, sum1, 2);
        l0 = l0 * al0 + sum0;
        l1 = l1 * al1 + sum1;
        m0 = mn0; m1 = mn1;
#pragma unroll
        for (int df = 0; df < 8; df++) {
            oa[df][0] *= al0; oa[df][1] *= al0;
            oa[df][2] *= al1; oa[df][3] *= al1;
        }

        // ---- O += P V (single-plane P) ----
#pragma unroll
        for (int kk = 0; kk < 4; kk++) {
            uint32_t pha[4];
            pha[0] = pack2h(sa[2 * kk][0],     sa[2 * kk][1]);
            pha[1] = pack2h(sa[2 * kk][2],     sa[2 * kk][3]);
            pha[2] = pack2h(sa[2 * kk + 1][0], sa[2 * kk + 1][1]);
            pha[3] = pack2h(sa[2 * kk + 1][2], sa[2 * kk + 1][3]);

            uint32_t vbh[8][2];
#pragma unroll
            for (int p = 0; p < 4; p++) {
                uint32_t r0, r1, r2, r3;
                uint32_t ro = (uint32_t)((p * 16 + lm_row) * AROW + (kk * 16 + lm_col) * 2);
                ldsm4(r0, r1, r2, r3, bufB + APLANE + ro);
                vbh[2 * p][0] = r0; vbh[2 * p + 1][0] = r1;
                vbh[2 * p][1] = r2; vbh[2 * p + 1][1] = r3;
            }
#pragma unroll
            for (int df = 0; df < 8; df++)
                mma16816h(oa[df], pha, vbh[df]);
        }
        __syncthreads();
    }

    // ---- epilogue: normalize + single fp16 plane ----
    float inv0 = 1.0f / l0;
    float inv1 = 1.0f / l1;
#pragma unroll
    for (int df = 0; df < 8; df++) {
        int dcol = df * 8 + 2 * t;
        size_t off0 = headBase + (size_t)rowA * DD + dcol;
        size_t off1 = headBase + (size_t)(rowA + 8) * DD + dcol;
        *(uint32_t*)&Yh[off0] = pack2h(oa[df][0] * inv0, oa[df][1] * inv0);
        *(uint32_t*)&Yh[off1] = pack2h(oa[df][2] * inv1, oa[df][3] * inv1);
    }
}

// ---------------------------------------------------------------------------
// Launch: x, Wq, bq, Wk, bk, Wv, bv, Wo, bo (all fp32)
// ---------------------------------------------------------------------------
extern "C" void kernel_launch(void* const* d_in, const int* in_sizes, int n_in,
                              void* d_out, int out_size)
{
    const float* x  = (const float*)d_in[0];
    const float* Wq = (const float*)d_in[1];
    const float* bq = (const float*)d_in[2];
    const float* Wk = (const float*)d_in[3];
    const float* bk = (const float*)d_in[4];
    const float* Wv = (const float*)d_in[5];
    const float* bv = (const float*)d_in[6];
    const float* Wo = (const float*)d_in[7];
    const float* bo = (const float*)d_in[8];
    float* out = (float*)d_out;

    float *qf, *kf, *vf, *xf, *yf;
    f16 *wp;
    cudaGetSymbolAddress((void**)&qf, g_q);
    cudaGetSymbolAddress((void**)&kf, g_k);
    cudaGetSymbolAddress((void**)&vf, g_v);
    cudaGetSymbolAddress((void**)&xf, g_x);
    cudaGetSymbolAddress((void**)&yf, g_y);
    cudaGetSymbolAddress((void**)&wp, g_w);

    const int nX = MROWS * DD;
    const int nW = DD * DD;

    f16* xh  = (f16*)xf;  f16* xl  = xh + nX;
    f16* yh  = (f16*)yf;
    f16* qh  = (f16*)qf;  f16* ql  = qh + nX;
    f16* kh  = (f16*)kf;
    f16* vth = (f16*)vf;

    splith_kernel<<<(nX + 255) / 256, 256>>>(x, xh, xl, nX);
    convh4_kernel<<<(4 * nW + 255) / 256, 256>>>(Wq, Wk, Wv, Wo, wp, nW);

    const int gemm_smem = 128 * 132 * 4;   // 67584 B
    cudaFuncSetAttribute(gemm_qkv, cudaFuncAttributeMaxDynamicSharedMemorySize, gemm_smem);
    cudaFuncSetAttribute(gemm_out, cudaFuncAttributeMaxDynamicSharedMemorySize, gemm_smem);

    const int attn_smem = 2 * ABUF;   // 36864 B
    cudaFuncSetAttribute(attn_mma, cudaFuncAttributeMaxDynamicSharedMemorySize, attn_smem);

    gemm_qkv<<<dim3(24, MROWS / 128), 256, gemm_smem>>>(
        xh, xl, wp, bq, bk, bv, qh, ql, kh, vth);

    attn_mma<<<dim3(TT / 64, BB * HH), 128, attn_smem>>>(
        qh, ql, kh, vth, yh);

    gemm_out<<<dim3(DD / 128, MROWS / 128), 256, gemm_smem>>>(
        yh, wp + 3 * nW, bo, out);
}

// round 12
// speedup vs baseline: 4.4423x; 1.0059x over previous
#include <cuda_runtime.h>
#include <cuda_fp16.h>
#include <math.h>
#include <cstdint>

#define BB 4
#define TT 2048
#define DD 1024
#define HH 16
#define HDIM 64
#define MROWS (BB*TT)   // 8192
#define GK 1024

typedef __half f16;

// ---------------------------------------------------------------------------
// Scratch (device globals — no allocation allowed). fp16 planes alias floats.
// ---------------------------------------------------------------------------
__device__ float g_q[MROWS * DD];   // qh | ql (fp16 planes)
__device__ float g_k[MROWS * DD];   // kh (single plane)
__device__ float g_v[MROWS * DD];   // vth (transposed [b][dg][t], single plane)
__device__ float g_x[MROWS * DD];   // xh | xl
__device__ float g_y[MROWS * DD];   // yh (single plane)
__device__ f16   g_w[4 * DD * DD];  // Wq,Wk,Wv,Wo single fp16 planes

__device__ __forceinline__ uint32_t smem_u32(const void* p) {
    return (uint32_t)__cvta_generic_to_shared(p);
}

__device__ __forceinline__ void split1h(float v, f16& h, f16& l) {
    h = __float2half_rn(v);
    l = __float2half_rn(v - __half2float(h));
}

__device__ __forceinline__ uint32_t pack2h(float x, float y) {
    __half2 H = __floats2half2_rn(x, y);
    return *reinterpret_cast<uint32_t*>(&H);
}

__device__ __forceinline__ void mma16816h(float* c, const uint32_t* a, const uint32_t* b) {
    asm volatile(
        "mma.sync.aligned.m16n8k16.row.col.f32.f16.f16.f32 "
        "{%0,%1,%2,%3}, {%4,%5,%6,%7}, {%8,%9}, {%0,%1,%2,%3};\n"
        : "+f"(c[0]), "+f"(c[1]), "+f"(c[2]), "+f"(c[3])
        : "r"(a[0]), "r"(a[1]), "r"(a[2]), "r"(a[3]), "r"(b[0]), "r"(b[1]));
}

__device__ __forceinline__ void ldsm4(uint32_t& r0, uint32_t& r1, uint32_t& r2, uint32_t& r3,
                                      uint32_t addr) {
    asm volatile("ldmatrix.sync.aligned.m8n8.x4.shared.b16 {%0,%1,%2,%3}, [%4];\n"
                 : "=r"(r0), "=r"(r1), "=r"(r2), "=r"(r3) : "r"(addr));
}

__device__ __forceinline__ void cpa16(uint32_t saddr, const void* g) {
    asm volatile("cp.async.ca.shared.global [%0], [%1], 16;\n" :: "r"(saddr), "l"(g));
}
__device__ __forceinline__ void cpa_commit() {
    asm volatile("cp.async.commit_group;\n");
}
template <int N>
__device__ __forceinline__ void cpa_wait() {
    asm volatile("cp.async.wait_group %0;\n" :: "n"(N));
}

// ---------------------------------------------------------------------------
// Splits / converts
// ---------------------------------------------------------------------------
__global__ void splith_kernel(const float* __restrict__ src,
                              f16* __restrict__ hi, f16* __restrict__ lo, int n)
{
    int i = blockIdx.x * blockDim.x + threadIdx.x;
    if (i < n) {
        float v = src[i];
        f16 h = __float2half_rn(v);
        hi[i] = h;
        lo[i] = __float2half_rn(v - __half2float(h));
    }
}

__global__ void convh4_kernel(const float* __restrict__ s0, const float* __restrict__ s1,
                              const float* __restrict__ s2, const float* __restrict__ s3,
                              f16* __restrict__ dst, int nW)
{
    int i = blockIdx.x * blockDim.x + threadIdx.x;
    int seg = i / nW;
    int off = i - seg * nW;
    const float* s = (seg == 0) ? s0 : (seg == 1) ? s1 : (seg == 2) ? s2 : s3;
    dst[i] = __float2half_rn(s[off]);
}

// ---------------------------------------------------------------------------
// GEMM mainloop: C = (Ah [+ Al]) * Wh^T. BK=32, 3-stage cp.async pipeline,
// ONE __syncthreads per iteration.
// Plane layout (halves): sAh[3 stages] | sAl[3] | sBh[3], stage = 128*SSTR.
// ---------------------------------------------------------------------------
#define BK 32
#define SSTR 40
#define TILEH (128 * SSTR)

#define GEMM_MAINLOOP_H(AhP, AlP, WhP, DOAL)                                   \
    const bool doAl = (DOAL);                                                  \
    const int lr = tid >> 1;                                                   \
    const int lc = (tid & 1) * 16;                                             \
    const f16* gAh = (AhP) + (size_t)(rowBase + lr) * GK + lc;                 \
    const f16* gAl = (AlP) + (size_t)(rowBase + lr) * GK + lc;                 \
    const f16* gWh = (WhP) + (size_t)(colBase + lr) * GK + lc;                 \
    const uint32_t soff = (uint32_t)((lr * SSTR + lc) * 2);                    \
    const uint32_t sAhB = smem_u32(smg);                                       \
    const uint32_t sAlB = sAhB + 3 * TILEH * 2;                                \
    const uint32_t sBhB = sAhB + 6 * TILEH * 2;                                \
    const int lm_row = (lane & 15);                                            \
    const int lm_col = ((lane >> 4) << 3);                                     \
    float acc[4][4][4];                                                        \
    _Pragma("unroll")                                                          \
    for (int mf = 0; mf < 4; mf++)                                             \
        _Pragma("unroll")                                                      \
        for (int nf = 0; nf < 4; nf++)                                         \
            _Pragma("unroll")                                                  \
            for (int r = 0; r < 4; r++) acc[mf][nf][r] = 0.f;                  \
    const int nIter = GK / BK;                                                 \
    auto load_stage = [&](int s, int k0) {                                     \
        const uint32_t sb = (uint32_t)(s * (TILEH * 2));                       \
        cpa16(sAhB + sb + soff,      gAh + k0);                                \
        cpa16(sAhB + sb + soff + 16, gAh + k0 + 8);                            \
        if (doAl) {                                                            \
            cpa16(sAlB + sb + soff,      gAl + k0);                            \
            cpa16(sAlB + sb + soff + 16, gAl + k0 + 8);                        \
        }                                                                      \
        cpa16(sBhB + sb + soff,      gWh + k0);                                \
        cpa16(sBhB + sb + soff + 16, gWh + k0 + 8);                            \
        cpa_commit();                                                          \
    };                                                                         \
    load_stage(0, 0);                                                          \
    load_stage(1, BK);                                                         \
    int cur = 0;                                                               \
    for (int iter = 0; iter < nIter; iter++) {                                 \
        if (iter + 1 < nIter) cpa_wait<1>(); else cpa_wait<0>();               \
        __syncthreads();                                                       \
        if (iter + 2 < nIter) {                                                \
            int pf = cur + 2; if (pf >= 3) pf -= 3;                            \
            load_stage(pf, (iter + 2) * BK);                                   \
        }                                                                      \
        _Pragma("unroll")                                                      \
        for (int ks = 0; ks < BK; ks += 16) {                                  \
            uint32_t ah[4][4], al[4][4];                                       \
            _Pragma("unroll")                                                  \
            for (int mf = 0; mf < 4; mf++) {                                   \
                int roff = (warpM * 64 + mf * 16 + lm_row) * SSTR + ks + lm_col; \
                ldsm4(ah[mf][0], ah[mf][1], ah[mf][2], ah[mf][3],              \
                      sAhB + (uint32_t)((cur * TILEH + roff) * 2));            \
                if (doAl)                                                      \
                    ldsm4(al[mf][0], al[mf][1], al[mf][2], al[mf][3],          \
                          sAlB + (uint32_t)((cur * TILEH + roff) * 2));        \
            }                                                                  \
            uint32_t bh[4][2];                                                 \
            _Pragma("unroll")                                                  \
            for (int p = 0; p < 2; p++) {                                      \
                int roff = (warpN * 32 + p * 16 + lm_row) * SSTR + ks + lm_col; \
                uint32_t r0, r1, r2, r3;                                       \
                ldsm4(r0, r1, r2, r3, sBhB + (uint32_t)((cur * TILEH + roff) * 2)); \
                bh[2 * p][0] = r0; bh[2 * p + 1][0] = r1;                      \
                bh[2 * p][1] = r2; bh[2 * p + 1][1] = r3;                      \
            }                                                                  \
            _Pragma("unroll")                                                  \
            for (int mf = 0; mf < 4; mf++)                                     \
                _Pragma("unroll")                                              \
                for (int nf = 0; nf < 4; nf++) {                               \
                    mma16816h(acc[mf][nf], ah[mf], bh[nf]);                    \
                    if (doAl) mma16816h(acc[mf][nf], al[mf], bh[nf]);          \
                }                                                              \
        }                                                                      \
        if (++cur >= 3) cur = 0;                                               \
    }

// ---------------------------------------------------------------------------
// Fused QKV GEMM + bias + RoPE + fp16 outputs (+ V transposed).
// Grid (24, 64): bx 0-7 -> q (x split x2, log2e folded into scale),
// 8-15 -> k (x single), 16-23 -> v (x single, transposed store).
// ---------------------------------------------------------------------------
__global__ void __launch_bounds__(256) gemm_qkv(
    const f16* __restrict__ Ah, const f16* __restrict__ Al,
    const f16* __restrict__ Wh,
    const float* __restrict__ bq, const float* __restrict__ bk,
    const float* __restrict__ bv,
    f16* __restrict__ qh_, f16* __restrict__ ql_,
    f16* __restrict__ kh_, f16* __restrict__ vth_)
{
    extern __shared__ f16 smg[];
    const int tid  = threadIdx.x;
    const int lane = tid & 31;
    const int wid  = tid >> 5;
    const int warpM = wid >> 2;
    const int warpN = wid & 3;
    const int bx = blockIdx.x;
    const int rowBase = blockIdx.y * 128;
    const int colBase = bx * 128;

    GEMM_MAINLOOP_H(Ah, Al, Wh, bx < 8)

    // all warps done with smem planes before Csm overwrite
    __syncthreads();

    // ---- epilogue: stage to smem fp32 with bias ----
    float* Csm = (float*)smg;   // [128][132]
    const float* biasp = (bx < 8) ? (bq + bx * 128)
                       : (bx < 16) ? (bk + (bx - 8) * 128)
                                   : (bv + (bx - 16) * 128);
#pragma unroll
    for (int mf = 0; mf < 4; mf++)
#pragma unroll
        for (int nf = 0; nf < 4; nf++) {
            int r0 = warpM * 64 + mf * 16 + (lane >> 2);
            int c0 = warpN * 32 + nf * 8 + (lane & 3) * 2;
            Csm[r0 * 132 + c0]           = acc[mf][nf][0] + biasp[c0];
            Csm[r0 * 132 + c0 + 1]       = acc[mf][nf][1] + biasp[c0 + 1];
            Csm[(r0 + 8) * 132 + c0]     = acc[mf][nf][2] + biasp[c0];
            Csm[(r0 + 8) * 132 + c0 + 1] = acc[mf][nf][3] + biasp[c0 + 1];
        }
    __syncthreads();

    const int bB = rowBase >> 11;       // batch
    const int t0 = rowBase & 2047;      // time offset within batch

    if (bx < 8) {
        // q: RoPE + scale (0.125 * log2e, softmax runs in exp2 domain) + split x2
        const int colB = bx * 128;
        const float scale = 0.125f * 1.4426950408889634f;
        const float lnc = logf(10000.f) / 32.f;
        for (int idx = tid; idx < 128 * 64; idx += 256) {
            int r  = idx >> 6;
            int pp = idx & 63;
            int hl = pp >> 5, dd = pp & 31;
            int c1 = hl * 64 + dd, c2 = c1 + 32;
            float x1 = Csm[r * 132 + c1];
            float x2 = Csm[r * 132 + c2];
            float theta = expf(-(float)dd * lnc);
            float ang = (float)(t0 + r + 1) * theta;
            float s, c;
            sincosf(ang, &s, &c);
            float y1 = (x1 * c - x2 * s) * scale;
            float y2 = (x2 * c + x1 * s) * scale;
            size_t gr = (size_t)(rowBase + r) * DD + colB;
            f16 hh, ll;
            split1h(y1, hh, ll); qh_[gr + c1] = hh; ql_[gr + c1] = ll;
            split1h(y2, hh, ll); qh_[gr + c2] = hh; ql_[gr + c2] = ll;
        }
    } else if (bx < 16) {
        // k: RoPE + single fp16
        const int colB = (bx - 8) * 128;
        const float lnc = logf(10000.f) / 32.f;
        for (int idx = tid; idx < 128 * 64; idx += 256) {
            int r  = idx >> 6;
            int pp = idx & 63;
            int hl = pp >> 5, dd = pp & 31;
            int c1 = hl * 64 + dd, c2 = c1 + 32;
            float x1 = Csm[r * 132 + c1];
            float x2 = Csm[r * 132 + c2];
            float theta = expf(-(float)dd * lnc);
            float ang = (float)(t0 + r + 1) * theta;
            float s, c;
            sincosf(ang, &s, &c);
            size_t gr = (size_t)(rowBase + r) * DD + colB;
            kh_[gr + c1] = __float2half_rn(x1 * c - x2 * s);
            kh_[gr + c2] = __float2half_rn(x2 * c + x1 * s);
        }
    } else {
        // v: single fp16, transposed store vt[b][dg][t]
        const int cb = bx - 16;
#pragma unroll
        for (int pass = 0; pass < 4; pass++) {
            int c  = pass * 32 + (wid << 2) + (lane >> 3);
            int rb = (lane & 7) * 16;
            __align__(16) f16 bh2[16];
#pragma unroll
            for (int i = 0; i < 16; i++)
                bh2[i] = __float2half_rn(Csm[(rb + i) * 132 + c]);
            size_t vb = ((size_t)bB * DD + cb * 128 + c) * TT + t0 + rb;
            *(uint4*)(vth_ + vb)     = *(uint4*)&bh2[0];
            *(uint4*)(vth_ + vb + 8) = *(uint4*)&bh2[8];
        }
    }
}

// ---------------------------------------------------------------------------
// Output-projection GEMM: C = Yh Wo^T + bias, fp32 out (single-plane A).
// ---------------------------------------------------------------------------
__global__ void __launch_bounds__(256) gemm_out(
    const f16* __restrict__ Ah, const f16* __restrict__ Wh,
    const float* __restrict__ bias, float* __restrict__ C)
{
    extern __shared__ f16 smg[];
    const int tid  = threadIdx.x;
    const int lane = tid & 31;
    const int wid  = tid >> 5;
    const int warpM = wid >> 2;
    const int warpN = wid & 3;
    const int rowBase = blockIdx.y * 128;
    const int colBase = blockIdx.x * 128;

    GEMM_MAINLOOP_H(Ah, Ah, Wh, false)

#pragma unroll
    for (int mf = 0; mf < 4; mf++)
#pragma unroll
        for (int nf = 0; nf < 4; nf++) {
            int m0 = rowBase + warpM * 64 + mf * 16 + (lane >> 2);
            int n0 = colBase + warpN * 32 + nf * 8 + (lane & 3) * 2;
            float b0 = bias[n0], b1 = bias[n0 + 1];
            float2 o0 = make_float2(acc[mf][nf][0] + b0, acc[mf][nf][1] + b1);
            float2 o1 = make_float2(acc[mf][nf][2] + b0, acc[mf][nf][3] + b1);
            *(float2*)&C[(size_t)m0 * DD + n0]       = o0;
            *(float2*)&C[(size_t)(m0 + 8) * DD + n0] = o1;
        }
}

// ---------------------------------------------------------------------------
// Flash attention: 128 threads / 64 Q-rows per CTA, 4 CTAs/SM.
// 3-buffer K/V pipeline, ONE __syncthreads per tile.
// S = (Qh+Ql) K^T (2 mmas, log2 domain), softmax exp2f, P·V 1 mma.
// Buffer (18432 B): Kh | Vh, 64 x 144 B.
// ---------------------------------------------------------------------------
#define AROW 144
#define APLANE (64 * AROW)
#define ABUF (2 * APLANE)

__global__ void __launch_bounds__(128, 4) attn_mma(
    const f16* __restrict__ Qh, const f16* __restrict__ Ql,
    const f16* __restrict__ Kh, const f16* __restrict__ Vth,
    f16* __restrict__ Yh)
{
    extern __shared__ f16 asmem[];
    const uint32_t smA = smem_u32(asmem);

    const int tid  = threadIdx.x;
    const int lane = tid & 31;
    const int wid  = tid >> 5;           // 0..3
    const int g    = lane >> 2;
    const int t    = lane & 3;
    const int lm_row = lane & 15;
    const int lm_col = (lane >> 4) << 3;

    const int qb = (gridDim.x - 1) - blockIdx.x;   // 0..31, heavy first
    const int bh = blockIdx.y;
    const int b  = bh >> 4;
    const int h  = bh & 15;

    const size_t headBase = (size_t)b * TT * DD + h * HDIM;
    const size_t kRow = (size_t)b * TT;
    const size_t vRow = (size_t)b * DD + h * HDIM;
    const int rowA = qb * 64 + wid * 16 + g;

    // ---- Q fragments (pre-scaled by 0.125*log2e) ----
    uint32_t qh[4][4], ql[4][4];
#pragma unroll
    for (int kf = 0; kf < 4; kf++) {
        int c0 = kf * 16 + 2 * t;
        size_t o00 = headBase + (size_t)rowA * DD + c0;
        size_t o10 = headBase + (size_t)(rowA + 8) * DD + c0;
        qh[kf][0] = *(const uint32_t*)(Qh + o00);
        qh[kf][1] = *(const uint32_t*)(Qh + o10);
        qh[kf][2] = *(const uint32_t*)(Qh + o00 + 8);
        qh[kf][3] = *(const uint32_t*)(Qh + o10 + 8);
        ql[kf][0] = *(const uint32_t*)(Ql + o00);
        ql[kf][1] = *(const uint32_t*)(Ql + o10);
        ql[kf][2] = *(const uint32_t*)(Ql + o00 + 8);
        ql[kf][3] = *(const uint32_t*)(Ql + o10 + 8);
    }

    float oa[8][4];
#pragma unroll
    for (int df = 0; df < 8; df++)
#pragma unroll
        for (int r = 0; r < 4; r++) oa[df][r] = 0.f;
    float m0 = -1e30f, m1 = -1e30f, l0 = 0.f, l1 = 0.f;

    const int lrow = tid >> 3;          // 0..15 (x4 -> 64 rows)
    const int lch  = tid & 7;

    auto load_tile = [&](int jt, int bsel) {
        const uint32_t bufB = smA + (uint32_t)bsel * ABUF;
#pragma unroll
        for (int i = 0; i < 4; i++) {
            int row = lrow + i * 16;
            uint32_t sm_off = (uint32_t)(row * AROW + lch * 16);
            size_t gk = (kRow + jt * 64 + row) * DD + h * HDIM + lch * 8;
            cpa16(bufB + sm_off,          Kh + gk);
            size_t gv = (vRow + row) * TT + jt * 64 + lch * 8;
            cpa16(bufB + APLANE + sm_off, Vth + gv);
        }
        cpa_commit();
    };

    const int nTiles = qb + 1;
    load_tile(0, 0);
    if (nTiles > 1) load_tile(1, 1);

    int cur = 0;
    for (int jt = 0; jt < nTiles; jt++) {
        if (jt + 1 < nTiles) cpa_wait<1>(); else cpa_wait<0>();
        __syncthreads();

        if (jt + 2 < nTiles) {
            int pf = cur + 2; if (pf >= 3) pf -= 3;
            load_tile(jt + 2, pf);
        }

        const uint32_t bufB = smA + (uint32_t)cur * ABUF;

        // ---- S = Q K^T (Q split x2, log2 domain) ----
        float sa[8][4];
#pragma unroll
        for (int nf = 0; nf < 8; nf++)
#pragma unroll
            for (int r = 0; r < 4; r++) sa[nf][r] = 0.f;

#pragma unroll
        for (int kf = 0; kf < 4; kf++) {
            uint32_t kbh[8][2];
#pragma unroll
            for (int p = 0; p < 4; p++) {
                uint32_t r0, r1, r2, r3;
                uint32_t ro = (uint32_t)((p * 16 + lm_row) * AROW + (kf * 16 + lm_col) * 2);
                ldsm4(r0, r1, r2, r3, bufB + ro);
                kbh[2 * p][0] = r0; kbh[2 * p + 1][0] = r1;
                kbh[2 * p][1] = r2; kbh[2 * p + 1][1] = r3;
            }
#pragma unroll
            for (int nf = 0; nf < 8; nf++) {
                mma16816h(sa[nf], qh[kf], kbh[nf]);
                mma16816h(sa[nf], ql[kf], kbh[nf]);
            }
        }

        if (jt == qb) {
#pragma unroll
            for (int nf = 0; nf < 8; nf++) {
                int col = jt * 64 + nf * 8 + 2 * t;
                if (col > rowA)         sa[nf][0] = -1e30f;
                if (col + 1 > rowA)     sa[nf][1] = -1e30f;
                if (col > rowA + 8)     sa[nf][2] = -1e30f;
                if (col + 1 > rowA + 8) sa[nf][3] = -1e30f;
            }
        }

        // ---- online softmax (exp2 domain) ----
        float mx0 = -1e30f, mx1 = -1e30f;
#pragma unroll
        for (int nf = 0; nf < 8; nf++) {
            mx0 = fmaxf(mx0, fmaxf(sa[nf][0], sa[nf][1]));
            mx1 = fmaxf(mx1, fmaxf(sa[nf][2], sa[nf][3]));
        }
        mx0 = fmaxf(mx0, __shfl_xor_sync(0xffffffffu, mx0, 1));
        mx0 = fmaxf(mx0, __shfl_xor_sync(0xffffffffu, mx0, 2));
        mx1 = fmaxf(mx1, __shfl_xor_sync(0xffffffffu, mx1, 1));
        mx1 = fmaxf(mx1, __shfl_xor_sync(0xffffffffu, mx1, 2));
        float mn0 = fmaxf(m0, mx0);
        float mn1 = fmaxf(m1, mx1);
        float al0 = exp2f(m0 - mn0);
        float al1 = exp2f(m1 - mn1);

        float sum0 = 0.f, sum1 = 0.f;
#pragma unroll
        for (int nf = 0; nf < 8; nf++) {
            sa[nf][0] = exp2f(sa[nf][0] - mn0);
            sa[nf][1] = exp2f(sa[nf][1] - mn0);
            sa[nf][2] = exp2f(sa[nf][2] - mn1);
            sa[nf][3] = exp2f(sa[nf][3] - mn1);
            sum0 += sa[nf][0] + sa[nf][1];
            sum1 += sa[nf][2] + sa[nf][3];
        }
        sum0 += __shfl_xor_sync(0xffffffffu, sum0, 1);
        sum0 += __shfl_xor_sync(0xffffffffu, sum0, 2);
        sum1 += __shfl_xor_sync(0xffffffffu, sum1, 1);
        sum1 += __shfl_xor_sync(0xffffffffu, sum1, 2);
        l0 = l0 * al0 + sum0;
        l1 = l1 * al1 + sum1;
        m0 = mn0; m1 = mn1;
#pragma unroll
        for (int df = 0; df < 8; df++) {
            oa[df][0] *= al0; oa[df][1] *= al0;
            oa[df][2] *= al1; oa[df][3] *= al1;
        }

        // ---- O += P V (single-plane P) ----
#pragma unroll
        for (int kk = 0; kk < 4; kk++) {
            uint32_t pha[4];
            pha[0] = pack2h(sa[2 * kk][0],     sa[2 * kk][1]);
            pha[1] = pack2h(sa[2 * kk][2],     sa[2 * kk][3]);
            pha[2] = pack2h(sa[2 * kk + 1][0], sa[2 * kk + 1][1]);
            pha[3] = pack2h(sa[2 * kk + 1][2], sa[2 * kk + 1][3]);

            uint32_t vbh[8][2];
#pragma unroll
            for (int p = 0; p < 4; p++) {
                uint32_t r0, r1, r2, r3;
                uint32_t ro = (uint32_t)((p * 16 + lm_row) * AROW + (kk * 16 + lm_col) * 2);
                ldsm4(r0, r1, r2, r3, bufB + APLANE + ro);
                vbh[2 * p][0] = r0; vbh[2 * p + 1][0] = r1;
                vbh[2 * p][1] = r2; vbh[2 * p + 1][1] = r3;
            }
#pragma unroll
            for (int df = 0; df < 8; df++)
                mma16816h(oa[df], pha, vbh[df]);
        }

        if (++cur >= 3) cur = 0;
    }

    // ---- epilogue: normalize + single fp16 plane ----
    float inv0 = 1.0f / l0;
    float inv1 = 1.0f / l1;
#pragma unroll
    for (int df = 0; df < 8; df++) {
        int dcol = df * 8 + 2 * t;
        size_t off0 = headBase + (size_t)rowA * DD + dcol;
        size_t off1 = headBase + (size_t)(rowA + 8) * DD + dcol;
        *(uint32_t*)&Yh[off0] = pack2h(oa[df][0] * inv0, oa[df][1] * inv0);
        *(uint32_t*)&Yh[off1] = pack2h(oa[df][2] * inv1, oa[df][3] * inv1);
    }
}

// ---------------------------------------------------------------------------
// Launch: x, Wq, bq, Wk, bk, Wv, bv, Wo, bo (all fp32)
// ---------------------------------------------------------------------------
extern "C" void kernel_launch(void* const* d_in, const int* in_sizes, int n_in,
                              void* d_out, int out_size)
{
    const float* x  = (const float*)d_in[0];
    const float* Wq = (const float*)d_in[1];
    const float* bq = (const float*)d_in[2];
    const float* Wk = (const float*)d_in[3];
    const float* bk = (const float*)d_in[4];
    const float* Wv = (const float*)d_in[5];
    const float* bv = (const float*)d_in[6];
    const float* Wo = (const float*)d_in[7];
    const float* bo = (const float*)d_in[8];
    float* out = (float*)d_out;

    float *qf, *kf, *vf, *xf, *yf;
    f16 *wp;
    cudaGetSymbolAddress((void**)&qf, g_q);
    cudaGetSymbolAddress((void**)&kf, g_k);
    cudaGetSymbolAddress((void**)&vf, g_v);
    cudaGetSymbolAddress((void**)&xf, g_x);
    cudaGetSymbolAddress((void**)&yf, g_y);
    cudaGetSymbolAddress((void**)&wp, g_w);

    const int nX = MROWS * DD;
    const int nW = DD * DD;

    f16* xh  = (f16*)xf;  f16* xl  = xh + nX;
    f16* yh  = (f16*)yf;
    f16* qh  = (f16*)qf;  f16* ql  = qh + nX;
    f16* kh  = (f16*)kf;
    f16* vth = (f16*)vf;

    splith_kernel<<<(nX + 255) / 256, 256>>>(x, xh, xl, nX);
    convh4_kernel<<<(4 * nW + 255) / 256, 256>>>(Wq, Wk, Wv, Wo, wp, nW);

    // 3-stage planes (92160 B) >= epilogue Csm (67584 B)
    const int gemm_smem = 9 * TILEH * 2;   // 92160 B
    cudaFuncSetAttribute(gemm_qkv, cudaFuncAttributeMaxDynamicSharedMemorySize, gemm_smem);
    cudaFuncSetAttribute(gemm_out, cudaFuncAttributeMaxDynamicSharedMemorySize, gemm_smem);

    const int attn_smem = 3 * ABUF;   // 55296 B
    cudaFuncSetAttribute(attn_mma, cudaFuncAttributeMaxDynamicSharedMemorySize, attn_smem);

    gemm_qkv<<<dim3(24, MROWS / 128), 256, gemm_smem>>>(
        xh, xl, wp, bq, bk, bv, qh, ql, kh, vth);

    attn_mma<<<dim3(TT / 64, BB * HH), 128, attn_smem>>>(
        qh, ql, kh, vth, yh);

    gemm_out<<<dim3(DD / 128, MROWS / 128), 256, gemm_smem>>>(
        yh, wp + 3 * nW, bo, out);
}